// round 9
// baseline (speedup 1.0000x reference)
#include <cuda_runtime.h>
#include <cuda_bf16.h>
#include <math.h>
#include <cstdint>

// ---------------- problem constants ----------------
static constexpr int B_   = 32;
static constexpr int CCH  = 3;
static constexpr int IMG  = 224;
static constexpr int P_   = 16;
static constexpr int GRD  = IMG / P_;        // 14
static constexpr int NP   = GRD * GRD;       // 196
static constexpr int NTOK = NP + 1;          // 197
static constexpr int H_   = 768;
static constexpr int NH   = 12;
static constexpr int HD   = 64;
static constexpr int MLP_ = 3072;
static constexpr int L_   = 12;
static constexpr int ROWS = B_ * NTOK;       // 6304
static constexpr int PROWS = B_ * NP;        // 6272

// weight scratch layout (bf16 hi/lo, transposed to [N,K])
static constexpr long W_PATCH_OFF = 0;                       // 768x768
static constexpr long W_LAYER_BASE = 768L * 768;
static constexpr long W_LAYER_SZ   = 768L*2304 + 768L*768 + 768L*3072 + 3072L*768;
static constexpr long W_QKV_OFF = 0;
static constexpr long W_OUT_OFF = 768L*2304;
static constexpr long W_FC1_OFF = W_OUT_OFF + 768L*768;
static constexpr long W_FC2_OFF = W_FC1_OFF + 768L*3072;
static constexpr long W_TOTAL = W_LAYER_BASE + 12L * W_LAYER_SZ;

// ---------------- device scratch ----------------
__device__ float g_h   [ROWS * H_];
__device__ float g_qkv [ROWS * 3 * H_];
__device__ float g_tmp [PROWS * H_];
__device__ __align__(256) __nv_bfloat16 g_yh [ROWS * H_];
__device__ __align__(256) __nv_bfloat16 g_yl [ROWS * H_];
__device__ __align__(256) __nv_bfloat16 g_ah [ROWS * H_];
__device__ __align__(256) __nv_bfloat16 g_al [ROWS * H_];
__device__ __align__(256) __nv_bfloat16 g_mh [ROWS * MLP_];
__device__ __align__(256) __nv_bfloat16 g_ml [ROWS * MLP_];
__device__ __align__(256) __nv_bfloat16 g_wh [W_TOTAL];
__device__ __align__(256) __nv_bfloat16 g_wl [W_TOTAL];

// ---------------- helpers ----------------
__device__ __forceinline__ uint32_t smem_u32(const void* p) {
    uint32_t a;
    asm("{ .reg .u64 t; cvta.to.shared.u64 t, %1; cvt.u32.u64 %0, t; }" : "=r"(a) : "l"(p));
    return a;
}
__device__ __forceinline__ void cp16(uint32_t dst, const void* src, bool valid) {
    int sz = valid ? 16 : 0;
    asm volatile("cp.async.cg.shared.global [%0], [%1], 16, %2;"
                 :: "r"(dst), "l"(src), "r"(sz) : "memory");
}
__device__ __forceinline__ void cp_commit() {
    asm volatile("cp.async.commit_group;" ::: "memory");
}
__device__ __forceinline__ void cp_wait1() {
    asm volatile("cp.async.wait_group 1;" ::: "memory");
}
__device__ __forceinline__ void ldm4(uint32_t* r, uint32_t addr) {
    asm volatile("ldmatrix.sync.aligned.m8n8.x4.shared.b16 {%0,%1,%2,%3}, [%4];"
                 : "=r"(r[0]), "=r"(r[1]), "=r"(r[2]), "=r"(r[3]) : "r"(addr));
}
__device__ __forceinline__ void mma_bf16(float* d, const uint32_t* a, uint32_t b0, uint32_t b1) {
    asm volatile(
        "mma.sync.aligned.m16n8k16.row.col.f32.bf16.bf16.f32 "
        "{%0,%1,%2,%3}, {%4,%5,%6,%7}, {%8,%9}, {%0,%1,%2,%3};"
        : "+f"(d[0]), "+f"(d[1]), "+f"(d[2]), "+f"(d[3])
        : "r"(a[0]), "r"(a[1]), "r"(a[2]), "r"(a[3]), "r"(b0), "r"(b1));
}
__device__ __forceinline__ float gelu_exact(float x) {
    return 0.5f * x * (1.0f + erff(x * 0.70710678118654752f));
}
__device__ __forceinline__ uint32_t bfpack(float f0, float f1) {
    __nv_bfloat16 b0 = __float2bfloat16(f0), b1 = __float2bfloat16(f1);
    uint16_t u0, u1;
    memcpy(&u0, &b0, 2); memcpy(&u1, &b1, 2);
    return (uint32_t)u0 | ((uint32_t)u1 << 16);
}
__device__ __forceinline__ float bfres(float f) {
    return f - __bfloat162float(__float2bfloat16(f));
}

// ---------------- tiny no-op (ncu capture alignment: launch idx 3 = mgemm) ----------------
__global__ void noop_kernel() {}

// ---------------- mega weight split+transpose (all weights, one launch) ----------------
__global__ void wsplit_mega_kernel(const float* __restrict__ pW,
                                   const float* __restrict__ qkvW,
                                   const float* __restrict__ outW,
                                   const float* __restrict__ fc1W,
                                   const float* __restrict__ fc2W,
                                   __nv_bfloat16* __restrict__ GWh,
                                   __nv_bfloat16* __restrict__ GWl) {
    const int seg = blockIdx.y;       // 0..48
    int K, N;
    const float* src;
    long dstoff;
    if (seg == 0) {
        K = 768; N = 768; src = pW; dstoff = W_PATCH_OFF;
    } else {
        int t = (seg - 1) & 3, l = (seg - 1) >> 2;
        long wb = W_LAYER_BASE + (long)l * W_LAYER_SZ;
        if (t == 0)      { K = 768;  N = 2304; src = qkvW + (long)l * 768 * 2304; dstoff = wb + W_QKV_OFF; }
        else if (t == 1) { K = 768;  N = 768;  src = outW + (long)l * 768 * 768;  dstoff = wb + W_OUT_OFF; }
        else if (t == 2) { K = 768;  N = 3072; src = fc1W + (long)l * 768 * 3072; dstoff = wb + W_FC1_OFF; }
        else             { K = 3072; N = 768;  src = fc2W + (long)l * 3072 * 768; dstoff = wb + W_FC2_OFF; }
    }
    const int tn = N >> 5, tk = K >> 5;
    const int tile = blockIdx.x;
    if (tile >= tn * tk) return;
    const int n0 = (tile % tn) * 32, k0 = (tile / tn) * 32;

    __shared__ float t_[32][33];
    const int tx = threadIdx.x, ty = threadIdx.y;    // 32 x 8
    #pragma unroll
    for (int i = 0; i < 32; i += 8)
        t_[ty + i][tx] = src[(long)(k0 + ty + i) * N + n0 + tx];
    __syncthreads();
    __nv_bfloat16* Wh = GWh + dstoff;
    __nv_bfloat16* Wl = GWl + dstoff;
    #pragma unroll
    for (int i = 0; i < 32; i += 8) {
        float v = t_[tx][ty + i];
        long o = (long)(n0 + ty + i) * K + k0 + tx;
        __nv_bfloat16 h = __float2bfloat16(v);
        Wh[o] = h;
        Wl[o] = __float2bfloat16(v - __bfloat162float(h));
    }
}

// ---------------- tensor-core GEMM via mma.sync (bf16 hi/lo split) ----------------
// CTA tile 128x64, BK=32, 256 threads, 8 warps in 4m x 2n grid (32x32 warp tiles),
// 3-stage cp.async; 73.7KB smem/CTA -> 3 CTAs/SM by smem alone.
// EPI: 0 store f32 | 1 +bias f32 | 2 +bias,gelu -> bf16 hi/lo | 3 +bias,gelu,+=C | 4 +=C
static constexpr int MG_STAGE = 24576;            // Ah 8K + Al 8K + Bh 4K + Bl 4K
static constexpr int MG_SMEM  = 3 * MG_STAGE;     // 73728

template<int EPI>
__global__ void __launch_bounds__(256) mgemm_kernel(
    const __nv_bfloat16* __restrict__ Ah, const __nv_bfloat16* __restrict__ Al,
    const __nv_bfloat16* __restrict__ Wh, const __nv_bfloat16* __restrict__ Wl,
    const float* __restrict__ bias, float* __restrict__ C,
    __nv_bfloat16* __restrict__ Oh, __nv_bfloat16* __restrict__ Ol,
    int M, int N, int K)
{
    extern __shared__ char smc[];
    const uint32_t smb = smem_u32(smc);
    const int tid = threadIdx.x;
    const int lane = tid & 31, warp = tid >> 5;
    const int wm = warp >> 1, wn = warp & 1;      // 4m x 2n warp grid, 32x32 tiles
    const int n0 = blockIdx.x * 64, m0 = blockIdx.y * 128;
    const int KT = K >> 5;

    float acc[2][4][4];
    #pragma unroll
    for (int a = 0; a < 2; a++)
        #pragma unroll
        for (int b = 0; b < 4; b++)
            #pragma unroll
            for (int c = 0; c < 4; c++) acc[a][b][c] = 0.f;

    auto issue = [&](int kt, int s) {
        const int k0 = kt << 5;
        const uint32_t st = smb + s * MG_STAGE;
        #pragma unroll
        for (int i = 0; i < 2; i++) {
            int idx = tid + (i << 8);               // 0..511
            int row = idx >> 2, ch = idx & 3;
            uint32_t off = (uint32_t)(row * 64 + ((ch ^ ((row >> 1) & 3)) << 4));
            bool av = (m0 + row) < M;
            long aoff = (long)(m0 + row) * K + k0 + ch * 8;
            cp16(st +    0 + off, Ah + aoff, av);
            cp16(st + 8192 + off, Al + aoff, av);
        }
        {
            int row = tid >> 2, ch = tid & 3;       // 64 rows x 4 chunks
            uint32_t off = (uint32_t)(row * 64 + ((ch ^ ((row >> 1) & 3)) << 4));
            long boff = (long)(n0 + row) * K + k0 + ch * 8;
            cp16(st + 16384 + off, Wh + boff, true);
            cp16(st + 20480 + off, Wl + boff, true);
        }
    };
    auto ldaddr = [&](uint32_t tb, int r0, int ks) -> uint32_t {
        int row = r0 + (lane & 7) + ((lane & 8) ? 8 : 0);
        int ch  = (ks << 1) + ((lane >> 4) & 1);
        return tb + (uint32_t)(row * 64 + ((ch ^ ((row >> 1) & 3)) << 4));
    };

    issue(0, 0);
    cp_commit();
    if (KT > 1) issue(1, 1);
    cp_commit();

    for (int kt = 0; kt < KT; kt++) {
        cp_wait1();
        __syncthreads();
        int pf = kt + 2;
        if (pf < KT) issue(pf, pf % 3);
        cp_commit();

        const uint32_t st = smb + (kt % 3) * MG_STAGE;
        #pragma unroll
        for (int ks = 0; ks < 2; ks++) {
            uint32_t ah[2][4], al[2][4];
            #pragma unroll
            for (int mt = 0; mt < 2; mt++) {
                ldm4(ah[mt], ldaddr(st +    0, wm * 32 + mt * 16, ks));
                ldm4(al[mt], ldaddr(st + 8192, wm * 32 + mt * 16, ks));
            }
            #pragma unroll
            for (int g = 0; g < 2; g++) {
                uint32_t bh[4], bl[4];
                ldm4(bh, ldaddr(st + 16384, wn * 32 + g * 16, ks));
                ldm4(bl, ldaddr(st + 20480, wn * 32 + g * 16, ks));
                #pragma unroll
                for (int mt = 0; mt < 2; mt++)
                    #pragma unroll
                    for (int sl = 0; sl < 2; sl++) {
                        int nt = g * 2 + sl;
                        mma_bf16(acc[mt][nt], ah[mt], bh[sl], bh[sl + 2]);
                        mma_bf16(acc[mt][nt], ah[mt], bl[sl], bl[sl + 2]);
                        mma_bf16(acc[mt][nt], al[mt], bh[sl], bh[sl + 2]);
                    }
            }
        }
    }

    // epilogue
    #pragma unroll
    for (int mt = 0; mt < 2; mt++)
        #pragma unroll
        for (int nt = 0; nt < 4; nt++) {
            int cb = n0 + wn * 32 + nt * 8 + (lane & 3) * 2;
            #pragma unroll
            for (int h = 0; h < 2; h++) {
                int r = m0 + wm * 32 + mt * 16 + (lane >> 2) + h * 8;
                if (r < M) {
                    float v0 = acc[mt][nt][h * 2 + 0];
                    float v1 = acc[mt][nt][h * 2 + 1];
                    if (EPI == 1 || EPI == 2 || EPI == 3) { v0 += bias[cb]; v1 += bias[cb + 1]; }
                    if (EPI == 2 || EPI == 3) { v0 = gelu_exact(v0); v1 = gelu_exact(v1); }
                    if (EPI == 2) {
                        long o = (long)r * N + cb;
                        __nv_bfloat16 h0 = __float2bfloat16(v0);
                        __nv_bfloat16 h1 = __float2bfloat16(v1);
                        Oh[o] = h0;      Ol[o] = __float2bfloat16(v0 - __bfloat162float(h0));
                        Oh[o + 1] = h1;  Ol[o + 1] = __float2bfloat16(v1 - __bfloat162float(h1));
                    } else {
                        float* cp = C + (long)r * N + cb;
                        if (EPI == 3 || EPI == 4) { v0 += cp[0]; v1 += cp[1]; }
                        cp[0] = v0; cp[1] = v1;
                    }
                }
            }
        }
}

// ---------------- tensor-core attention (hi/lo bf16 mma, register softmax) ----------------
static constexpr int ATT_QH = 0;                     // Q hi: 208 rows x 128B (swizzled)
static constexpr int ATT_QL = 26624;
static constexpr int ATT_KH = 53248;                 // K hi: 224 rows x 128B
static constexpr int ATT_KL = 81920;
static constexpr int ATT_VH = 110592;                // Vt hi: 64 rows x 512B (token-major)
static constexpr int ATT_VL = 143360;
static constexpr int ATT_SMEM = 176128;

__global__ void __launch_bounds__(256) attn_mma_kernel(const float* __restrict__ qkv,
                                                       __nv_bfloat16* __restrict__ oh,
                                                       __nv_bfloat16* __restrict__ ol) {
    extern __shared__ char sma[];
    const uint32_t smb = smem_u32(sma);
    const int tid = threadIdx.x, lane = tid & 31, warp = tid >> 5;
    const int bb = blockIdx.x / NH, hh = blockIdx.x % NH;

    // zero all tiles (pads must be 0, not garbage)
    for (int i = tid; i < ATT_SMEM / 16; i += 256)
        *(uint4*)(sma + i * 16) = make_uint4(0, 0, 0, 0);
    __syncthreads();

    // stage Q,K (row-major d) and Vt (token-major) as bf16 hi/lo
    const float* base = qkv + (long)bb * NTOK * 2304 + hh * 64;
    for (int idx = tid; idx < NTOK * 64; idx += 256) {
        int row = idx >> 6, d = idx & 63;
        const float* rp = base + (long)row * 2304;
        float q = rp[d], k = rp[768 + d], v = rp[1536 + d];
        uint32_t qko = (uint32_t)(row * 128 + (((d >> 3) ^ (row & 7)) << 4) + (d & 7) * 2);
        __nv_bfloat16 t;
        t = __float2bfloat16(q);
        *(__nv_bfloat16*)(sma + ATT_QH + qko) = t;
        *(__nv_bfloat16*)(sma + ATT_QL + qko) = __float2bfloat16(q - __bfloat162float(t));
        t = __float2bfloat16(k);
        *(__nv_bfloat16*)(sma + ATT_KH + qko) = t;
        *(__nv_bfloat16*)(sma + ATT_KL + qko) = __float2bfloat16(k - __bfloat162float(t));
        uint32_t vo = (uint32_t)(d * 512 + (((row >> 3) ^ (d & 7)) << 4) + (row & 7) * 2);
        t = __float2bfloat16(v);
        *(__nv_bfloat16*)(sma + ATT_VH + vo) = t;
        *(__nv_bfloat16*)(sma + ATT_VL + vo) = __float2bfloat16(v - __bfloat162float(t));
    }
    __syncthreads();

    auto qkaddr = [&](uint32_t toff, int r0, int kt) -> uint32_t {
        int row = r0 + (lane & 7) + ((lane & 8) ? 8 : 0);
        int ch  = kt * 2 + (lane >> 4);
        return smb + toff + (uint32_t)(row * 128 + ((ch ^ (row & 7)) << 4));
    };
    auto vaddr = [&](uint32_t toff, int d0, int kt2) -> uint32_t {
        int row = d0 + (lane & 7) + ((lane & 8) ? 8 : 0);
        int ch  = kt2 * 2 + (lane >> 4);
        return smb + toff + (uint32_t)(row * 512 + ((ch ^ (row & 7)) << 4));
    };

    for (int mt = warp; mt < 13; mt += 8) {
        const int r0 = mt * 16;
        float sacc[28][4];
        #pragma unroll
        for (int n = 0; n < 28; n++)
            #pragma unroll
            for (int c = 0; c < 4; c++) sacc[n][c] = 0.f;

        uint32_t ah[4][4], al[4][4];
        #pragma unroll
        for (int kt = 0; kt < 4; kt++) {
            ldm4(ah[kt], qkaddr(ATT_QH, r0, kt));
            ldm4(al[kt], qkaddr(ATT_QL, r0, kt));
        }
        #pragma unroll
        for (int g = 0; g < 14; g++) {
            #pragma unroll
            for (int kt = 0; kt < 4; kt++) {
                uint32_t kh4[4], kl4[4];
                ldm4(kh4, qkaddr(ATT_KH, g * 16, kt));
                ldm4(kl4, qkaddr(ATT_KL, g * 16, kt));
                #pragma unroll
                for (int sl = 0; sl < 2; sl++) {
                    mma_bf16(sacc[2 * g + sl], ah[kt], kh4[sl], kh4[sl + 2]);
                    mma_bf16(sacc[2 * g + sl], al[kt], kh4[sl], kh4[sl + 2]);
                    mma_bf16(sacc[2 * g + sl], ah[kt], kl4[sl], kl4[sl + 2]);
                }
            }
        }

        // softmax over rows (row0 = r0 + lane>>2, row1 = +8); cols = nt*8 + (lane&3)*2 (+1)
        const int cb = (lane & 3) * 2;
        float m0 = -1e30f, m1 = -1e30f;
        #pragma unroll
        for (int nt = 0; nt < 28; nt++) {
            int c0 = nt * 8 + cb;
            sacc[nt][0] = (c0     < 197) ? sacc[nt][0] * 0.125f : -1e30f;
            sacc[nt][1] = (c0 + 1 < 197) ? sacc[nt][1] * 0.125f : -1e30f;
            sacc[nt][2] = (c0     < 197) ? sacc[nt][2] * 0.125f : -1e30f;
            sacc[nt][3] = (c0 + 1 < 197) ? sacc[nt][3] * 0.125f : -1e30f;
            m0 = fmaxf(m0, fmaxf(sacc[nt][0], sacc[nt][1]));
            m1 = fmaxf(m1, fmaxf(sacc[nt][2], sacc[nt][3]));
        }
        m0 = fmaxf(m0, __shfl_xor_sync(0xffffffffu, m0, 1));
        m0 = fmaxf(m0, __shfl_xor_sync(0xffffffffu, m0, 2));
        m1 = fmaxf(m1, __shfl_xor_sync(0xffffffffu, m1, 1));
        m1 = fmaxf(m1, __shfl_xor_sync(0xffffffffu, m1, 2));
        float s0 = 0.f, s1 = 0.f;
        #pragma unroll
        for (int nt = 0; nt < 28; nt++) {
            sacc[nt][0] = __expf(sacc[nt][0] - m0);
            sacc[nt][1] = __expf(sacc[nt][1] - m0);
            sacc[nt][2] = __expf(sacc[nt][2] - m1);
            sacc[nt][3] = __expf(sacc[nt][3] - m1);
            s0 += sacc[nt][0] + sacc[nt][1];
            s1 += sacc[nt][2] + sacc[nt][3];
        }
        s0 += __shfl_xor_sync(0xffffffffu, s0, 1);
        s0 += __shfl_xor_sync(0xffffffffu, s0, 2);
        s1 += __shfl_xor_sync(0xffffffffu, s1, 1);
        s1 += __shfl_xor_sync(0xffffffffu, s1, 2);
        float i0 = 1.f / s0, i1 = 1.f / s1;
        #pragma unroll
        for (int nt = 0; nt < 28; nt++) {
            sacc[nt][0] *= i0; sacc[nt][1] *= i0;
            sacc[nt][2] *= i1; sacc[nt][3] *= i1;
        }

        // O = P V (P hi/lo from registers, Vt hi/lo from smem)
        float oacc[8][4];
        #pragma unroll
        for (int n = 0; n < 8; n++)
            #pragma unroll
            for (int c = 0; c < 4; c++) oacc[n][c] = 0.f;
        #pragma unroll
        for (int kt2 = 0; kt2 < 14; kt2++) {
            float p00 = sacc[2*kt2][0],   p01 = sacc[2*kt2][1];
            float p10 = sacc[2*kt2][2],   p11 = sacc[2*kt2][3];
            float q00 = sacc[2*kt2+1][0], q01 = sacc[2*kt2+1][1];
            float q10 = sacc[2*kt2+1][2], q11 = sacc[2*kt2+1][3];
            uint32_t pah[4], pal[4];
            pah[0] = bfpack(p00, p01); pal[0] = bfpack(bfres(p00), bfres(p01));
            pah[1] = bfpack(p10, p11); pal[1] = bfpack(bfres(p10), bfres(p11));
            pah[2] = bfpack(q00, q01); pal[2] = bfpack(bfres(q00), bfres(q01));
            pah[3] = bfpack(q10, q11); pal[3] = bfpack(bfres(q10), bfres(q11));
            #pragma unroll
            for (int g = 0; g < 4; g++) {
                uint32_t vh4[4], vl4[4];
                ldm4(vh4, vaddr(ATT_VH, g * 16, kt2));
                ldm4(vl4, vaddr(ATT_VL, g * 16, kt2));
                #pragma unroll
                for (int sl = 0; sl < 2; sl++) {
                    mma_bf16(oacc[2 * g + sl], pah, vh4[sl], vh4[sl + 2]);
                    mma_bf16(oacc[2 * g + sl], pal, vh4[sl], vh4[sl + 2]);
                    mma_bf16(oacc[2 * g + sl], pah, vl4[sl], vl4[sl + 2]);
                }
            }
        }

        // write output (bf16 hi/lo), rows < 197
        const int row0 = r0 + (lane >> 2), row1 = row0 + 8;
        #pragma unroll
        for (int nt = 0; nt < 8; nt++) {
            int d0 = nt * 8 + cb;
            if (row0 < NTOK) {
                long o = ((long)(bb * NTOK + row0)) * H_ + hh * 64 + d0;
                *(uint32_t*)(oh + o) = bfpack(oacc[nt][0], oacc[nt][1]);
                *(uint32_t*)(ol + o) = bfpack(bfres(oacc[nt][0]), bfres(oacc[nt][1]));
            }
            if (row1 < NTOK) {
                long o = ((long)(bb * NTOK + row1)) * H_ + hh * 64 + d0;
                *(uint32_t*)(oh + o) = bfpack(oacc[nt][2], oacc[nt][3]);
                *(uint32_t*)(ol + o) = bfpack(bfres(oacc[nt][2]), bfres(oacc[nt][3]));
            }
        }
    }
}

// ---------------- LayerNorm (768) -> bf16 hi/lo ----------------
__global__ void ln_kernel(const float* __restrict__ in, __nv_bfloat16* __restrict__ yh,
                          __nv_bfloat16* __restrict__ yl,
                          const float* __restrict__ g, const float* __restrict__ b) {
    const int row = blockIdx.x;
    const int tid = threadIdx.x;  // 256
    const float* x = in + (long)row * H_;
    float v0 = x[tid], v1 = x[tid + 256], v2 = x[tid + 512];
    __shared__ float red[256];
    __shared__ float s_mean, s_rstd;
    red[tid] = v0 + v1 + v2;
    __syncthreads();
    for (int o = 128; o > 0; o >>= 1) { if (tid < o) red[tid] += red[tid + o]; __syncthreads(); }
    if (tid == 0) s_mean = red[0] * (1.f / H_);
    __syncthreads();
    float m = s_mean;
    float d0 = v0 - m, d1 = v1 - m, d2 = v2 - m;
    red[tid] = d0 * d0 + d1 * d1 + d2 * d2;
    __syncthreads();
    for (int o = 128; o > 0; o >>= 1) { if (tid < o) red[tid] += red[tid + o]; __syncthreads(); }
    if (tid == 0) s_rstd = rsqrtf(red[0] * (1.f / H_) + 1e-5f);
    __syncthreads();
    float rs = s_rstd;
    long base = (long)row * H_;
    #pragma unroll
    for (int rr = 0; rr < 3; rr++) {
        int c = tid + rr * 256;
        float d = (rr == 0 ? d0 : rr == 1 ? d1 : d2);
        float v = d * rs * g[c] + b[c];
        __nv_bfloat16 h = __float2bfloat16(v);
        yh[base + c] = h;
        yl[base + c] = __float2bfloat16(v - __bfloat162float(h));
    }
}

// ---------------- patchify + LN(pn1) -> bf16 hi/lo ----------------
__global__ void patchify_ln_kernel(const float* __restrict__ x,
                                   const float* __restrict__ g, const float* __restrict__ b,
                                   __nv_bfloat16* __restrict__ yh, __nv_bfloat16* __restrict__ yl) {
    const int pidx = blockIdx.x;
    const int bimg = pidx / NP;
    const int pp   = pidx % NP;
    const int hg = pp / GRD, wg = pp % GRD;
    const int tid = threadIdx.x;
    float v[3];
    #pragma unroll
    for (int r = 0; r < 3; r++) {
        int f = tid + r * 256;
        int p1 = f / 48, rem = f % 48, p2 = rem / 3, c = rem % 3;
        v[r] = x[(((long)bimg * CCH + c) * IMG + (hg * P_ + p1)) * IMG + (wg * P_ + p2)];
    }
    __shared__ float red[256];
    __shared__ float s_mean, s_rstd;
    red[tid] = v[0] + v[1] + v[2];
    __syncthreads();
    for (int o = 128; o > 0; o >>= 1) { if (tid < o) red[tid] += red[tid + o]; __syncthreads(); }
    if (tid == 0) s_mean = red[0] * (1.f / H_);
    __syncthreads();
    float m = s_mean;
    float d0 = v[0] - m, d1 = v[1] - m, d2 = v[2] - m;
    red[tid] = d0 * d0 + d1 * d1 + d2 * d2;
    __syncthreads();
    for (int o = 128; o > 0; o >>= 1) { if (tid < o) red[tid] += red[tid + o]; __syncthreads(); }
    if (tid == 0) s_rstd = rsqrtf(red[0] * (1.f / H_) + 1e-5f);
    __syncthreads();
    float rs = s_rstd;
    long base = (long)pidx * H_;
    #pragma unroll
    for (int rr = 0; rr < 3; rr++) {
        int c = tid + rr * 256;
        float d = (rr == 0 ? d0 : rr == 1 ? d1 : d2);
        float vv = d * rs * g[c] + b[c];
        __nv_bfloat16 h = __float2bfloat16(vv);
        yh[base + c] = h;
        yl[base + c] = __float2bfloat16(vv - __bfloat162float(h));
    }
}

// ---------------- LN(pn2) + cls + pos -> h (f32) ----------------
__global__ void assemble_kernel(const float* __restrict__ pemb,
                                const float* __restrict__ g, const float* __restrict__ b,
                                const float* __restrict__ cls, const float* __restrict__ pos,
                                float* __restrict__ h) {
    const int row = blockIdx.x;
    const int bb = row / NTOK, t = row % NTOK;
    const int tid = threadIdx.x;
    float* o_ = h + (long)row * H_;
    if (t == 0) {
        o_[tid]       = cls[tid]       + pos[tid];
        o_[tid + 256] = cls[tid + 256] + pos[tid + 256];
        o_[tid + 512] = cls[tid + 512] + pos[tid + 512];
        return;
    }
    const float* x = pemb + (long)(bb * NP + t - 1) * H_;
    float v0 = x[tid], v1 = x[tid + 256], v2 = x[tid + 512];
    __shared__ float red[256];
    __shared__ float s_mean, s_rstd;
    red[tid] = v0 + v1 + v2;
    __syncthreads();
    for (int o = 128; o > 0; o >>= 1) { if (tid < o) red[tid] += red[tid + o]; __syncthreads(); }
    if (tid == 0) s_mean = red[0] * (1.f / H_);
    __syncthreads();
    float m = s_mean;
    float d0 = v0 - m, d1 = v1 - m, d2 = v2 - m;
    red[tid] = d0 * d0 + d1 * d1 + d2 * d2;
    __syncthreads();
    for (int o = 128; o > 0; o >>= 1) { if (tid < o) red[tid] += red[tid + o]; __syncthreads(); }
    if (tid == 0) s_rstd = rsqrtf(red[0] * (1.f / H_) + 1e-5f);
    __syncthreads();
    float rs = s_rstd;
    const float* pp = pos + (long)t * H_;
    o_[tid]       = d0 * rs * g[tid]       + b[tid]       + pp[tid];
    o_[tid + 256] = d1 * rs * g[tid + 256] + b[tid + 256] + pp[tid + 256];
    o_[tid + 512] = d2 * rs * g[tid + 512] + b[tid + 512] + pp[tid + 512];
}

// ---------------- mean pool ----------------
__global__ void meanpool_kernel(const float* __restrict__ h, float* __restrict__ out) {
    const int bb = blockIdx.x;
    const int j = threadIdx.x;
    float s = 0.f;
    for (int i = 0; i < NTOK; i++) s += h[((long)bb * NTOK + i) * H_ + j];
    out[bb * H_ + j] = s * (1.f / NTOK);
}

// ---------------- host orchestration ----------------
static inline dim3 ggrid(int M, int N) { return dim3(N / 64, (M + 127) / 128); }

extern "C" void kernel_launch(void* const* d_in, const int* in_sizes, int n_in,
                              void* d_out, int out_size) {
    const float* x      = (const float*)d_in[0];
    const float* pn1_g  = (const float*)d_in[1];
    const float* pn1_b  = (const float*)d_in[2];
    const float* pW     = (const float*)d_in[3];
    const float* pb     = (const float*)d_in[4];
    const float* pn2_g  = (const float*)d_in[5];
    const float* pn2_b  = (const float*)d_in[6];
    const float* cls    = (const float*)d_in[7];
    const float* pos    = (const float*)d_in[8];
    const float* ln1_g  = (const float*)d_in[9];
    const float* ln1_b  = (const float*)d_in[10];
    const float* qkv_W  = (const float*)d_in[11];
    const float* out_W  = (const float*)d_in[12];
    const float* ln2_g  = (const float*)d_in[13];
    const float* ln2_b  = (const float*)d_in[14];
    const float* fc1_W  = (const float*)d_in[15];
    const float* fc1_b  = (const float*)d_in[16];
    const float* fc2_W  = (const float*)d_in[17];
    const float* fc2_b  = (const float*)d_in[18];
    float* out = (float*)d_out;

    float *p_h, *p_qkv, *p_tmp;
    __nv_bfloat16 *p_yh, *p_yl, *p_ahh, *p_all, *p_mh, *p_ml, *p_wh, *p_wl;
    cudaGetSymbolAddress((void**)&p_h,   g_h);
    cudaGetSymbolAddress((void**)&p_qkv, g_qkv);
    cudaGetSymbolAddress((void**)&p_tmp, g_tmp);
    cudaGetSymbolAddress((void**)&p_yh,  g_yh);
    cudaGetSymbolAddress((void**)&p_yl,  g_yl);
    cudaGetSymbolAddress((void**)&p_ahh, g_ah);
    cudaGetSymbolAddress((void**)&p_all, g_al);
    cudaGetSymbolAddress((void**)&p_mh,  g_mh);
    cudaGetSymbolAddress((void**)&p_ml,  g_ml);
    cudaGetSymbolAddress((void**)&p_wh,  g_wh);
    cudaGetSymbolAddress((void**)&p_wl,  g_wl);

    cudaFuncSetAttribute(attn_mma_kernel, cudaFuncAttributeMaxDynamicSharedMemorySize, ATT_SMEM);
    cudaFuncSetAttribute(mgemm_kernel<0>, cudaFuncAttributeMaxDynamicSharedMemorySize, MG_SMEM);
    cudaFuncSetAttribute(mgemm_kernel<1>, cudaFuncAttributeMaxDynamicSharedMemorySize, MG_SMEM);
    cudaFuncSetAttribute(mgemm_kernel<2>, cudaFuncAttributeMaxDynamicSharedMemorySize, MG_SMEM);
    cudaFuncSetAttribute(mgemm_kernel<3>, cudaFuncAttributeMaxDynamicSharedMemorySize, MG_SMEM);
    cudaFuncSetAttribute(mgemm_kernel<4>, cudaFuncAttributeMaxDynamicSharedMemorySize, MG_SMEM);

    // launch idx 0: patchify + LN(pn1)
    patchify_ln_kernel<<<PROWS, 256>>>(x, pn1_g, pn1_b, p_yh, p_yl);
    // launch idx 1: mega weight split
    wsplit_mega_kernel<<<dim3(2304, 49), dim3(32, 8)>>>(pW, qkv_W, out_W, fc1_W, fc2_W, p_wh, p_wl);
    // launch idx 2: no-op (aligns ncu capture to idx 3 = mgemm)
    noop_kernel<<<1, 32>>>();
    // launch idx 3: patch embed GEMM + bias -> g_tmp (f32)
    mgemm_kernel<1><<<ggrid(PROWS, H_), 256, MG_SMEM>>>(p_yh, p_yl, p_wh + W_PATCH_OFF, p_wl + W_PATCH_OFF,
                                                        pb, p_tmp, nullptr, nullptr, PROWS, H_, H_);
    // LN(pn2) + cls + pos -> h
    assemble_kernel<<<ROWS, 256>>>(p_tmp, pn2_g, pn2_b, cls, pos, p_h);

    // transformer layers
    for (int l = 0; l < L_; l++) {
        long wb = W_LAYER_BASE + (long)l * W_LAYER_SZ;
        const float* l1g = ln1_g + l * H_;
        const float* l1b = ln1_b + l * H_;
        const float* l2g = ln2_g + l * H_;
        const float* l2b = ln2_b + l * H_;
        const float* f1b = fc1_b + (long)l * MLP_;
        const float* f2b = fc2_b + (long)l * H_;

        ln_kernel<<<ROWS, 256>>>(p_h, p_yh, p_yl, l1g, l1b);
        mgemm_kernel<0><<<ggrid(ROWS, 3 * H_), 256, MG_SMEM>>>(p_yh, p_yl, p_wh + wb + W_QKV_OFF, p_wl + wb + W_QKV_OFF,
                                                               nullptr, p_qkv, nullptr, nullptr, ROWS, 3 * H_, H_);
        attn_mma_kernel<<<B_ * NH, 256, ATT_SMEM>>>(p_qkv, p_ahh, p_all);
        mgemm_kernel<4><<<ggrid(ROWS, H_), 256, MG_SMEM>>>(p_ahh, p_all, p_wh + wb + W_OUT_OFF, p_wl + wb + W_OUT_OFF,
                                                           nullptr, p_h, nullptr, nullptr, ROWS, H_, H_);
        ln_kernel<<<ROWS, 256>>>(p_h, p_yh, p_yl, l2g, l2b);
        mgemm_kernel<2><<<ggrid(ROWS, MLP_), 256, MG_SMEM>>>(p_yh, p_yl, p_wh + wb + W_FC1_OFF, p_wl + wb + W_FC1_OFF,
                                                             f1b, nullptr, p_mh, p_ml, ROWS, MLP_, H_);
        mgemm_kernel<3><<<ggrid(ROWS, H_), 256, MG_SMEM>>>(p_mh, p_ml, p_wh + wb + W_FC2_OFF, p_wl + wb + W_FC2_OFF,
                                                           f2b, p_h, nullptr, nullptr, ROWS, H_, MLP_);
    }

    // mean pool
    meanpool_kernel<<<B_, H_>>>(p_h, out);
}

// round 10
// speedup vs baseline: 1.3438x; 1.3438x over previous
#include <cuda_runtime.h>
#include <cuda_bf16.h>
#include <cuda_fp16.h>
#include <math.h>
#include <cstdint>

// ---------------- problem constants ----------------
static constexpr int B_   = 32;
static constexpr int CCH  = 3;
static constexpr int IMG  = 224;
static constexpr int P_   = 16;
static constexpr int GRD  = IMG / P_;        // 14
static constexpr int NP   = GRD * GRD;       // 196
static constexpr int NTOK = NP + 1;          // 197
static constexpr int H_   = 768;
static constexpr int NH   = 12;
static constexpr int HD   = 64;
static constexpr int MLP_ = 3072;
static constexpr int L_   = 12;
static constexpr int ROWS = B_ * NTOK;       // 6304
static constexpr int PROWS = B_ * NP;        // 6272

// bf16 weight scratch (patch + QKV), transposed [N,K]
static constexpr long W_PATCH_OFF = 0;                         // 768x768
static constexpr long W_QKV_BASE  = 768L * 768;                // then 12 x (2304x768)
static constexpr long W_QKV_SZ    = 768L * 2304;
static constexpr long WB_TOTAL    = W_QKV_BASE + 12L * W_QKV_SZ;

// fp16 weight scratch (out, fc1, fc2), transposed [N,K]
static constexpr long F_OUT_OFF  = 0;
static constexpr long F_FC1_OFF  = 768L * 768;
static constexpr long F_FC2_OFF  = F_FC1_OFF + 768L * 3072;
static constexpr long F_LAYER_SZ = F_FC2_OFF + 3072L * 768;    // 5308416
static constexpr long F_TOTAL    = 12L * F_LAYER_SZ;

// ---------------- device scratch ----------------
__device__ float g_h   [ROWS * H_];
__device__ float g_qkv [ROWS * 3 * H_];
__device__ float g_tmp [PROWS * H_];
__device__ __align__(256) __nv_bfloat16 g_yh [ROWS * H_];
__device__ __align__(256) __nv_bfloat16 g_yl [ROWS * H_];
__device__ __align__(256) __half g_ha [ROWS * H_];     // attention out (fp16 single)
__device__ __align__(256) __half g_hy [ROWS * H_];     // LN2 out (fp16 single)
__device__ __align__(256) __half g_hm [ROWS * MLP_];   // FC1+gelu out (fp16 single)
__device__ __align__(256) __nv_bfloat16 g_wh [WB_TOTAL];
__device__ __align__(256) __nv_bfloat16 g_wl [WB_TOTAL];
__device__ __align__(256) __half g_fh [F_TOTAL];
__device__ __align__(256) __half g_fl [F_TOTAL];

// ---------------- helpers ----------------
__device__ __forceinline__ uint32_t smem_u32(const void* p) {
    uint32_t a;
    asm("{ .reg .u64 t; cvta.to.shared.u64 t, %1; cvt.u32.u64 %0, t; }" : "=r"(a) : "l"(p));
    return a;
}
__device__ __forceinline__ void cp16(uint32_t dst, const void* src, bool valid) {
    int sz = valid ? 16 : 0;
    asm volatile("cp.async.cg.shared.global [%0], [%1], 16, %2;"
                 :: "r"(dst), "l"(src), "r"(sz) : "memory");
}
__device__ __forceinline__ void cp_commit() {
    asm volatile("cp.async.commit_group;" ::: "memory");
}
__device__ __forceinline__ void cp_wait1() {
    asm volatile("cp.async.wait_group 1;" ::: "memory");
}
__device__ __forceinline__ void ldm4(uint32_t* r, uint32_t addr) {
    asm volatile("ldmatrix.sync.aligned.m8n8.x4.shared.b16 {%0,%1,%2,%3}, [%4];"
                 : "=r"(r[0]), "=r"(r[1]), "=r"(r[2]), "=r"(r[3]) : "r"(addr));
}
__device__ __forceinline__ void mma_bf16(float* d, const uint32_t* a, uint32_t b0, uint32_t b1) {
    asm volatile(
        "mma.sync.aligned.m16n8k16.row.col.f32.bf16.bf16.f32 "
        "{%0,%1,%2,%3}, {%4,%5,%6,%7}, {%8,%9}, {%0,%1,%2,%3};"
        : "+f"(d[0]), "+f"(d[1]), "+f"(d[2]), "+f"(d[3])
        : "r"(a[0]), "r"(a[1]), "r"(a[2]), "r"(a[3]), "r"(b0), "r"(b1));
}
__device__ __forceinline__ void mma_f16(float* d, const uint32_t* a, uint32_t b0, uint32_t b1) {
    asm volatile(
        "mma.sync.aligned.m16n8k16.row.col.f32.f16.f16.f32 "
        "{%0,%1,%2,%3}, {%4,%5,%6,%7}, {%8,%9}, {%0,%1,%2,%3};"
        : "+f"(d[0]), "+f"(d[1]), "+f"(d[2]), "+f"(d[3])
        : "r"(a[0]), "r"(a[1]), "r"(a[2]), "r"(a[3]), "r"(b0), "r"(b1));
}
__device__ __forceinline__ float gelu_exact(float x) {
    return 0.5f * x * (1.0f + erff(x * 0.70710678118654752f));
}
__device__ __forceinline__ uint32_t bfpack(float f0, float f1) {
    __nv_bfloat16 b0 = __float2bfloat16(f0), b1 = __float2bfloat16(f1);
    uint16_t u0, u1;
    memcpy(&u0, &b0, 2); memcpy(&u1, &b1, 2);
    return (uint32_t)u0 | ((uint32_t)u1 << 16);
}
__device__ __forceinline__ uint32_t hpack(float f0, float f1) {
    __half2 h = __floats2half2_rn(f0, f1);
    uint32_t u;
    memcpy(&u, &h, 4);
    return u;
}
__device__ __forceinline__ float bfres(float f) {
    return f - __bfloat162float(__float2bfloat16(f));
}

// ---------------- tiny no-op (ncu capture alignment: launch idx 3 = mgemm control) ----------------
__global__ void noop_kernel() {}

// ---------------- weight split (bf16: patch + QKV) ----------------
__global__ void wsplit_bf16_kernel(const float* __restrict__ pW,
                                   const float* __restrict__ qkvW,
                                   __nv_bfloat16* __restrict__ GWh,
                                   __nv_bfloat16* __restrict__ GWl) {
    const int seg = blockIdx.y;       // 0 = patch, 1..12 = qkv layer
    int K, N;
    const float* src;
    long dstoff;
    if (seg == 0) { K = 768; N = 768; src = pW; dstoff = W_PATCH_OFF; }
    else { K = 768; N = 2304; src = qkvW + (long)(seg - 1) * 768 * 2304; dstoff = W_QKV_BASE + (long)(seg - 1) * W_QKV_SZ; }
    const int tn = N >> 5, tk = K >> 5;
    const int tile = blockIdx.x;
    if (tile >= tn * tk) return;
    const int n0 = (tile % tn) * 32, k0 = (tile / tn) * 32;

    __shared__ float t_[32][33];
    const int tx = threadIdx.x, ty = threadIdx.y;    // 32 x 8
    #pragma unroll
    for (int i = 0; i < 32; i += 8)
        t_[ty + i][tx] = src[(long)(k0 + ty + i) * N + n0 + tx];
    __syncthreads();
    __nv_bfloat16* Wh = GWh + dstoff;
    __nv_bfloat16* Wl = GWl + dstoff;
    #pragma unroll
    for (int i = 0; i < 32; i += 8) {
        float v = t_[tx][ty + i];
        long o = (long)(n0 + ty + i) * K + k0 + tx;
        __nv_bfloat16 h = __float2bfloat16(v);
        Wh[o] = h;
        Wl[o] = __float2bfloat16(v - __bfloat162float(h));
    }
}

// ---------------- weight split (fp16: out + fc1 + fc2) ----------------
__global__ void wsplit_fp16_kernel(const float* __restrict__ outW,
                                   const float* __restrict__ fc1W,
                                   const float* __restrict__ fc2W,
                                   __half* __restrict__ GFh,
                                   __half* __restrict__ GFl) {
    const int seg = blockIdx.y;       // 0..35 : t = seg%3, l = seg/3
    const int t = seg % 3, l = seg / 3;
    int K, N;
    const float* src;
    long dstoff;
    long fb = (long)l * F_LAYER_SZ;
    if (t == 0)      { K = 768;  N = 768;  src = outW + (long)l * 768 * 768;  dstoff = fb + F_OUT_OFF; }
    else if (t == 1) { K = 768;  N = 3072; src = fc1W + (long)l * 768 * 3072; dstoff = fb + F_FC1_OFF; }
    else             { K = 3072; N = 768;  src = fc2W + (long)l * 3072 * 768; dstoff = fb + F_FC2_OFF; }
    const int tn = N >> 5, tk = K >> 5;
    const int tile = blockIdx.x;
    if (tile >= tn * tk) return;
    const int n0 = (tile % tn) * 32, k0 = (tile / tn) * 32;

    __shared__ float t_[32][33];
    const int tx = threadIdx.x, ty = threadIdx.y;
    #pragma unroll
    for (int i = 0; i < 32; i += 8)
        t_[ty + i][tx] = src[(long)(k0 + ty + i) * N + n0 + tx];
    __syncthreads();
    __half* Wh = GFh + dstoff;
    __half* Wl = GFl + dstoff;
    #pragma unroll
    for (int i = 0; i < 32; i += 8) {
        float v = t_[tx][ty + i];
        long o = (long)(n0 + ty + i) * K + k0 + tx;
        __half h = __float2half(v);
        Wh[o] = h;
        Wl[o] = __float2half(v - __half2float(h));
    }
}

// ---------------- bf16 3-pass GEMM (patch + QKV): 128x64 tile, BK32 ----------------
// EPI: 0 store f32 | 1 +bias f32
static constexpr int MG_STAGE = 24576;            // Ah 8K + Al 8K + Bh 4K + Bl 4K
static constexpr int MG_SMEM  = 3 * MG_STAGE;     // 73728

template<int EPI>
__global__ void __launch_bounds__(256) mgemm_kernel(
    const __nv_bfloat16* __restrict__ Ah, const __nv_bfloat16* __restrict__ Al,
    const __nv_bfloat16* __restrict__ Wh, const __nv_bfloat16* __restrict__ Wl,
    const float* __restrict__ bias, float* __restrict__ C,
    int M, int N, int K)
{
    extern __shared__ char smc[];
    const uint32_t smb = smem_u32(smc);
    const int tid = threadIdx.x;
    const int lane = tid & 31, warp = tid >> 5;
    const int wm = warp >> 1, wn = warp & 1;      // 4m x 2n warp grid, 32x32 tiles
    const int n0 = blockIdx.x * 64, m0 = blockIdx.y * 128;
    const int KT = K >> 5;

    float acc[2][4][4];
    #pragma unroll
    for (int a = 0; a < 2; a++)
        #pragma unroll
        for (int b = 0; b < 4; b++)
            #pragma unroll
            for (int c = 0; c < 4; c++) acc[a][b][c] = 0.f;

    auto issue = [&](int kt, int s) {
        const int k0 = kt << 5;
        const uint32_t st = smb + s * MG_STAGE;
        #pragma unroll
        for (int i = 0; i < 2; i++) {
            int idx = tid + (i << 8);
            int row = idx >> 2, ch = idx & 3;
            uint32_t off = (uint32_t)(row * 64 + ((ch ^ ((row >> 1) & 3)) << 4));
            bool av = (m0 + row) < M;
            long aoff = (long)(m0 + row) * K + k0 + ch * 8;
            cp16(st +    0 + off, Ah + aoff, av);
            cp16(st + 8192 + off, Al + aoff, av);
        }
        {
            int row = tid >> 2, ch = tid & 3;
            uint32_t off = (uint32_t)(row * 64 + ((ch ^ ((row >> 1) & 3)) << 4));
            long boff = (long)(n0 + row) * K + k0 + ch * 8;
            cp16(st + 16384 + off, Wh + boff, true);
            cp16(st + 20480 + off, Wl + boff, true);
        }
    };
    auto ldaddr = [&](uint32_t tb, int r0, int ks) -> uint32_t {
        int row = r0 + (lane & 7) + ((lane & 8) ? 8 : 0);
        int ch  = (ks << 1) + ((lane >> 4) & 1);
        return tb + (uint32_t)(row * 64 + ((ch ^ ((row >> 1) & 3)) << 4));
    };

    issue(0, 0);
    cp_commit();
    if (KT > 1) issue(1, 1);
    cp_commit();

    for (int kt = 0; kt < KT; kt++) {
        cp_wait1();
        __syncthreads();
        int pf = kt + 2;
        if (pf < KT) issue(pf, pf % 3);
        cp_commit();

        const uint32_t st = smb + (kt % 3) * MG_STAGE;
        #pragma unroll
        for (int ks = 0; ks < 2; ks++) {
            uint32_t ah[2][4], al[2][4];
            #pragma unroll
            for (int mt = 0; mt < 2; mt++) {
                ldm4(ah[mt], ldaddr(st +    0, wm * 32 + mt * 16, ks));
                ldm4(al[mt], ldaddr(st + 8192, wm * 32 + mt * 16, ks));
            }
            #pragma unroll
            for (int g = 0; g < 2; g++) {
                uint32_t bh[4], bl[4];
                ldm4(bh, ldaddr(st + 16384, wn * 32 + g * 16, ks));
                ldm4(bl, ldaddr(st + 20480, wn * 32 + g * 16, ks));
                #pragma unroll
                for (int mt = 0; mt < 2; mt++)
                    #pragma unroll
                    for (int sl = 0; sl < 2; sl++) {
                        int nt = g * 2 + sl;
                        mma_bf16(acc[mt][nt], ah[mt], bh[sl], bh[sl + 2]);
                        mma_bf16(acc[mt][nt], ah[mt], bl[sl], bl[sl + 2]);
                        mma_bf16(acc[mt][nt], al[mt], bh[sl], bh[sl + 2]);
                    }
            }
        }
    }

    #pragma unroll
    for (int mt = 0; mt < 2; mt++)
        #pragma unroll
        for (int nt = 0; nt < 4; nt++) {
            int cb = n0 + wn * 32 + nt * 8 + (lane & 3) * 2;
            #pragma unroll
            for (int h = 0; h < 2; h++) {
                int r = m0 + wm * 32 + mt * 16 + (lane >> 2) + h * 8;
                if (r < M) {
                    float v0 = acc[mt][nt][h * 2 + 0];
                    float v1 = acc[mt][nt][h * 2 + 1];
                    if (EPI == 1) { v0 += bias[cb]; v1 += bias[cb + 1]; }
                    float* cp = C + (long)r * N + cb;
                    cp[0] = v0; cp[1] = v1;
                }
            }
        }
}

// ---------------- fp16 2-pass GEMM (out, FC1, FC2): A fp16 single, W fp16 hi/lo ----------------
// EPI: 2 +bias,gelu -> fp16 | 3 +bias,gelu,+=C f32 | 4 +=C f32
static constexpr int HG_STAGE = 16384;            // A 8K + Bh 4K + Bl 4K
static constexpr int HG_SMEM  = 3 * HG_STAGE;     // 49152

template<int EPI>
__global__ void __launch_bounds__(256) hgemm_kernel(
    const __half* __restrict__ A,
    const __half* __restrict__ Wh, const __half* __restrict__ Wl,
    const float* __restrict__ bias, float* __restrict__ C,
    __half* __restrict__ O,
    int M, int N, int K)
{
    extern __shared__ char smc[];
    const uint32_t smb = smem_u32(smc);
    const int tid = threadIdx.x;
    const int lane = tid & 31, warp = tid >> 5;
    const int wm = warp >> 1, wn = warp & 1;      // 4m x 2n, 32x32 warp tiles
    const int n0 = blockIdx.x * 64, m0 = blockIdx.y * 128;
    const int KT = K >> 5;

    float acc[2][4][4];
    #pragma unroll
    for (int a = 0; a < 2; a++)
        #pragma unroll
        for (int b = 0; b < 4; b++)
            #pragma unroll
            for (int c = 0; c < 4; c++) acc[a][b][c] = 0.f;

    auto issue = [&](int kt, int s) {
        const int k0 = kt << 5;
        const uint32_t st = smb + s * HG_STAGE;
        #pragma unroll
        for (int i = 0; i < 2; i++) {
            int idx = tid + (i << 8);               // 0..511
            int row = idx >> 2, ch = idx & 3;
            uint32_t off = (uint32_t)(row * 64 + ((ch ^ ((row >> 1) & 3)) << 4));
            bool av = (m0 + row) < M;
            long aoff = (long)(m0 + row) * K + k0 + ch * 8;
            cp16(st + off, A + aoff, av);
        }
        {
            int row = tid >> 2, ch = tid & 3;       // 64 rows x 4 chunks
            uint32_t off = (uint32_t)(row * 64 + ((ch ^ ((row >> 1) & 3)) << 4));
            long boff = (long)(n0 + row) * K + k0 + ch * 8;
            cp16(st +  8192 + off, Wh + boff, true);
            cp16(st + 12288 + off, Wl + boff, true);
        }
    };
    auto ldaddr = [&](uint32_t tb, int r0, int ks) -> uint32_t {
        int row = r0 + (lane & 7) + ((lane & 8) ? 8 : 0);
        int ch  = (ks << 1) + ((lane >> 4) & 1);
        return tb + (uint32_t)(row * 64 + ((ch ^ ((row >> 1) & 3)) << 4));
    };

    issue(0, 0);
    cp_commit();
    if (KT > 1) issue(1, 1);
    cp_commit();

    for (int kt = 0; kt < KT; kt++) {
        cp_wait1();
        __syncthreads();
        int pf = kt + 2;
        if (pf < KT) issue(pf, pf % 3);
        cp_commit();

        const uint32_t st = smb + (kt % 3) * HG_STAGE;
        #pragma unroll
        for (int ks = 0; ks < 2; ks++) {
            uint32_t a4[2][4];
            #pragma unroll
            for (int mt = 0; mt < 2; mt++)
                ldm4(a4[mt], ldaddr(st, wm * 32 + mt * 16, ks));
            #pragma unroll
            for (int g = 0; g < 2; g++) {
                uint32_t bh[4], bl[4];
                ldm4(bh, ldaddr(st +  8192, wn * 32 + g * 16, ks));
                ldm4(bl, ldaddr(st + 12288, wn * 32 + g * 16, ks));
                #pragma unroll
                for (int mt = 0; mt < 2; mt++)
                    #pragma unroll
                    for (int sl = 0; sl < 2; sl++) {
                        int nt = g * 2 + sl;
                        mma_f16(acc[mt][nt], a4[mt], bh[sl], bh[sl + 2]);
                        mma_f16(acc[mt][nt], a4[mt], bl[sl], bl[sl + 2]);
                    }
            }
        }
    }

    #pragma unroll
    for (int mt = 0; mt < 2; mt++)
        #pragma unroll
        for (int nt = 0; nt < 4; nt++) {
            int cb = n0 + wn * 32 + nt * 8 + (lane & 3) * 2;
            #pragma unroll
            for (int h = 0; h < 2; h++) {
                int r = m0 + wm * 32 + mt * 16 + (lane >> 2) + h * 8;
                if (r < M) {
                    float v0 = acc[mt][nt][h * 2 + 0];
                    float v1 = acc[mt][nt][h * 2 + 1];
                    if (EPI == 2 || EPI == 3) {
                        v0 = gelu_exact(v0 + bias[cb]);
                        v1 = gelu_exact(v1 + bias[cb + 1]);
                    }
                    if (EPI == 2) {
                        *(uint32_t*)(O + (long)r * N + cb) = hpack(v0, v1);
                    } else {
                        float* cp = C + (long)r * N + cb;
                        cp[0] = v0 + cp[0];
                        cp[1] = v1 + cp[1];
                    }
                }
            }
        }
}

// ---------------- tensor-core attention (bf16 3-pass internals, fp16 single out) ----------------
static constexpr int ATT_QH = 0;
static constexpr int ATT_QL = 26624;
static constexpr int ATT_KH = 53248;
static constexpr int ATT_KL = 81920;
static constexpr int ATT_VH = 110592;
static constexpr int ATT_VL = 143360;
static constexpr int ATT_SMEM = 176128;

__global__ void __launch_bounds__(256) attn_mma_kernel(const float* __restrict__ qkv,
                                                       __half* __restrict__ oo) {
    extern __shared__ char sma[];
    const uint32_t smb = smem_u32(sma);
    const int tid = threadIdx.x, lane = tid & 31, warp = tid >> 5;
    const int bb = blockIdx.x / NH, hh = blockIdx.x % NH;

    for (int i = tid; i < ATT_SMEM / 16; i += 256)
        *(uint4*)(sma + i * 16) = make_uint4(0, 0, 0, 0);
    __syncthreads();

    const float* base = qkv + (long)bb * NTOK * 2304 + hh * 64;
    for (int idx = tid; idx < NTOK * 64; idx += 256) {
        int row = idx >> 6, d = idx & 63;
        const float* rp = base + (long)row * 2304;
        float q = rp[d], k = rp[768 + d], v = rp[1536 + d];
        uint32_t qko = (uint32_t)(row * 128 + (((d >> 3) ^ (row & 7)) << 4) + (d & 7) * 2);
        __nv_bfloat16 t;
        t = __float2bfloat16(q);
        *(__nv_bfloat16*)(sma + ATT_QH + qko) = t;
        *(__nv_bfloat16*)(sma + ATT_QL + qko) = __float2bfloat16(q - __bfloat162float(t));
        t = __float2bfloat16(k);
        *(__nv_bfloat16*)(sma + ATT_KH + qko) = t;
        *(__nv_bfloat16*)(sma + ATT_KL + qko) = __float2bfloat16(k - __bfloat162float(t));
        uint32_t vo = (uint32_t)(d * 512 + (((row >> 3) ^ (d & 7)) << 4) + (row & 7) * 2);
        t = __float2bfloat16(v);
        *(__nv_bfloat16*)(sma + ATT_VH + vo) = t;
        *(__nv_bfloat16*)(sma + ATT_VL + vo) = __float2bfloat16(v - __bfloat162float(t));
    }
    __syncthreads();

    auto qkaddr = [&](uint32_t toff, int r0, int kt) -> uint32_t {
        int row = r0 + (lane & 7) + ((lane & 8) ? 8 : 0);
        int ch  = kt * 2 + (lane >> 4);
        return smb + toff + (uint32_t)(row * 128 + ((ch ^ (row & 7)) << 4));
    };
    auto vaddr = [&](uint32_t toff, int d0, int kt2) -> uint32_t {
        int row = d0 + (lane & 7) + ((lane & 8) ? 8 : 0);
        int ch  = kt2 * 2 + (lane >> 4);
        return smb + toff + (uint32_t)(row * 512 + ((ch ^ (row & 7)) << 4));
    };

    for (int mt = warp; mt < 13; mt += 8) {
        const int r0 = mt * 16;
        float sacc[28][4];
        #pragma unroll
        for (int n = 0; n < 28; n++)
            #pragma unroll
            for (int c = 0; c < 4; c++) sacc[n][c] = 0.f;

        uint32_t ah[4][4], al[4][4];
        #pragma unroll
        for (int kt = 0; kt < 4; kt++) {
            ldm4(ah[kt], qkaddr(ATT_QH, r0, kt));
            ldm4(al[kt], qkaddr(ATT_QL, r0, kt));
        }
        #pragma unroll
        for (int g = 0; g < 14; g++) {
            #pragma unroll
            for (int kt = 0; kt < 4; kt++) {
                uint32_t kh4[4], kl4[4];
                ldm4(kh4, qkaddr(ATT_KH, g * 16, kt));
                ldm4(kl4, qkaddr(ATT_KL, g * 16, kt));
                #pragma unroll
                for (int sl = 0; sl < 2; sl++) {
                    mma_bf16(sacc[2 * g + sl], ah[kt], kh4[sl], kh4[sl + 2]);
                    mma_bf16(sacc[2 * g + sl], al[kt], kh4[sl], kh4[sl + 2]);
                    mma_bf16(sacc[2 * g + sl], ah[kt], kl4[sl], kl4[sl + 2]);
                }
            }
        }

        const int cb = (lane & 3) * 2;
        float m0 = -1e30f, m1 = -1e30f;
        #pragma unroll
        for (int nt = 0; nt < 28; nt++) {
            int c0 = nt * 8 + cb;
            sacc[nt][0] = (c0     < 197) ? sacc[nt][0] * 0.125f : -1e30f;
            sacc[nt][1] = (c0 + 1 < 197) ? sacc[nt][1] * 0.125f : -1e30f;
            sacc[nt][2] = (c0     < 197) ? sacc[nt][2] * 0.125f : -1e30f;
            sacc[nt][3] = (c0 + 1 < 197) ? sacc[nt][3] * 0.125f : -1e30f;
            m0 = fmaxf(m0, fmaxf(sacc[nt][0], sacc[nt][1]));
            m1 = fmaxf(m1, fmaxf(sacc[nt][2], sacc[nt][3]));
        }
        m0 = fmaxf(m0, __shfl_xor_sync(0xffffffffu, m0, 1));
        m0 = fmaxf(m0, __shfl_xor_sync(0xffffffffu, m0, 2));
        m1 = fmaxf(m1, __shfl_xor_sync(0xffffffffu, m1, 1));
        m1 = fmaxf(m1, __shfl_xor_sync(0xffffffffu, m1, 2));
        float s0 = 0.f, s1 = 0.f;
        #pragma unroll
        for (int nt = 0; nt < 28; nt++) {
            sacc[nt][0] = __expf(sacc[nt][0] - m0);
            sacc[nt][1] = __expf(sacc[nt][1] - m0);
            sacc[nt][2] = __expf(sacc[nt][2] - m1);
            sacc[nt][3] = __expf(sacc[nt][3] - m1);
            s0 += sacc[nt][0] + sacc[nt][1];
            s1 += sacc[nt][2] + sacc[nt][3];
        }
        s0 += __shfl_xor_sync(0xffffffffu, s0, 1);
        s0 += __shfl_xor_sync(0xffffffffu, s0, 2);
        s1 += __shfl_xor_sync(0xffffffffu, s1, 1);
        s1 += __shfl_xor_sync(0xffffffffu, s1, 2);
        float i0 = 1.f / s0, i1 = 1.f / s1;
        #pragma unroll
        for (int nt = 0; nt < 28; nt++) {
            sacc[nt][0] *= i0; sacc[nt][1] *= i0;
            sacc[nt][2] *= i1; sacc[nt][3] *= i1;
        }

        float oacc[8][4];
        #pragma unroll
        for (int n = 0; n < 8; n++)
            #pragma unroll
            for (int c = 0; c < 4; c++) oacc[n][c] = 0.f;
        #pragma unroll
        for (int kt2 = 0; kt2 < 14; kt2++) {
            float p00 = sacc[2*kt2][0],   p01 = sacc[2*kt2][1];
            float p10 = sacc[2*kt2][2],   p11 = sacc[2*kt2][3];
            float q00 = sacc[2*kt2+1][0], q01 = sacc[2*kt2+1][1];
            float q10 = sacc[2*kt2+1][2], q11 = sacc[2*kt2+1][3];
            uint32_t pah[4], pal[4];
            pah[0] = bfpack(p00, p01); pal[0] = bfpack(bfres(p00), bfres(p01));
            pah[1] = bfpack(p10, p11); pal[1] = bfpack(bfres(p10), bfres(p11));
            pah[2] = bfpack(q00, q01); pal[2] = bfpack(bfres(q00), bfres(q01));
            pah[3] = bfpack(q10, q11); pal[3] = bfpack(bfres(q10), bfres(q11));
            #pragma unroll
            for (int g = 0; g < 4; g++) {
                uint32_t vh4[4], vl4[4];
                ldm4(vh4, vaddr(ATT_VH, g * 16, kt2));
                ldm4(vl4, vaddr(ATT_VL, g * 16, kt2));
                #pragma unroll
                for (int sl = 0; sl < 2; sl++) {
                    mma_bf16(oacc[2 * g + sl], pah, vh4[sl], vh4[sl + 2]);
                    mma_bf16(oacc[2 * g + sl], pal, vh4[sl], vh4[sl + 2]);
                    mma_bf16(oacc[2 * g + sl], pah, vl4[sl], vl4[sl + 2]);
                }
            }
        }

        // write output (fp16 single), rows < 197
        const int row0 = r0 + (lane >> 2), row1 = row0 + 8;
        #pragma unroll
        for (int nt = 0; nt < 8; nt++) {
            int d0 = nt * 8 + cb;
            if (row0 < NTOK) {
                long o = ((long)(bb * NTOK + row0)) * H_ + hh * 64 + d0;
                *(uint32_t*)(oo + o) = hpack(oacc[nt][0], oacc[nt][1]);
            }
            if (row1 < NTOK) {
                long o = ((long)(bb * NTOK + row1)) * H_ + hh * 64 + d0;
                *(uint32_t*)(oo + o) = hpack(oacc[nt][2], oacc[nt][3]);
            }
        }
    }
}

// ---------------- LayerNorm (768) -> bf16 hi/lo (QKV path) ----------------
__global__ void ln_kernel(const float* __restrict__ in, __nv_bfloat16* __restrict__ yh,
                          __nv_bfloat16* __restrict__ yl,
                          const float* __restrict__ g, const float* __restrict__ b) {
    const int row = blockIdx.x;
    const int tid = threadIdx.x;
    const float* x = in + (long)row * H_;
    float v0 = x[tid], v1 = x[tid + 256], v2 = x[tid + 512];
    __shared__ float red[256];
    __shared__ float s_mean, s_rstd;
    red[tid] = v0 + v1 + v2;
    __syncthreads();
    for (int o = 128; o > 0; o >>= 1) { if (tid < o) red[tid] += red[tid + o]; __syncthreads(); }
    if (tid == 0) s_mean = red[0] * (1.f / H_);
    __syncthreads();
    float m = s_mean;
    float d0 = v0 - m, d1 = v1 - m, d2 = v2 - m;
    red[tid] = d0 * d0 + d1 * d1 + d2 * d2;
    __syncthreads();
    for (int o = 128; o > 0; o >>= 1) { if (tid < o) red[tid] += red[tid + o]; __syncthreads(); }
    if (tid == 0) s_rstd = rsqrtf(red[0] * (1.f / H_) + 1e-5f);
    __syncthreads();
    float rs = s_rstd;
    long base = (long)row * H_;
    #pragma unroll
    for (int rr = 0; rr < 3; rr++) {
        int c = tid + rr * 256;
        float d = (rr == 0 ? d0 : rr == 1 ? d1 : d2);
        float v = d * rs * g[c] + b[c];
        __nv_bfloat16 h = __float2bfloat16(v);
        yh[base + c] = h;
        yl[base + c] = __float2bfloat16(v - __bfloat162float(h));
    }
}

// ---------------- LayerNorm (768) -> fp16 single (MLP path) ----------------
__global__ void ln_half_kernel(const float* __restrict__ in, __half* __restrict__ y,
                               const float* __restrict__ g, const float* __restrict__ b) {
    const int row = blockIdx.x;
    const int tid = threadIdx.x;
    const float* x = in + (long)row * H_;
    float v0 = x[tid], v1 = x[tid + 256], v2 = x[tid + 512];
    __shared__ float red[256];
    __shared__ float s_mean, s_rstd;
    red[tid] = v0 + v1 + v2;
    __syncthreads();
    for (int o = 128; o > 0; o >>= 1) { if (tid < o) red[tid] += red[tid + o]; __syncthreads(); }
    if (tid == 0) s_mean = red[0] * (1.f / H_);
    __syncthreads();
    float m = s_mean;
    float d0 = v0 - m, d1 = v1 - m, d2 = v2 - m;
    red[tid] = d0 * d0 + d1 * d1 + d2 * d2;
    __syncthreads();
    for (int o = 128; o > 0; o >>= 1) { if (tid < o) red[tid] += red[tid + o]; __syncthreads(); }
    if (tid == 0) s_rstd = rsqrtf(red[0] * (1.f / H_) + 1e-5f);
    __syncthreads();
    float rs = s_rstd;
    long base = (long)row * H_;
    y[base + tid]       = __float2half(d0 * rs * g[tid]       + b[tid]);
    y[base + tid + 256] = __float2half(d1 * rs * g[tid + 256] + b[tid + 256]);
    y[base + tid + 512] = __float2half(d2 * rs * g[tid + 512] + b[tid + 512]);
}

// ---------------- patchify + LN(pn1) -> bf16 hi/lo ----------------
__global__ void patchify_ln_kernel(const float* __restrict__ x,
                                   const float* __restrict__ g, const float* __restrict__ b,
                                   __nv_bfloat16* __restrict__ yh, __nv_bfloat16* __restrict__ yl) {
    const int pidx = blockIdx.x;
    const int bimg = pidx / NP;
    const int pp   = pidx % NP;
    const int hg = pp / GRD, wg = pp % GRD;
    const int tid = threadIdx.x;
    float v[3];
    #pragma unroll
    for (int r = 0; r < 3; r++) {
        int f = tid + r * 256;
        int p1 = f / 48, rem = f % 48, p2 = rem / 3, c = rem % 3;
        v[r] = x[(((long)bimg * CCH + c) * IMG + (hg * P_ + p1)) * IMG + (wg * P_ + p2)];
    }
    __shared__ float red[256];
    __shared__ float s_mean, s_rstd;
    red[tid] = v[0] + v[1] + v[2];
    __syncthreads();
    for (int o = 128; o > 0; o >>= 1) { if (tid < o) red[tid] += red[tid + o]; __syncthreads(); }
    if (tid == 0) s_mean = red[0] * (1.f / H_);
    __syncthreads();
    float m = s_mean;
    float d0 = v[0] - m, d1 = v[1] - m, d2 = v[2] - m;
    red[tid] = d0 * d0 + d1 * d1 + d2 * d2;
    __syncthreads();
    for (int o = 128; o > 0; o >>= 1) { if (tid < o) red[tid] += red[tid + o]; __syncthreads(); }
    if (tid == 0) s_rstd = rsqrtf(red[0] * (1.f / H_) + 1e-5f);
    __syncthreads();
    float rs = s_rstd;
    long base = (long)pidx * H_;
    #pragma unroll
    for (int rr = 0; rr < 3; rr++) {
        int c = tid + rr * 256;
        float d = (rr == 0 ? d0 : rr == 1 ? d1 : d2);
        float vv = d * rs * g[c] + b[c];
        __nv_bfloat16 h = __float2bfloat16(vv);
        yh[base + c] = h;
        yl[base + c] = __float2bfloat16(vv - __bfloat162float(h));
    }
}

// ---------------- LN(pn2) + cls + pos -> h (f32) ----------------
__global__ void assemble_kernel(const float* __restrict__ pemb,
                                const float* __restrict__ g, const float* __restrict__ b,
                                const float* __restrict__ cls, const float* __restrict__ pos,
                                float* __restrict__ h) {
    const int row = blockIdx.x;
    const int bb = row / NTOK, t = row % NTOK;
    const int tid = threadIdx.x;
    float* o_ = h + (long)row * H_;
    if (t == 0) {
        o_[tid]       = cls[tid]       + pos[tid];
        o_[tid + 256] = cls[tid + 256] + pos[tid + 256];
        o_[tid + 512] = cls[tid + 512] + pos[tid + 512];
        return;
    }
    const float* x = pemb + (long)(bb * NP + t - 1) * H_;
    float v0 = x[tid], v1 = x[tid + 256], v2 = x[tid + 512];
    __shared__ float red[256];
    __shared__ float s_mean, s_rstd;
    red[tid] = v0 + v1 + v2;
    __syncthreads();
    for (int o = 128; o > 0; o >>= 1) { if (tid < o) red[tid] += red[tid + o]; __syncthreads(); }
    if (tid == 0) s_mean = red[0] * (1.f / H_);
    __syncthreads();
    float m = s_mean;
    float d0 = v0 - m, d1 = v1 - m, d2 = v2 - m;
    red[tid] = d0 * d0 + d1 * d1 + d2 * d2;
    __syncthreads();
    for (int o = 128; o > 0; o >>= 1) { if (tid < o) red[tid] += red[tid + o]; __syncthreads(); }
    if (tid == 0) s_rstd = rsqrtf(red[0] * (1.f / H_) + 1e-5f);
    __syncthreads();
    float rs = s_rstd;
    const float* pp = pos + (long)t * H_;
    o_[tid]       = d0 * rs * g[tid]       + b[tid]       + pp[tid];
    o_[tid + 256] = d1 * rs * g[tid + 256] + b[tid + 256] + pp[tid + 256];
    o_[tid + 512] = d2 * rs * g[tid + 512] + b[tid + 512] + pp[tid + 512];
}

// ---------------- mean pool ----------------
__global__ void meanpool_kernel(const float* __restrict__ h, float* __restrict__ out) {
    const int bb = blockIdx.x;
    const int j = threadIdx.x;
    float s = 0.f;
    for (int i = 0; i < NTOK; i++) s += h[((long)bb * NTOK + i) * H_ + j];
    out[bb * H_ + j] = s * (1.f / NTOK);
}

// ---------------- host orchestration ----------------
static inline dim3 ggrid(int M, int N) { return dim3(N / 64, (M + 127) / 128); }

extern "C" void kernel_launch(void* const* d_in, const int* in_sizes, int n_in,
                              void* d_out, int out_size) {
    const float* x      = (const float*)d_in[0];
    const float* pn1_g  = (const float*)d_in[1];
    const float* pn1_b  = (const float*)d_in[2];
    const float* pW     = (const float*)d_in[3];
    const float* pb     = (const float*)d_in[4];
    const float* pn2_g  = (const float*)d_in[5];
    const float* pn2_b  = (const float*)d_in[6];
    const float* cls    = (const float*)d_in[7];
    const float* pos    = (const float*)d_in[8];
    const float* ln1_g  = (const float*)d_in[9];
    const float* ln1_b  = (const float*)d_in[10];
    const float* qkv_W  = (const float*)d_in[11];
    const float* out_W  = (const float*)d_in[12];
    const float* ln2_g  = (const float*)d_in[13];
    const float* ln2_b  = (const float*)d_in[14];
    const float* fc1_W  = (const float*)d_in[15];
    const float* fc1_b  = (const float*)d_in[16];
    const float* fc2_W  = (const float*)d_in[17];
    const float* fc2_b  = (const float*)d_in[18];
    float* out = (float*)d_out;

    float *p_h, *p_qkv, *p_tmp;
    __nv_bfloat16 *p_yh, *p_yl, *p_wh, *p_wl;
    __half *p_ha, *p_hy, *p_hm, *p_fh, *p_fl;
    cudaGetSymbolAddress((void**)&p_h,   g_h);
    cudaGetSymbolAddress((void**)&p_qkv, g_qkv);
    cudaGetSymbolAddress((void**)&p_tmp, g_tmp);
    cudaGetSymbolAddress((void**)&p_yh,  g_yh);
    cudaGetSymbolAddress((void**)&p_yl,  g_yl);
    cudaGetSymbolAddress((void**)&p_ha,  g_ha);
    cudaGetSymbolAddress((void**)&p_hy,  g_hy);
    cudaGetSymbolAddress((void**)&p_hm,  g_hm);
    cudaGetSymbolAddress((void**)&p_wh,  g_wh);
    cudaGetSymbolAddress((void**)&p_wl,  g_wl);
    cudaGetSymbolAddress((void**)&p_fh,  g_fh);
    cudaGetSymbolAddress((void**)&p_fl,  g_fl);

    cudaFuncSetAttribute(attn_mma_kernel, cudaFuncAttributeMaxDynamicSharedMemorySize, ATT_SMEM);
    cudaFuncSetAttribute(mgemm_kernel<0>, cudaFuncAttributeMaxDynamicSharedMemorySize, MG_SMEM);
    cudaFuncSetAttribute(mgemm_kernel<1>, cudaFuncAttributeMaxDynamicSharedMemorySize, MG_SMEM);
    cudaFuncSetAttribute(hgemm_kernel<2>, cudaFuncAttributeMaxDynamicSharedMemorySize, HG_SMEM);
    cudaFuncSetAttribute(hgemm_kernel<3>, cudaFuncAttributeMaxDynamicSharedMemorySize, HG_SMEM);
    cudaFuncSetAttribute(hgemm_kernel<4>, cudaFuncAttributeMaxDynamicSharedMemorySize, HG_SMEM);

    dim3 tb(32, 8);
    // idx 0: patchify + LN(pn1)
    patchify_ln_kernel<<<PROWS, 256>>>(x, pn1_g, pn1_b, p_yh, p_yl);
    // idx 1: bf16 weight split (patch + QKV)
    wsplit_bf16_kernel<<<dim3(1728, 13), tb>>>(pW, qkv_W, p_wh, p_wl);
    // idx 2: fp16 weight split (out + fc1 + fc2)
    wsplit_fp16_kernel<<<dim3(2304, 36), tb>>>(out_W, fc1_W, fc2_W, p_fh, p_fl);
    // idx 3: patch embed GEMM (bf16 3-pass control for ncu)
    mgemm_kernel<1><<<ggrid(PROWS, H_), 256, MG_SMEM>>>(p_yh, p_yl, p_wh + W_PATCH_OFF, p_wl + W_PATCH_OFF,
                                                        pb, p_tmp, PROWS, H_, H_);
    // LN(pn2) + cls + pos -> h
    assemble_kernel<<<ROWS, 256>>>(p_tmp, pn2_g, pn2_b, cls, pos, p_h);

    // transformer layers
    for (int l = 0; l < L_; l++) {
        long fb = (long)l * F_LAYER_SZ;
        const float* l1g = ln1_g + l * H_;
        const float* l1b = ln1_b + l * H_;
        const float* l2g = ln2_g + l * H_;
        const float* l2b = ln2_b + l * H_;
        const float* f1b = fc1_b + (long)l * MLP_;
        const float* f2b = fc2_b + (long)l * H_;

        ln_kernel<<<ROWS, 256>>>(p_h, p_yh, p_yl, l1g, l1b);
        mgemm_kernel<0><<<ggrid(ROWS, 3 * H_), 256, MG_SMEM>>>(
            p_yh, p_yl, p_wh + W_QKV_BASE + (long)l * W_QKV_SZ, p_wl + W_QKV_BASE + (long)l * W_QKV_SZ,
            nullptr, p_qkv, ROWS, 3 * H_, H_);
        attn_mma_kernel<<<B_ * NH, 256, ATT_SMEM>>>(p_qkv, p_ha);
        hgemm_kernel<4><<<ggrid(ROWS, H_), 256, HG_SMEM>>>(
            p_ha, p_fh + fb + F_OUT_OFF, p_fl + fb + F_OUT_OFF,
            nullptr, p_h, nullptr, ROWS, H_, H_);
        ln_half_kernel<<<ROWS, 256>>>(p_h, p_hy, l2g, l2b);
        hgemm_kernel<2><<<ggrid(ROWS, MLP_), 256, HG_SMEM>>>(
            p_hy, p_fh + fb + F_FC1_OFF, p_fl + fb + F_FC1_OFF,
            f1b, nullptr, p_hm, ROWS, MLP_, H_);
        hgemm_kernel<3><<<ggrid(ROWS, H_), 256, HG_SMEM>>>(
            p_hm, p_fh + fb + F_FC2_OFF, p_fl + fb + F_FC2_OFF,
            f2b, p_h, nullptr, ROWS, H_, MLP_);
    }

    // mean pool
    meanpool_kernel<<<B_, H_>>>(p_h, out);
}

// round 13
// speedup vs baseline: 1.4716x; 1.0951x over previous
#include <cuda_runtime.h>
#include <cuda_bf16.h>
#include <cuda_fp16.h>
#include <math.h>
#include <cstdint>

// ---------------- problem constants ----------------
static constexpr int B_   = 32;
static constexpr int CCH  = 3;
static constexpr int IMG  = 224;
static constexpr int P_   = 16;
static constexpr int GRD  = IMG / P_;        // 14
static constexpr int NP   = GRD * GRD;       // 196
static constexpr int NTOK = NP + 1;          // 197
static constexpr int H_   = 768;
static constexpr int NH   = 12;
static constexpr int HD   = 64;
static constexpr int MLP_ = 3072;
static constexpr int L_   = 12;
static constexpr int ROWS = B_ * NTOK;       // 6304
static constexpr int PROWS = B_ * NP;        // 6272

// fp16 weight scratch (ALL weights), transposed [N,K], hi/lo split
static constexpr long W_PATCH_OFF = 0;                        // 768x768
static constexpr long W_LAYER_BASE = 768L * 768;              // 589824
static constexpr long W_QKV_OFF = 0;                          // 2304x768
static constexpr long W_OUT_OFF = 768L * 2304;                // 1769472
static constexpr long W_FC1_OFF = W_OUT_OFF + 768L * 768;     // 2359296
static constexpr long W_FC2_OFF = W_FC1_OFF + 768L * 3072;    // 4718592
static constexpr long W_LAYER_SZ = W_FC2_OFF + 3072L * 768;   // 7077888
static constexpr long W_TOTAL = W_LAYER_BASE + 12L * W_LAYER_SZ;

// ---------------- device scratch ----------------
__device__ float g_h   [ROWS * H_];
__device__ float g_qkv [ROWS * 3 * H_];
__device__ float g_tmp [PROWS * H_];
__device__ __align__(256) __half g_hq [ROWS * H_];     // patchify / LN1 out (fp16 single)
__device__ __align__(256) __half g_hy [ROWS * H_];     // LN2 out (fp16 single)
__device__ __align__(256) __half g_ha [ROWS * H_];     // attention out (fp16 single)
__device__ __align__(256) __half g_hm [ROWS * MLP_];   // FC1+gelu out (fp16 single)
__device__ __align__(256) __half g_fh [W_TOTAL];
__device__ __align__(256) __half g_fl [W_TOTAL];

// ---------------- helpers ----------------
__device__ __forceinline__ uint32_t smem_u32(const void* p) {
    uint32_t a;
    asm("{ .reg .u64 t; cvta.to.shared.u64 t, %1; cvt.u32.u64 %0, t; }" : "=r"(a) : "l"(p));
    return a;
}
__device__ __forceinline__ void cp16(uint32_t dst, const void* src, bool valid) {
    int sz = valid ? 16 : 0;
    asm volatile("cp.async.cg.shared.global [%0], [%1], 16, %2;"
                 :: "r"(dst), "l"(src), "r"(sz) : "memory");
}
__device__ __forceinline__ void cp_commit() {
    asm volatile("cp.async.commit_group;" ::: "memory");
}
__device__ __forceinline__ void cp_wait1() {
    asm volatile("cp.async.wait_group 1;" ::: "memory");
}
__device__ __forceinline__ void ldm4(uint32_t* r, uint32_t addr) {
    asm volatile("ldmatrix.sync.aligned.m8n8.x4.shared.b16 {%0,%1,%2,%3}, [%4];"
                 : "=r"(r[0]), "=r"(r[1]), "=r"(r[2]), "=r"(r[3]) : "r"(addr));
}
__device__ __forceinline__ void mma_bf16(float* d, const uint32_t* a, uint32_t b0, uint32_t b1) {
    asm volatile(
        "mma.sync.aligned.m16n8k16.row.col.f32.bf16.bf16.f32 "
        "{%0,%1,%2,%3}, {%4,%5,%6,%7}, {%8,%9}, {%0,%1,%2,%3};"
        : "+f"(d[0]), "+f"(d[1]), "+f"(d[2]), "+f"(d[3])
        : "r"(a[0]), "r"(a[1]), "r"(a[2]), "r"(a[3]), "r"(b0), "r"(b1));
}
__device__ __forceinline__ void mma_f16(float* d, const uint32_t* a, uint32_t b0, uint32_t b1) {
    asm volatile(
        "mma.sync.aligned.m16n8k16.row.col.f32.f16.f16.f32 "
        "{%0,%1,%2,%3}, {%4,%5,%6,%7}, {%8,%9}, {%0,%1,%2,%3};"
        : "+f"(d[0]), "+f"(d[1]), "+f"(d[2]), "+f"(d[3])
        : "r"(a[0]), "r"(a[1]), "r"(a[2]), "r"(a[3]), "r"(b0), "r"(b1));
}
__device__ __forceinline__ float gelu_exact(float x) {
    return 0.5f * x * (1.0f + erff(x * 0.70710678118654752f));
}
__device__ __forceinline__ uint32_t bfpack(float f0, float f1) {
    __nv_bfloat16 b0 = __float2bfloat16(f0), b1 = __float2bfloat16(f1);
    uint16_t u0, u1;
    memcpy(&u0, &b0, 2); memcpy(&u1, &b1, 2);
    return (uint32_t)u0 | ((uint32_t)u1 << 16);
}
__device__ __forceinline__ uint32_t hpack(float f0, float f1) {
    __half2 h = __floats2half2_rn(f0, f1);
    uint32_t u;
    memcpy(&u, &h, 4);
    return u;
}
__device__ __forceinline__ float bfres(float f) {
    return f - __bfloat162float(__float2bfloat16(f));
}

// ---------------- mega weight split (ALL weights -> fp16 hi/lo, [N,K]) ----------------
__global__ void wsplit_mega_kernel(const float* __restrict__ pW,
                                   const float* __restrict__ qkvW,
                                   const float* __restrict__ outW,
                                   const float* __restrict__ fc1W,
                                   const float* __restrict__ fc2W,
                                   __half* __restrict__ GFh,
                                   __half* __restrict__ GFl) {
    const int seg = blockIdx.y;       // 0..48
    int K, N;
    const float* src;
    long dstoff;
    if (seg == 0) {
        K = 768; N = 768; src = pW; dstoff = W_PATCH_OFF;
    } else {
        int t = (seg - 1) & 3, l = (seg - 1) >> 2;
        long wb = W_LAYER_BASE + (long)l * W_LAYER_SZ;
        if (t == 0)      { K = 768;  N = 2304; src = qkvW + (long)l * 768 * 2304; dstoff = wb + W_QKV_OFF; }
        else if (t == 1) { K = 768;  N = 768;  src = outW + (long)l * 768 * 768;  dstoff = wb + W_OUT_OFF; }
        else if (t == 2) { K = 768;  N = 3072; src = fc1W + (long)l * 768 * 3072; dstoff = wb + W_FC1_OFF; }
        else             { K = 3072; N = 768;  src = fc2W + (long)l * 3072 * 768; dstoff = wb + W_FC2_OFF; }
    }
    const int tn = N >> 5, tk = K >> 5;
    const int tile = blockIdx.x;
    if (tile >= tn * tk) return;
    const int n0 = (tile % tn) * 32, k0 = (tile / tn) * 32;

    __shared__ float t_[32][33];
    const int tx = threadIdx.x, ty = threadIdx.y;    // 32 x 8
    #pragma unroll
    for (int i = 0; i < 32; i += 8)
        t_[ty + i][tx] = src[(long)(k0 + ty + i) * N + n0 + tx];
    __syncthreads();
    __half* Wh = GFh + dstoff;
    __half* Wl = GFl + dstoff;
    #pragma unroll
    for (int i = 0; i < 32; i += 8) {
        float v = t_[tx][ty + i];
        long o = (long)(n0 + ty + i) * K + k0 + tx;
        __half h = __float2half(v);
        Wh[o] = h;
        Wl[o] = __float2half(v - __half2float(h));
    }
}

// ---------------- fp16 2-pass GEMM (all GEMMs): A fp16 single, W fp16 hi/lo ----------------
// 128x64 CTA tile, BK32, 256 thr, 8 warps 4m x 2n (32x32 tiles), 3-stage cp.async.
// EPI: 0 store f32 | 1 +bias f32 | 2 +bias,gelu -> fp16 | 3 +bias,gelu,+=C f32 | 4 +=C f32
static constexpr int HG_STAGE = 16384;            // A 8K + Bh 4K + Bl 4K
static constexpr int HG_SMEM  = 3 * HG_STAGE;     // 49152

template<int EPI>
__global__ void __launch_bounds__(256) hgemm_kernel(
    const __half* __restrict__ A,
    const __half* __restrict__ Wh, const __half* __restrict__ Wl,
    const float* __restrict__ bias, float* __restrict__ C,
    __half* __restrict__ O,
    int M, int N, int K)
{
    extern __shared__ char smc[];
    const uint32_t smb = smem_u32(smc);
    const int tid = threadIdx.x;
    const int lane = tid & 31, warp = tid >> 5;
    const int wm = warp >> 1, wn = warp & 1;      // 4m x 2n, 32x32 warp tiles
    const int n0 = blockIdx.x * 64, m0 = blockIdx.y * 128;
    const int KT = K >> 5;

    float acc[2][4][4];
    #pragma unroll
    for (int a = 0; a < 2; a++)
        #pragma unroll
        for (int b = 0; b < 4; b++)
            #pragma unroll
            for (int c = 0; c < 4; c++) acc[a][b][c] = 0.f;

    auto issue = [&](int kt, int s) {
        const int k0 = kt << 5;
        const uint32_t st = smb + s * HG_STAGE;
        #pragma unroll
        for (int i = 0; i < 2; i++) {
            int idx = tid + (i << 8);               // 0..511
            int row = idx >> 2, ch = idx & 3;
            uint32_t off = (uint32_t)(row * 64 + ((ch ^ ((row >> 1) & 3)) << 4));
            bool av = (m0 + row) < M;
            long aoff = (long)(m0 + row) * K + k0 + ch * 8;
            cp16(st + off, A + aoff, av);
        }
        {
            int row = tid >> 2, ch = tid & 3;       // 64 rows x 4 chunks
            uint32_t off = (uint32_t)(row * 64 + ((ch ^ ((row >> 1) & 3)) << 4));
            long boff = (long)(n0 + row) * K + k0 + ch * 8;
            cp16(st +  8192 + off, Wh + boff, true);
            cp16(st + 12288 + off, Wl + boff, true);
        }
    };
    auto ldaddr = [&](uint32_t tb, int r0, int ks) -> uint32_t {
        int row = r0 + (lane & 7) + ((lane & 8) ? 8 : 0);
        int ch  = (ks << 1) + ((lane >> 4) & 1);
        return tb + (uint32_t)(row * 64 + ((ch ^ ((row >> 1) & 3)) << 4));
    };

    issue(0, 0);
    cp_commit();
    if (KT > 1) issue(1, 1);
    cp_commit();

    for (int kt = 0; kt < KT; kt++) {
        cp_wait1();
        __syncthreads();
        int pf = kt + 2;
        if (pf < KT) issue(pf, pf % 3);
        cp_commit();

        const uint32_t st = smb + (kt % 3) * HG_STAGE;
        #pragma unroll
        for (int ks = 0; ks < 2; ks++) {
            uint32_t a4[2][4];
            #pragma unroll
            for (int mt = 0; mt < 2; mt++)
                ldm4(a4[mt], ldaddr(st, wm * 32 + mt * 16, ks));
            #pragma unroll
            for (int g = 0; g < 2; g++) {
                uint32_t bh[4], bl[4];
                ldm4(bh, ldaddr(st +  8192, wn * 32 + g * 16, ks));
                ldm4(bl, ldaddr(st + 12288, wn * 32 + g * 16, ks));
                #pragma unroll
                for (int mt = 0; mt < 2; mt++)
                    #pragma unroll
                    for (int sl = 0; sl < 2; sl++) {
                        int nt = g * 2 + sl;
                        mma_f16(acc[mt][nt], a4[mt], bh[sl], bh[sl + 2]);
                        mma_f16(acc[mt][nt], a4[mt], bl[sl], bl[sl + 2]);
                    }
            }
        }
    }

    #pragma unroll
    for (int mt = 0; mt < 2; mt++)
        #pragma unroll
        for (int nt = 0; nt < 4; nt++) {
            int cb = n0 + wn * 32 + nt * 8 + (lane & 3) * 2;
            #pragma unroll
            for (int h = 0; h < 2; h++) {
                int r = m0 + wm * 32 + mt * 16 + (lane >> 2) + h * 8;
                if (r < M) {
                    float v0 = acc[mt][nt][h * 2 + 0];
                    float v1 = acc[mt][nt][h * 2 + 1];
                    if (EPI == 1) { v0 += bias[cb]; v1 += bias[cb + 1]; }
                    if (EPI == 2 || EPI == 3) {
                        v0 = gelu_exact(v0 + bias[cb]);
                        v1 = gelu_exact(v1 + bias[cb + 1]);
                    }
                    if (EPI == 2) {
                        *(uint32_t*)(O + (long)r * N + cb) = hpack(v0, v1);
                    } else {
                        float* cp = C + (long)r * N + cb;
                        if (EPI == 3 || EPI == 4) { v0 += cp[0]; v1 += cp[1]; }
                        cp[0] = v0; cp[1] = v1;
                    }
                }
            }
        }
}

// ---------------- tensor-core attention (bf16 3-pass internals, fp16 single out) ----------------
static constexpr int ATT_QH = 0;
static constexpr int ATT_QL = 26624;
static constexpr int ATT_KH = 53248;
static constexpr int ATT_KL = 81920;
static constexpr int ATT_VH = 110592;
static constexpr int ATT_VL = 143360;
static constexpr int ATT_SMEM = 176128;

__global__ void __launch_bounds__(256) attn_mma_kernel(const float* __restrict__ qkv,
                                                       __half* __restrict__ oo) {
    extern __shared__ char sma[];
    const uint32_t smb = smem_u32(sma);
    const int tid = threadIdx.x, lane = tid & 31, warp = tid >> 5;
    const int bb = blockIdx.x / NH, hh = blockIdx.x % NH;

    for (int i = tid; i < ATT_SMEM / 16; i += 256)
        *(uint4*)(sma + i * 16) = make_uint4(0, 0, 0, 0);
    __syncthreads();

    const float* base = qkv + (long)bb * NTOK * 2304 + hh * 64;
    for (int idx = tid; idx < NTOK * 64; idx += 256) {
        int row = idx >> 6, d = idx & 63;
        const float* rp = base + (long)row * 2304;
        float q = rp[d], k = rp[768 + d], v = rp[1536 + d];
        uint32_t qko = (uint32_t)(row * 128 + (((d >> 3) ^ (row & 7)) << 4) + (d & 7) * 2);
        __nv_bfloat16 t;
        t = __float2bfloat16(q);
        *(__nv_bfloat16*)(sma + ATT_QH + qko) = t;
        *(__nv_bfloat16*)(sma + ATT_QL + qko) = __float2bfloat16(q - __bfloat162float(t));
        t = __float2bfloat16(k);
        *(__nv_bfloat16*)(sma + ATT_KH + qko) = t;
        *(__nv_bfloat16*)(sma + ATT_KL + qko) = __float2bfloat16(k - __bfloat162float(t));
        uint32_t vo = (uint32_t)(d * 512 + (((row >> 3) ^ (d & 7)) << 4) + (row & 7) * 2);
        t = __float2bfloat16(v);
        *(__nv_bfloat16*)(sma + ATT_VH + vo) = t;
        *(__nv_bfloat16*)(sma + ATT_VL + vo) = __float2bfloat16(v - __bfloat162float(t));
    }
    __syncthreads();

    auto qkaddr = [&](uint32_t toff, int r0, int kt) -> uint32_t {
        int row = r0 + (lane & 7) + ((lane & 8) ? 8 : 0);
        int ch  = kt * 2 + (lane >> 4);
        return smb + toff + (uint32_t)(row * 128 + ((ch ^ (row & 7)) << 4));
    };
    auto vaddr = [&](uint32_t toff, int d0, int kt2) -> uint32_t {
        int row = d0 + (lane & 7) + ((lane & 8) ? 8 : 0);
        int ch  = kt2 * 2 + (lane >> 4);
        return smb + toff + (uint32_t)(row * 512 + ((ch ^ (row & 7)) << 4));
    };

    for (int mt = warp; mt < 13; mt += 8) {
        const int r0 = mt * 16;
        float sacc[28][4];
        #pragma unroll
        for (int n = 0; n < 28; n++)
            #pragma unroll
            for (int c = 0; c < 4; c++) sacc[n][c] = 0.f;

        uint32_t ah[4][4], al[4][4];
        #pragma unroll
        for (int kt = 0; kt < 4; kt++) {
            ldm4(ah[kt], qkaddr(ATT_QH, r0, kt));
            ldm4(al[kt], qkaddr(ATT_QL, r0, kt));
        }
        #pragma unroll
        for (int g = 0; g < 14; g++) {
            #pragma unroll
            for (int kt = 0; kt < 4; kt++) {
                uint32_t kh4[4], kl4[4];
                ldm4(kh4, qkaddr(ATT_KH, g * 16, kt));
                ldm4(kl4, qkaddr(ATT_KL, g * 16, kt));
                #pragma unroll
                for (int sl = 0; sl < 2; sl++) {
                    mma_bf16(sacc[2 * g + sl], ah[kt], kh4[sl], kh4[sl + 2]);
                    mma_bf16(sacc[2 * g + sl], al[kt], kh4[sl], kh4[sl + 2]);
                    mma_bf16(sacc[2 * g + sl], ah[kt], kl4[sl], kl4[sl + 2]);
                }
            }
        }

        const int cb = (lane & 3) * 2;
        float m0 = -1e30f, m1 = -1e30f;
        #pragma unroll
        for (int nt = 0; nt < 28; nt++) {
            int c0 = nt * 8 + cb;
            sacc[nt][0] = (c0     < 197) ? sacc[nt][0] * 0.125f : -1e30f;
            sacc[nt][1] = (c0 + 1 < 197) ? sacc[nt][1] * 0.125f : -1e30f;
            sacc[nt][2] = (c0     < 197) ? sacc[nt][2] * 0.125f : -1e30f;
            sacc[nt][3] = (c0 + 1 < 197) ? sacc[nt][3] * 0.125f : -1e30f;
            m0 = fmaxf(m0, fmaxf(sacc[nt][0], sacc[nt][1]));
            m1 = fmaxf(m1, fmaxf(sacc[nt][2], sacc[nt][3]));
        }
        m0 = fmaxf(m0, __shfl_xor_sync(0xffffffffu, m0, 1));
        m0 = fmaxf(m0, __shfl_xor_sync(0xffffffffu, m0, 2));
        m1 = fmaxf(m1, __shfl_xor_sync(0xffffffffu, m1, 1));
        m1 = fmaxf(m1, __shfl_xor_sync(0xffffffffu, m1, 2));
        float s0 = 0.f, s1 = 0.f;
        #pragma unroll
        for (int nt = 0; nt < 28; nt++) {
            sacc[nt][0] = __expf(sacc[nt][0] - m0);
            sacc[nt][1] = __expf(sacc[nt][1] - m0);
            sacc[nt][2] = __expf(sacc[nt][2] - m1);
            sacc[nt][3] = __expf(sacc[nt][3] - m1);
            s0 += sacc[nt][0] + sacc[nt][1];
            s1 += sacc[nt][2] + sacc[nt][3];
        }
        s0 += __shfl_xor_sync(0xffffffffu, s0, 1);
        s0 += __shfl_xor_sync(0xffffffffu, s0, 2);
        s1 += __shfl_xor_sync(0xffffffffu, s1, 1);
        s1 += __shfl_xor_sync(0xffffffffu, s1, 2);
        float i0 = 1.f / s0, i1 = 1.f / s1;
        #pragma unroll
        for (int nt = 0; nt < 28; nt++) {
            sacc[nt][0] *= i0; sacc[nt][1] *= i0;
            sacc[nt][2] *= i1; sacc[nt][3] *= i1;
        }

        float oacc[8][4];
        #pragma unroll
        for (int n = 0; n < 8; n++)
            #pragma unroll
            for (int c = 0; c < 4; c++) oacc[n][c] = 0.f;
        #pragma unroll
        for (int kt2 = 0; kt2 < 14; kt2++) {
            float p00 = sacc[2*kt2][0],   p01 = sacc[2*kt2][1];
            float p10 = sacc[2*kt2][2],   p11 = sacc[2*kt2][3];
            float q00 = sacc[2*kt2+1][0], q01 = sacc[2*kt2+1][1];
            float q10 = sacc[2*kt2+1][2], q11 = sacc[2*kt2+1][3];
            uint32_t pah[4], pal[4];
            pah[0] = bfpack(p00, p01); pal[0] = bfpack(bfres(p00), bfres(p01));
            pah[1] = bfpack(p10, p11); pal[1] = bfpack(bfres(p10), bfres(p11));
            pah[2] = bfpack(q00, q01); pal[2] = bfpack(bfres(q00), bfres(q01));
            pah[3] = bfpack(q10, q11); pal[3] = bfpack(bfres(q10), bfres(q11));
            #pragma unroll
            for (int g = 0; g < 4; g++) {
                uint32_t vh4[4], vl4[4];
                ldm4(vh4, vaddr(ATT_VH, g * 16, kt2));
                ldm4(vl4, vaddr(ATT_VL, g * 16, kt2));
                #pragma unroll
                for (int sl = 0; sl < 2; sl++) {
                    mma_bf16(oacc[2 * g + sl], pah, vh4[sl], vh4[sl + 2]);
                    mma_bf16(oacc[2 * g + sl], pal, vh4[sl], vh4[sl + 2]);
                    mma_bf16(oacc[2 * g + sl], pah, vl4[sl], vl4[sl + 2]);
                }
            }
        }

        const int row0 = r0 + (lane >> 2), row1 = row0 + 8;
        #pragma unroll
        for (int nt = 0; nt < 8; nt++) {
            int d0 = nt * 8 + cb;
            if (row0 < NTOK) {
                long o = ((long)(bb * NTOK + row0)) * H_ + hh * 64 + d0;
                *(uint32_t*)(oo + o) = hpack(oacc[nt][0], oacc[nt][1]);
            }
            if (row1 < NTOK) {
                long o = ((long)(bb * NTOK + row1)) * H_ + hh * 64 + d0;
                *(uint32_t*)(oo + o) = hpack(oacc[nt][2], oacc[nt][3]);
            }
        }
    }
}

// ---------------- LayerNorm (768) -> fp16 single ----------------
__global__ void ln_half_kernel(const float* __restrict__ in, __half* __restrict__ y,
                               const float* __restrict__ g, const float* __restrict__ b) {
    const int row = blockIdx.x;
    const int tid = threadIdx.x;
    const float* x = in + (long)row * H_;
    float v0 = x[tid], v1 = x[tid + 256], v2 = x[tid + 512];
    __shared__ float red[256];
    __shared__ float s_mean, s_rstd;
    red[tid] = v0 + v1 + v2;
    __syncthreads();
    for (int o = 128; o > 0; o >>= 1) { if (tid < o) red[tid] += red[tid + o]; __syncthreads(); }
    if (tid == 0) s_mean = red[0] * (1.f / H_);
    __syncthreads();
    float m = s_mean;
    float d0 = v0 - m, d1 = v1 - m, d2 = v2 - m;
    red[tid] = d0 * d0 + d1 * d1 + d2 * d2;
    __syncthreads();
    for (int o = 128; o > 0; o >>= 1) { if (tid < o) red[tid] += red[tid + o]; __syncthreads(); }
    if (tid == 0) s_rstd = rsqrtf(red[0] * (1.f / H_) + 1e-5f);
    __syncthreads();
    float rs = s_rstd;
    long base = (long)row * H_;
    y[base + tid]       = __float2half(d0 * rs * g[tid]       + b[tid]);
    y[base + tid + 256] = __float2half(d1 * rs * g[tid + 256] + b[tid + 256]);
    y[base + tid + 512] = __float2half(d2 * rs * g[tid + 512] + b[tid + 512]);
}

// ---------------- patchify + LN(pn1) -> fp16 single ----------------
__global__ void patchify_ln_kernel(const float* __restrict__ x,
                                   const float* __restrict__ g, const float* __restrict__ b,
                                   __half* __restrict__ y) {
    const int pidx = blockIdx.x;
    const int bimg = pidx / NP;
    const int pp   = pidx % NP;
    const int hg = pp / GRD, wg = pp % GRD;
    const int tid = threadIdx.x;
    float v[3];
    #pragma unroll
    for (int r = 0; r < 3; r++) {
        int f = tid + r * 256;
        int p1 = f / 48, rem = f % 48, p2 = rem / 3, c = rem % 3;
        v[r] = x[(((long)bimg * CCH + c) * IMG + (hg * P_ + p1)) * IMG + (wg * P_ + p2)];
    }
    __shared__ float red[256];
    __shared__ float s_mean, s_rstd;
    red[tid] = v[0] + v[1] + v[2];
    __syncthreads();
    for (int o = 128; o > 0; o >>= 1) { if (tid < o) red[tid] += red[tid + o]; __syncthreads(); }
    if (tid == 0) s_mean = red[0] * (1.f / H_);
    __syncthreads();
    float m = s_mean;
    float d0 = v[0] - m, d1 = v[1] - m, d2 = v[2] - m;
    red[tid] = d0 * d0 + d1 * d1 + d2 * d2;
    __syncthreads();
    for (int o = 128; o > 0; o >>= 1) { if (tid < o) red[tid] += red[tid + o]; __syncthreads(); }
    if (tid == 0) s_rstd = rsqrtf(red[0] * (1.f / H_) + 1e-5f);
    __syncthreads();
    float rs = s_rstd;
    long base = (long)pidx * H_;
    y[base + tid]       = __float2half(d0 * rs * g[tid]       + b[tid]);
    y[base + tid + 256] = __float2half(d1 * rs * g[tid + 256] + b[tid + 256]);
    y[base + tid + 512] = __float2half(d2 * rs * g[tid + 512] + b[tid + 512]);
}

// ---------------- LN(pn2) + cls + pos -> h (f32) ----------------
__global__ void assemble_kernel(const float* __restrict__ pemb,
                                const float* __restrict__ g, const float* __restrict__ b,
                                const float* __restrict__ cls, const float* __restrict__ pos,
                                float* __restrict__ h) {
    const int row = blockIdx.x;
    const int bb = row / NTOK, t = row % NTOK;
    const int tid = threadIdx.x;
    float* o_ = h + (long)row * H_;
    if (t == 0) {
        o_[tid]       = cls[tid]       + pos[tid];
        o_[tid + 256] = cls[tid + 256] + pos[tid + 256];
        o_[tid + 512] = cls[tid + 512] + pos[tid + 512];
        return;
    }
    const float* x = pemb + (long)(bb * NP + t - 1) * H_;
    float v0 = x[tid], v1 = x[tid + 256], v2 = x[tid + 512];
    __shared__ float red[256];
    __shared__ float s_mean, s_rstd;
    red[tid] = v0 + v1 + v2;
    __syncthreads();
    for (int o = 128; o > 0; o >>= 1) { if (tid < o) red[tid] += red[tid + o]; __syncthreads(); }
    if (tid == 0) s_mean = red[0] * (1.f / H_);
    __syncthreads();
    float m = s_mean;
    float d0 = v0 - m, d1 = v1 - m, d2 = v2 - m;
    red[tid] = d0 * d0 + d1 * d1 + d2 * d2;
    __syncthreads();
    for (int o = 128; o > 0; o >>= 1) { if (tid < o) red[tid] += red[tid + o]; __syncthreads(); }
    if (tid == 0) s_rstd = rsqrtf(red[0] * (1.f / H_) + 1e-5f);
    __syncthreads();
    float rs = s_rstd;
    const float* pp = pos + (long)t * H_;
    o_[tid]       = d0 * rs * g[tid]       + b[tid]       + pp[tid];
    o_[tid + 256] = d1 * rs * g[tid + 256] + b[tid + 256] + pp[tid + 256];
    o_[tid + 512] = d2 * rs * g[tid + 512] + b[tid + 512] + pp[tid + 512];
}

// ---------------- mean pool ----------------
__global__ void meanpool_kernel(const float* __restrict__ h, float* __restrict__ out) {
    const int bb = blockIdx.x;
    const int j = threadIdx.x;
    float s = 0.f;
    for (int i = 0; i < NTOK; i++) s += h[((long)bb * NTOK + i) * H_ + j];
    out[bb * H_ + j] = s * (1.f / NTOK);
}

// ---------------- host orchestration ----------------
static inline dim3 ggrid(int M, int N) { return dim3(N / 64, (M + 127) / 128); }

extern "C" void kernel_launch(void* const* d_in, const int* in_sizes, int n_in,
                              void* d_out, int out_size) {
    const float* x      = (const float*)d_in[0];
    const float* pn1_g  = (const float*)d_in[1];
    const float* pn1_b  = (const float*)d_in[2];
    const float* pW     = (const float*)d_in[3];
    const float* pb     = (const float*)d_in[4];
    const float* pn2_g  = (const float*)d_in[5];
    const float* pn2_b  = (const float*)d_in[6];
    const float* cls    = (const float*)d_in[7];
    const float* pos    = (const float*)d_in[8];
    const float* ln1_g  = (const float*)d_in[9];
    const float* ln1_b  = (const float*)d_in[10];
    const float* qkv_W  = (const float*)d_in[11];
    const float* out_W  = (const float*)d_in[12];
    const float* ln2_g  = (const float*)d_in[13];
    const float* ln2_b  = (const float*)d_in[14];
    const float* fc1_W  = (const float*)d_in[15];
    const float* fc1_b  = (const float*)d_in[16];
    const float* fc2_W  = (const float*)d_in[17];
    const float* fc2_b  = (const float*)d_in[18];
    float* out = (float*)d_out;

    float *p_h, *p_qkv, *p_tmp;
    __half *p_hq, *p_hy, *p_ha, *p_hm, *p_fh, *p_fl;
    cudaGetSymbolAddress((void**)&p_h,   g_h);
    cudaGetSymbolAddress((void**)&p_qkv, g_qkv);
    cudaGetSymbolAddress((void**)&p_tmp, g_tmp);
    cudaGetSymbolAddress((void**)&p_hq,  g_hq);
    cudaGetSymbolAddress((void**)&p_hy,  g_hy);
    cudaGetSymbolAddress((void**)&p_ha,  g_ha);
    cudaGetSymbolAddress((void**)&p_hm,  g_hm);
    cudaGetSymbolAddress((void**)&p_fh,  g_fh);
    cudaGetSymbolAddress((void**)&p_fl,  g_fl);

    cudaFuncSetAttribute(attn_mma_kernel, cudaFuncAttributeMaxDynamicSharedMemorySize, ATT_SMEM);
    cudaFuncSetAttribute(hgemm_kernel<0>, cudaFuncAttributeMaxDynamicSharedMemorySize, HG_SMEM);
    cudaFuncSetAttribute(hgemm_kernel<1>, cudaFuncAttributeMaxDynamicSharedMemorySize, HG_SMEM);
    cudaFuncSetAttribute(hgemm_kernel<2>, cudaFuncAttributeMaxDynamicSharedMemorySize, HG_SMEM);
    cudaFuncSetAttribute(hgemm_kernel<3>, cudaFuncAttributeMaxDynamicSharedMemorySize, HG_SMEM);
    cudaFuncSetAttribute(hgemm_kernel<4>, cudaFuncAttributeMaxDynamicSharedMemorySize, HG_SMEM);

    dim3 tb(32, 8);
    // idx 0: patchify + LN(pn1) -> fp16
    patchify_ln_kernel<<<PROWS, 256>>>(x, pn1_g, pn1_b, p_hq);
    // idx 1: mega weight split (all weights -> fp16 hi/lo)
    wsplit_mega_kernel<<<dim3(2304, 49), tb>>>(pW, qkv_W, out_W, fc1_W, fc2_W, p_fh, p_fl);
    // idx 2: patch embed GEMM + bias -> g_tmp (f32)
    hgemm_kernel<1><<<ggrid(PROWS, H_), 256, HG_SMEM>>>(p_hq, p_fh + W_PATCH_OFF, p_fl + W_PATCH_OFF,
                                                        pb, p_tmp, nullptr, PROWS, H_, H_);
    // idx 3: LN(pn2) + cls + pos -> h
    assemble_kernel<<<ROWS, 256>>>(p_tmp, pn2_g, pn2_b, cls, pos, p_h);

    // transformer layers (idx 4 = LN1, idx 5 = QKV hgemm, ...)
    for (int l = 0; l < L_; l++) {
        long wb = W_LAYER_BASE + (long)l * W_LAYER_SZ;
        const float* l1g = ln1_g + l * H_;
        const float* l1b = ln1_b + l * H_;
        const float* l2g = ln2_g + l * H_;
        const float* l2b = ln2_b + l * H_;
        const float* f1b = fc1_b + (long)l * MLP_;
        const float* f2b = fc2_b + (long)l * H_;

        ln_half_kernel<<<ROWS, 256>>>(p_h, p_hq, l1g, l1b);
        hgemm_kernel<0><<<ggrid(ROWS, 3 * H_), 256, HG_SMEM>>>(
            p_hq, p_fh + wb + W_QKV_OFF, p_fl + wb + W_QKV_OFF,
            nullptr, p_qkv, nullptr, ROWS, 3 * H_, H_);
        attn_mma_kernel<<<B_ * NH, 256, ATT_SMEM>>>(p_qkv, p_ha);
        hgemm_kernel<4><<<ggrid(ROWS, H_), 256, HG_SMEM>>>(
            p_ha, p_fh + wb + W_OUT_OFF, p_fl + wb + W_OUT_OFF,
            nullptr, p_h, nullptr, ROWS, H_, H_);
        ln_half_kernel<<<ROWS, 256>>>(p_h, p_hy, l2g, l2b);
        hgemm_kernel<2><<<ggrid(ROWS, MLP_), 256, HG_SMEM>>>(
            p_hy, p_fh + wb + W_FC1_OFF, p_fl + wb + W_FC1_OFF,
            f1b, nullptr, p_hm, ROWS, MLP_, H_);
        hgemm_kernel<3><<<ggrid(ROWS, H_), 256, HG_SMEM>>>(
            p_hm, p_fh + wb + W_FC2_OFF, p_fl + wb + W_FC2_OFF,
            f2b, p_h, nullptr, ROWS, H_, MLP_);
    }

    // mean pool
    meanpool_kernel<<<B_, H_>>>(p_h, out);
}

// round 14
// speedup vs baseline: 1.5824x; 1.0753x over previous
#include <cuda_runtime.h>
#include <cuda_bf16.h>
#include <cuda_fp16.h>
#include <math.h>
#include <cstdint>

// ---------------- problem constants ----------------
static constexpr int B_   = 32;
static constexpr int CCH  = 3;
static constexpr int IMG  = 224;
static constexpr int P_   = 16;
static constexpr int GRD  = IMG / P_;        // 14
static constexpr int NP   = GRD * GRD;       // 196
static constexpr int NTOK = NP + 1;          // 197
static constexpr int H_   = 768;
static constexpr int NH   = 12;
static constexpr int HD   = 64;
static constexpr int MLP_ = 3072;
static constexpr int L_   = 12;
static constexpr int ROWS = B_ * NTOK;       // 6304
static constexpr int PROWS = B_ * NP;        // 6272

// fp16 weight scratch (ALL weights), transposed [N,K], hi/lo split
static constexpr long W_PATCH_OFF = 0;                        // 768x768
static constexpr long W_LAYER_BASE = 768L * 768;
static constexpr long W_QKV_OFF = 0;                          // 2304x768
static constexpr long W_OUT_OFF = 768L * 2304;
static constexpr long W_FC1_OFF = W_OUT_OFF + 768L * 768;
static constexpr long W_FC2_OFF = W_FC1_OFF + 768L * 3072;
static constexpr long W_LAYER_SZ = W_FC2_OFF + 3072L * 768;
static constexpr long W_TOTAL = W_LAYER_BASE + 12L * W_LAYER_SZ;

// ---------------- device scratch ----------------
__device__ float g_h   [ROWS * H_];
__device__ float g_tmp [PROWS * H_];
__device__ __align__(256) __half g_qkv [ROWS * 3 * H_];  // QKV (fp16 single)
__device__ __align__(256) __half g_hq [ROWS * H_];       // patchify / LN1 out
__device__ __align__(256) __half g_hy [ROWS * H_];       // LN2 out
__device__ __align__(256) __half g_ha [ROWS * H_];       // attention out
__device__ __align__(256) __half g_hm [ROWS * MLP_];     // FC1+gelu out
__device__ __align__(256) __half g_fh [W_TOTAL];
__device__ __align__(256) __half g_fl [W_TOTAL];

// ---------------- helpers ----------------
__device__ __forceinline__ uint32_t smem_u32(const void* p) {
    uint32_t a;
    asm("{ .reg .u64 t; cvta.to.shared.u64 t, %1; cvt.u32.u64 %0, t; }" : "=r"(a) : "l"(p));
    return a;
}
__device__ __forceinline__ void cp16(uint32_t dst, const void* src, bool valid) {
    int sz = valid ? 16 : 0;
    asm volatile("cp.async.cg.shared.global [%0], [%1], 16, %2;"
                 :: "r"(dst), "l"(src), "r"(sz) : "memory");
}
__device__ __forceinline__ void cp_commit() {
    asm volatile("cp.async.commit_group;" ::: "memory");
}
__device__ __forceinline__ void cp_wait1() {
    asm volatile("cp.async.wait_group 1;" ::: "memory");
}
__device__ __forceinline__ void ldm4(uint32_t* r, uint32_t addr) {
    asm volatile("ldmatrix.sync.aligned.m8n8.x4.shared.b16 {%0,%1,%2,%3}, [%4];"
                 : "=r"(r[0]), "=r"(r[1]), "=r"(r[2]), "=r"(r[3]) : "r"(addr));
}
__device__ __forceinline__ void mma_f16(float* d, const uint32_t* a, uint32_t b0, uint32_t b1) {
    asm volatile(
        "mma.sync.aligned.m16n8k16.row.col.f32.f16.f16.f32 "
        "{%0,%1,%2,%3}, {%4,%5,%6,%7}, {%8,%9}, {%0,%1,%2,%3};"
        : "+f"(d[0]), "+f"(d[1]), "+f"(d[2]), "+f"(d[3])
        : "r"(a[0]), "r"(a[1]), "r"(a[2]), "r"(a[3]), "r"(b0), "r"(b1));
}
__device__ __forceinline__ float gelu_exact(float x) {
    return 0.5f * x * (1.0f + erff(x * 0.70710678118654752f));
}
__device__ __forceinline__ uint32_t hpack(float f0, float f1) {
    __half2 h = __floats2half2_rn(f0, f1);
    uint32_t u;
    memcpy(&u, &h, 4);
    return u;
}

// ---------------- mega weight split (ALL weights -> fp16 hi/lo, [N,K]) ----------------
__global__ void wsplit_mega_kernel(const float* __restrict__ pW,
                                   const float* __restrict__ qkvW,
                                   const float* __restrict__ outW,
                                   const float* __restrict__ fc1W,
                                   const float* __restrict__ fc2W,
                                   __half* __restrict__ GFh,
                                   __half* __restrict__ GFl) {
    const int seg = blockIdx.y;       // 0..48
    int K, N;
    const float* src;
    long dstoff;
    if (seg == 0) {
        K = 768; N = 768; src = pW; dstoff = W_PATCH_OFF;
    } else {
        int t = (seg - 1) & 3, l = (seg - 1) >> 2;
        long wb = W_LAYER_BASE + (long)l * W_LAYER_SZ;
        if (t == 0)      { K = 768;  N = 2304; src = qkvW + (long)l * 768 * 2304; dstoff = wb + W_QKV_OFF; }
        else if (t == 1) { K = 768;  N = 768;  src = outW + (long)l * 768 * 768;  dstoff = wb + W_OUT_OFF; }
        else if (t == 2) { K = 768;  N = 3072; src = fc1W + (long)l * 768 * 3072; dstoff = wb + W_FC1_OFF; }
        else             { K = 3072; N = 768;  src = fc2W + (long)l * 3072 * 768; dstoff = wb + W_FC2_OFF; }
    }
    const int tn = N >> 5, tk = K >> 5;
    const int tile = blockIdx.x;
    if (tile >= tn * tk) return;
    const int n0 = (tile % tn) * 32, k0 = (tile / tn) * 32;

    __shared__ float t_[32][33];
    const int tx = threadIdx.x, ty = threadIdx.y;    // 32 x 8
    #pragma unroll
    for (int i = 0; i < 32; i += 8)
        t_[ty + i][tx] = src[(long)(k0 + ty + i) * N + n0 + tx];
    __syncthreads();
    __half* Wh = GFh + dstoff;
    __half* Wl = GFl + dstoff;
    #pragma unroll
    for (int i = 0; i < 32; i += 8) {
        float v = t_[tx][ty + i];
        long o = (long)(n0 + ty + i) * K + k0 + tx;
        __half h = __float2half(v);
        Wh[o] = h;
        Wl[o] = __float2half(v - __half2float(h));
    }
}

// ---------------- fp16 2-pass GEMM: A fp16 single, W fp16 hi/lo ----------------
// 128x64 CTA tile, BK32, 256 thr, 8 warps 4m x 2n (32x32 tiles), 3-stage cp.async.
// EPI: 0 store f32 | 1 +bias f32 | 2 +bias,gelu -> fp16 | 3 +bias,gelu,+=C f32 | 4 +=C f32 | 5 store fp16
static constexpr int HG_STAGE = 16384;            // A 8K + Bh 4K + Bl 4K
static constexpr int HG_SMEM  = 3 * HG_STAGE;     // 49152

template<int EPI>
__global__ void __launch_bounds__(256) hgemm_kernel(
    const __half* __restrict__ A,
    const __half* __restrict__ Wh, const __half* __restrict__ Wl,
    const float* __restrict__ bias, float* __restrict__ C,
    __half* __restrict__ O,
    int M, int N, int K)
{
    extern __shared__ char smc[];
    const uint32_t smb = smem_u32(smc);
    const int tid = threadIdx.x;
    const int lane = tid & 31, warp = tid >> 5;
    const int wm = warp >> 1, wn = warp & 1;
    const int n0 = blockIdx.x * 64, m0 = blockIdx.y * 128;
    const int KT = K >> 5;

    float acc[2][4][4];
    #pragma unroll
    for (int a = 0; a < 2; a++)
        #pragma unroll
        for (int b = 0; b < 4; b++)
            #pragma unroll
            for (int c = 0; c < 4; c++) acc[a][b][c] = 0.f;

    auto issue = [&](int kt, int s) {
        const int k0 = kt << 5;
        const uint32_t st = smb + s * HG_STAGE;
        #pragma unroll
        for (int i = 0; i < 2; i++) {
            int idx = tid + (i << 8);
            int row = idx >> 2, ch = idx & 3;
            uint32_t off = (uint32_t)(row * 64 + ((ch ^ ((row >> 1) & 3)) << 4));
            bool av = (m0 + row) < M;
            long aoff = (long)(m0 + row) * K + k0 + ch * 8;
            cp16(st + off, A + aoff, av);
        }
        {
            int row = tid >> 2, ch = tid & 3;
            uint32_t off = (uint32_t)(row * 64 + ((ch ^ ((row >> 1) & 3)) << 4));
            long boff = (long)(n0 + row) * K + k0 + ch * 8;
            cp16(st +  8192 + off, Wh + boff, true);
            cp16(st + 12288 + off, Wl + boff, true);
        }
    };
    auto ldaddr = [&](uint32_t tb, int r0, int ks) -> uint32_t {
        int row = r0 + (lane & 7) + ((lane & 8) ? 8 : 0);
        int ch  = (ks << 1) + ((lane >> 4) & 1);
        return tb + (uint32_t)(row * 64 + ((ch ^ ((row >> 1) & 3)) << 4));
    };

    issue(0, 0);
    cp_commit();
    if (KT > 1) issue(1, 1);
    cp_commit();

    for (int kt = 0; kt < KT; kt++) {
        cp_wait1();
        __syncthreads();
        int pf = kt + 2;
        if (pf < KT) issue(pf, pf % 3);
        cp_commit();

        const uint32_t st = smb + (kt % 3) * HG_STAGE;
        #pragma unroll
        for (int ks = 0; ks < 2; ks++) {
            uint32_t a4[2][4];
            #pragma unroll
            for (int mt = 0; mt < 2; mt++)
                ldm4(a4[mt], ldaddr(st, wm * 32 + mt * 16, ks));
            #pragma unroll
            for (int g = 0; g < 2; g++) {
                uint32_t bh[4], bl[4];
                ldm4(bh, ldaddr(st +  8192, wn * 32 + g * 16, ks));
                ldm4(bl, ldaddr(st + 12288, wn * 32 + g * 16, ks));
                #pragma unroll
                for (int mt = 0; mt < 2; mt++)
                    #pragma unroll
                    for (int sl = 0; sl < 2; sl++) {
                        int nt = g * 2 + sl;
                        mma_f16(acc[mt][nt], a4[mt], bh[sl], bh[sl + 2]);
                        mma_f16(acc[mt][nt], a4[mt], bl[sl], bl[sl + 2]);
                    }
            }
        }
    }

    #pragma unroll
    for (int mt = 0; mt < 2; mt++)
        #pragma unroll
        for (int nt = 0; nt < 4; nt++) {
            int cb = n0 + wn * 32 + nt * 8 + (lane & 3) * 2;
            #pragma unroll
            for (int h = 0; h < 2; h++) {
                int r = m0 + wm * 32 + mt * 16 + (lane >> 2) + h * 8;
                if (r < M) {
                    float v0 = acc[mt][nt][h * 2 + 0];
                    float v1 = acc[mt][nt][h * 2 + 1];
                    if (EPI == 1) { v0 += bias[cb]; v1 += bias[cb + 1]; }
                    if (EPI == 2 || EPI == 3) {
                        v0 = gelu_exact(v0 + bias[cb]);
                        v1 = gelu_exact(v1 + bias[cb + 1]);
                    }
                    if (EPI == 2 || EPI == 5) {
                        *(uint32_t*)(O + (long)r * N + cb) = hpack(v0, v1);
                    } else {
                        float* cp = C + (long)r * N + cb;
                        if (EPI == 3 || EPI == 4) { v0 += cp[0]; v1 += cp[1]; }
                        cp[0] = v0; cp[1] = v1;
                    }
                }
            }
        }
}

// ---------------- tensor-core attention (fp16 single, 1-pass QK + 1-pass PV) ----------------
static constexpr int ATT_Q = 0;                      // 208 rows x 128B (swizzled)
static constexpr int ATT_K = 26624;                  // 224 rows x 128B
static constexpr int ATT_V = 55296;                  // Vt: 64 rows x 512B (token-major)
static constexpr int ATT_SMEM = 88064;

__global__ void __launch_bounds__(256) attn_mma_kernel(const __half* __restrict__ qkv,
                                                       __half* __restrict__ oo) {
    extern __shared__ char sma[];
    const uint32_t smb = smem_u32(sma);
    const int tid = threadIdx.x, lane = tid & 31, warp = tid >> 5;
    const int bb = blockIdx.x / NH, hh = blockIdx.x % NH;

    // zero tiles (padding rows/cols must be 0)
    for (int i = tid; i < ATT_SMEM / 16; i += 256)
        *(uint4*)(sma + i * 16) = make_uint4(0, 0, 0, 0);
    __syncthreads();

    // stage Q,K (row-major d) and Vt (token-major), fp16 single
    const __half* base = qkv + (long)bb * NTOK * 2304 + hh * 64;
    for (int idx = tid; idx < NTOK * 64; idx += 256) {
        int row = idx >> 6, d = idx & 63;
        const __half* rp = base + (long)row * 2304;
        uint32_t qko = (uint32_t)(row * 128 + (((d >> 3) ^ (row & 7)) << 4) + (d & 7) * 2);
        *(__half*)(sma + ATT_Q + qko) = rp[d];
        *(__half*)(sma + ATT_K + qko) = rp[768 + d];
        uint32_t vo = (uint32_t)(d * 512 + (((row >> 3) ^ (d & 7)) << 4) + (row & 7) * 2);
        *(__half*)(sma + ATT_V + vo) = rp[1536 + d];
    }
    __syncthreads();

    auto qkaddr = [&](uint32_t toff, int r0, int kt) -> uint32_t {
        int row = r0 + (lane & 7) + ((lane & 8) ? 8 : 0);
        int ch  = kt * 2 + (lane >> 4);
        return smb + toff + (uint32_t)(row * 128 + ((ch ^ (row & 7)) << 4));
    };
    auto vaddr = [&](int d0, int kt2) -> uint32_t {
        int row = d0 + (lane & 7) + ((lane & 8) ? 8 : 0);
        int ch  = kt2 * 2 + (lane >> 4);
        return smb + ATT_V + (uint32_t)(row * 512 + ((ch ^ (row & 7)) << 4));
    };

    for (int mt = warp; mt < 13; mt += 8) {
        const int r0 = mt * 16;
        float sacc[28][4];
        #pragma unroll
        for (int n = 0; n < 28; n++)
            #pragma unroll
            for (int c = 0; c < 4; c++) sacc[n][c] = 0.f;

        uint32_t aq[4][4];
        #pragma unroll
        for (int kt = 0; kt < 4; kt++)
            ldm4(aq[kt], qkaddr(ATT_Q, r0, kt));
        #pragma unroll
        for (int g = 0; g < 14; g++) {
            #pragma unroll
            for (int kt = 0; kt < 4; kt++) {
                uint32_t k4[4];
                ldm4(k4, qkaddr(ATT_K, g * 16, kt));
                #pragma unroll
                for (int sl = 0; sl < 2; sl++)
                    mma_f16(sacc[2 * g + sl], aq[kt], k4[sl], k4[sl + 2]);
            }
        }

        // softmax (row0 = r0 + lane>>2, row1 = +8); cols = nt*8 + (lane&3)*2 (+1)
        const int cb = (lane & 3) * 2;
        float m0 = -1e30f, m1 = -1e30f;
        #pragma unroll
        for (int nt = 0; nt < 28; nt++) {
            int c0 = nt * 8 + cb;
            sacc[nt][0] = (c0     < 197) ? sacc[nt][0] * 0.125f : -1e30f;
            sacc[nt][1] = (c0 + 1 < 197) ? sacc[nt][1] * 0.125f : -1e30f;
            sacc[nt][2] = (c0     < 197) ? sacc[nt][2] * 0.125f : -1e30f;
            sacc[nt][3] = (c0 + 1 < 197) ? sacc[nt][3] * 0.125f : -1e30f;
            m0 = fmaxf(m0, fmaxf(sacc[nt][0], sacc[nt][1]));
            m1 = fmaxf(m1, fmaxf(sacc[nt][2], sacc[nt][3]));
        }
        m0 = fmaxf(m0, __shfl_xor_sync(0xffffffffu, m0, 1));
        m0 = fmaxf(m0, __shfl_xor_sync(0xffffffffu, m0, 2));
        m1 = fmaxf(m1, __shfl_xor_sync(0xffffffffu, m1, 1));
        m1 = fmaxf(m1, __shfl_xor_sync(0xffffffffu, m1, 2));
        float s0 = 0.f, s1 = 0.f;
        #pragma unroll
        for (int nt = 0; nt < 28; nt++) {
            sacc[nt][0] = __expf(sacc[nt][0] - m0);
            sacc[nt][1] = __expf(sacc[nt][1] - m0);
            sacc[nt][2] = __expf(sacc[nt][2] - m1);
            sacc[nt][3] = __expf(sacc[nt][3] - m1);
            s0 += sacc[nt][0] + sacc[nt][1];
            s1 += sacc[nt][2] + sacc[nt][3];
        }
        s0 += __shfl_xor_sync(0xffffffffu, s0, 1);
        s0 += __shfl_xor_sync(0xffffffffu, s0, 2);
        s1 += __shfl_xor_sync(0xffffffffu, s1, 1);
        s1 += __shfl_xor_sync(0xffffffffu, s1, 2);
        float i0 = 1.f / s0, i1 = 1.f / s1;
        #pragma unroll
        for (int nt = 0; nt < 28; nt++) {
            sacc[nt][0] *= i0; sacc[nt][1] *= i0;
            sacc[nt][2] *= i1; sacc[nt][3] *= i1;
        }

        // O = P V (P fp16 single from registers, Vt fp16 from smem)
        float oacc[8][4];
        #pragma unroll
        for (int n = 0; n < 8; n++)
            #pragma unroll
            for (int c = 0; c < 4; c++) oacc[n][c] = 0.f;
        #pragma unroll
        for (int kt2 = 0; kt2 < 14; kt2++) {
            uint32_t pa[4];
            pa[0] = hpack(sacc[2*kt2][0],   sacc[2*kt2][1]);
            pa[1] = hpack(sacc[2*kt2][2],   sacc[2*kt2][3]);
            pa[2] = hpack(sacc[2*kt2+1][0], sacc[2*kt2+1][1]);
            pa[3] = hpack(sacc[2*kt2+1][2], sacc[2*kt2+1][3]);
            #pragma unroll
            for (int g = 0; g < 4; g++) {
                uint32_t v4[4];
                ldm4(v4, vaddr(g * 16, kt2));
                #pragma unroll
                for (int sl = 0; sl < 2; sl++)
                    mma_f16(oacc[2 * g + sl], pa, v4[sl], v4[sl + 2]);
            }
        }

        const int row0 = r0 + (lane >> 2), row1 = row0 + 8;
        #pragma unroll
        for (int nt = 0; nt < 8; nt++) {
            int d0 = nt * 8 + cb;
            if (row0 < NTOK) {
                long o = ((long)(bb * NTOK + row0)) * H_ + hh * 64 + d0;
                *(uint32_t*)(oo + o) = hpack(oacc[nt][0], oacc[nt][1]);
            }
            if (row1 < NTOK) {
                long o = ((long)(bb * NTOK + row1)) * H_ + hh * 64 + d0;
                *(uint32_t*)(oo + o) = hpack(oacc[nt][2], oacc[nt][3]);
            }
        }
    }
}

// ---------------- LayerNorm (768) -> fp16 single ----------------
__global__ void ln_half_kernel(const float* __restrict__ in, __half* __restrict__ y,
                               const float* __restrict__ g, const float* __restrict__ b) {
    const int row = blockIdx.x;
    const int tid = threadIdx.x;
    const float* x = in + (long)row * H_;
    float v0 = x[tid], v1 = x[tid + 256], v2 = x[tid + 512];
    __shared__ float red[256];
    __shared__ float s_mean, s_rstd;
    red[tid] = v0 + v1 + v2;
    __syncthreads();
    for (int o = 128; o > 0; o >>= 1) { if (tid < o) red[tid] += red[tid + o]; __syncthreads(); }
    if (tid == 0) s_mean = red[0] * (1.f / H_);
    __syncthreads();
    float m = s_mean;
    float d0 = v0 - m, d1 = v1 - m, d2 = v2 - m;
    red[tid] = d0 * d0 + d1 * d1 + d2 * d2;
    __syncthreads();
    for (int o = 128; o > 0; o >>= 1) { if (tid < o) red[tid] += red[tid + o]; __syncthreads(); }
    if (tid == 0) s_rstd = rsqrtf(red[0] * (1.f / H_) + 1e-5f);
    __syncthreads();
    float rs = s_rstd;
    long base = (long)row * H_;
    y[base + tid]       = __float2half(d0 * rs * g[tid]       + b[tid]);
    y[base + tid + 256] = __float2half(d1 * rs * g[tid + 256] + b[tid + 256]);
    y[base + tid + 512] = __float2half(d2 * rs * g[tid + 512] + b[tid + 512]);
}

// ---------------- patchify + LN(pn1) -> fp16 single ----------------
__global__ void patchify_ln_kernel(const float* __restrict__ x,
                                   const float* __restrict__ g, const float* __restrict__ b,
                                   __half* __restrict__ y) {
    const int pidx = blockIdx.x;
    const int bimg = pidx / NP;
    const int pp   = pidx % NP;
    const int hg = pp / GRD, wg = pp % GRD;
    const int tid = threadIdx.x;
    float v[3];
    #pragma unroll
    for (int r = 0; r < 3; r++) {
        int f = tid + r * 256;
        int p1 = f / 48, rem = f % 48, p2 = rem / 3, c = rem % 3;
        v[r] = x[(((long)bimg * CCH + c) * IMG + (hg * P_ + p1)) * IMG + (wg * P_ + p2)];
    }
    __shared__ float red[256];
    __shared__ float s_mean, s_rstd;
    red[tid] = v[0] + v[1] + v[2];
    __syncthreads();
    for (int o = 128; o > 0; o >>= 1) { if (tid < o) red[tid] += red[tid + o]; __syncthreads(); }
    if (tid == 0) s_mean = red[0] * (1.f / H_);
    __syncthreads();
    float m = s_mean;
    float d0 = v[0] - m, d1 = v[1] - m, d2 = v[2] - m;
    red[tid] = d0 * d0 + d1 * d1 + d2 * d2;
    __syncthreads();
    for (int o = 128; o > 0; o >>= 1) { if (tid < o) red[tid] += red[tid + o]; __syncthreads(); }
    if (tid == 0) s_rstd = rsqrtf(red[0] * (1.f / H_) + 1e-5f);
    __syncthreads();
    float rs = s_rstd;
    long base = (long)pidx * H_;
    y[base + tid]       = __float2half(d0 * rs * g[tid]       + b[tid]);
    y[base + tid + 256] = __float2half(d1 * rs * g[tid + 256] + b[tid + 256]);
    y[base + tid + 512] = __float2half(d2 * rs * g[tid + 512] + b[tid + 512]);
}

// ---------------- LN(pn2) + cls + pos -> h (f32) ----------------
__global__ void assemble_kernel(const float* __restrict__ pemb,
                                const float* __restrict__ g, const float* __restrict__ b,
                                const float* __restrict__ cls, const float* __restrict__ pos,
                                float* __restrict__ h) {
    const int row = blockIdx.x;
    const int bb = row / NTOK, t = row % NTOK;
    const int tid = threadIdx.x;
    float* o_ = h + (long)row * H_;
    if (t == 0) {
        o_[tid]       = cls[tid]       + pos[tid];
        o_[tid + 256] = cls[tid + 256] + pos[tid + 256];
        o_[tid + 512] = cls[tid + 512] + pos[tid + 512];
        return;
    }
    const float* x = pemb + (long)(bb * NP + t - 1) * H_;
    float v0 = x[tid], v1 = x[tid + 256], v2 = x[tid + 512];
    __shared__ float red[256];
    __shared__ float s_mean, s_rstd;
    red[tid] = v0 + v1 + v2;
    __syncthreads();
    for (int o = 128; o > 0; o >>= 1) { if (tid < o) red[tid] += red[tid + o]; __syncthreads(); }
    if (tid == 0) s_mean = red[0] * (1.f / H_);
    __syncthreads();
    float m = s_mean;
    float d0 = v0 - m, d1 = v1 - m, d2 = v2 - m;
    red[tid] = d0 * d0 + d1 * d1 + d2 * d2;
    __syncthreads();
    for (int o = 128; o > 0; o >>= 1) { if (tid < o) red[tid] += red[tid + o]; __syncthreads(); }
    if (tid == 0) s_rstd = rsqrtf(red[0] * (1.f / H_) + 1e-5f);
    __syncthreads();
    float rs = s_rstd;
    const float* pp = pos + (long)t * H_;
    o_[tid]       = d0 * rs * g[tid]       + b[tid]       + pp[tid];
    o_[tid + 256] = d1 * rs * g[tid + 256] + b[tid + 256] + pp[tid + 256];
    o_[tid + 512] = d2 * rs * g[tid + 512] + b[tid + 512] + pp[tid + 512];
}

// ---------------- mean pool ----------------
__global__ void meanpool_kernel(const float* __restrict__ h, float* __restrict__ out) {
    const int bb = blockIdx.x;
    const int j = threadIdx.x;
    float s = 0.f;
    for (int i = 0; i < NTOK; i++) s += h[((long)bb * NTOK + i) * H_ + j];
    out[bb * H_ + j] = s * (1.f / NTOK);
}

// ---------------- host orchestration ----------------
static inline dim3 ggrid(int M, int N) { return dim3(N / 64, (M + 127) / 128); }

extern "C" void kernel_launch(void* const* d_in, const int* in_sizes, int n_in,
                              void* d_out, int out_size) {
    const float* x      = (const float*)d_in[0];
    const float* pn1_g  = (const float*)d_in[1];
    const float* pn1_b  = (const float*)d_in[2];
    const float* pW     = (const float*)d_in[3];
    const float* pb     = (const float*)d_in[4];
    const float* pn2_g  = (const float*)d_in[5];
    const float* pn2_b  = (const float*)d_in[6];
    const float* cls    = (const float*)d_in[7];
    const float* pos    = (const float*)d_in[8];
    const float* ln1_g  = (const float*)d_in[9];
    const float* ln1_b  = (const float*)d_in[10];
    const float* qkv_W  = (const float*)d_in[11];
    const float* out_W  = (const float*)d_in[12];
    const float* ln2_g  = (const float*)d_in[13];
    const float* ln2_b  = (const float*)d_in[14];
    const float* fc1_W  = (const float*)d_in[15];
    const float* fc1_b  = (const float*)d_in[16];
    const float* fc2_W  = (const float*)d_in[17];
    const float* fc2_b  = (const float*)d_in[18];
    float* out = (float*)d_out;

    float *p_h, *p_tmp;
    __half *p_qkv, *p_hq, *p_hy, *p_ha, *p_hm, *p_fh, *p_fl;
    cudaGetSymbolAddress((void**)&p_h,   g_h);
    cudaGetSymbolAddress((void**)&p_tmp, g_tmp);
    cudaGetSymbolAddress((void**)&p_qkv, g_qkv);
    cudaGetSymbolAddress((void**)&p_hq,  g_hq);
    cudaGetSymbolAddress((void**)&p_hy,  g_hy);
    cudaGetSymbolAddress((void**)&p_ha,  g_ha);
    cudaGetSymbolAddress((void**)&p_hm,  g_hm);
    cudaGetSymbolAddress((void**)&p_fh,  g_fh);
    cudaGetSymbolAddress((void**)&p_fl,  g_fl);

    cudaFuncSetAttribute(attn_mma_kernel, cudaFuncAttributeMaxDynamicSharedMemorySize, ATT_SMEM);
    cudaFuncSetAttribute(hgemm_kernel<1>, cudaFuncAttributeMaxDynamicSharedMemorySize, HG_SMEM);
    cudaFuncSetAttribute(hgemm_kernel<2>, cudaFuncAttributeMaxDynamicSharedMemorySize, HG_SMEM);
    cudaFuncSetAttribute(hgemm_kernel<3>, cudaFuncAttributeMaxDynamicSharedMemorySize, HG_SMEM);
    cudaFuncSetAttribute(hgemm_kernel<4>, cudaFuncAttributeMaxDynamicSharedMemorySize, HG_SMEM);
    cudaFuncSetAttribute(hgemm_kernel<5>, cudaFuncAttributeMaxDynamicSharedMemorySize, HG_SMEM);

    dim3 tb(32, 8);
    // idx 0: patchify + LN(pn1) -> fp16
    patchify_ln_kernel<<<PROWS, 256>>>(x, pn1_g, pn1_b, p_hq);
    // idx 1: mega weight split (all weights -> fp16 hi/lo)
    wsplit_mega_kernel<<<dim3(2304, 49), tb>>>(pW, qkv_W, out_W, fc1_W, fc2_W, p_fh, p_fl);
    // idx 2: patch embed GEMM + bias -> g_tmp (f32)
    hgemm_kernel<1><<<ggrid(PROWS, H_), 256, HG_SMEM>>>(p_hq, p_fh + W_PATCH_OFF, p_fl + W_PATCH_OFF,
                                                        pb, p_tmp, nullptr, PROWS, H_, H_);
    // idx 3: LN(pn2) + cls + pos -> h
    assemble_kernel<<<ROWS, 256>>>(p_tmp, pn2_g, pn2_b, cls, pos, p_h);

    // transformer layers
    for (int l = 0; l < L_; l++) {
        long wb = W_LAYER_BASE + (long)l * W_LAYER_SZ;
        const float* l1g = ln1_g + l * H_;
        const float* l1b = ln1_b + l * H_;
        const float* l2g = ln2_g + l * H_;
        const float* l2b = ln2_b + l * H_;
        const float* f1b = fc1_b + (long)l * MLP_;
        const float* f2b = fc2_b + (long)l * H_;

        ln_half_kernel<<<ROWS, 256>>>(p_h, p_hq, l1g, l1b);
        hgemm_kernel<5><<<ggrid(ROWS, 3 * H_), 256, HG_SMEM>>>(
            p_hq, p_fh + wb + W_QKV_OFF, p_fl + wb + W_QKV_OFF,
            nullptr, nullptr, p_qkv, ROWS, 3 * H_, H_);
        attn_mma_kernel<<<B_ * NH, 256, ATT_SMEM>>>(p_qkv, p_ha);
        hgemm_kernel<4><<<ggrid(ROWS, H_), 256, HG_SMEM>>>(
            p_ha, p_fh + wb + W_OUT_OFF, p_fl + wb + W_OUT_OFF,
            nullptr, p_h, nullptr, ROWS, H_, H_);
        ln_half_kernel<<<ROWS, 256>>>(p_h, p_hy, l2g, l2b);
        hgemm_kernel<2><<<ggrid(ROWS, MLP_), 256, HG_SMEM>>>(
            p_hy, p_fh + wb + W_FC1_OFF, p_fl + wb + W_FC1_OFF,
            f1b, nullptr, p_hm, ROWS, MLP_, H_);
        hgemm_kernel<3><<<ggrid(ROWS, H_), 256, HG_SMEM>>>(
            p_hm, p_fh + wb + W_FC2_OFF, p_fl + wb + W_FC2_OFF,
            f2b, p_h, nullptr, ROWS, H_, MLP_);
    }

    // mean pool
    meanpool_kernel<<<B_, H_>>>(p_h, out);
}

// round 16
// speedup vs baseline: 2.3893x; 1.5099x over previous
#include <cuda_runtime.h>
#include <cuda_bf16.h>
#include <cuda_fp16.h>
#include <math.h>
#include <cstdint>

// ---------------- problem constants ----------------
static constexpr int B_   = 32;
static constexpr int CCH  = 3;
static constexpr int IMG  = 224;
static constexpr int P_   = 16;
static constexpr int GRD  = IMG / P_;        // 14
static constexpr int NP   = GRD * GRD;       // 196
static constexpr int NTOK = NP + 1;          // 197
static constexpr int H_   = 768;
static constexpr int NH   = 12;
static constexpr int HD   = 64;
static constexpr int MLP_ = 3072;
static constexpr int L_   = 12;
static constexpr int ROWS = B_ * NTOK;       // 6304
static constexpr int PROWS = B_ * NP;        // 6272

// fp16 weight scratch (ALL weights), transposed [N,K], single fp16
static constexpr long W_PATCH_OFF = 0;                        // 768x768
static constexpr long W_LAYER_BASE = 768L * 768;
static constexpr long W_QKV_OFF = 0;                          // 2304x768
static constexpr long W_OUT_OFF = 768L * 2304;
static constexpr long W_FC1_OFF = W_OUT_OFF + 768L * 768;
static constexpr long W_FC2_OFF = W_FC1_OFF + 768L * 3072;
static constexpr long W_LAYER_SZ = W_FC2_OFF + 3072L * 768;
static constexpr long W_TOTAL = W_LAYER_BASE + 12L * W_LAYER_SZ;

// ---------------- device scratch ----------------
__device__ float g_h   [ROWS * H_];
__device__ float g_tmp [PROWS * H_];
__device__ __align__(256) __half g_qkv [ROWS * 3 * H_];  // QKV (fp16 single)
__device__ __align__(256) __half g_hq [ROWS * H_];       // patchify / LN1 out
__device__ __align__(256) __half g_hy [ROWS * H_];       // LN2 out
__device__ __align__(256) __half g_ha [ROWS * H_];       // attention out
__device__ __align__(256) __half g_hm [ROWS * MLP_];     // FC1+gelu out
__device__ __align__(256) __half g_fh [W_TOTAL];

// ---------------- helpers ----------------
__device__ __forceinline__ uint32_t smem_u32(const void* p) {
    uint32_t a;
    asm("{ .reg .u64 t; cvta.to.shared.u64 t, %1; cvt.u32.u64 %0, t; }" : "=r"(a) : "l"(p));
    return a;
}
__device__ __forceinline__ void cp16(uint32_t dst, const void* src, bool valid) {
    int sz = valid ? 16 : 0;
    asm volatile("cp.async.cg.shared.global [%0], [%1], 16, %2;"
                 :: "r"(dst), "l"(src), "r"(sz) : "memory");
}
__device__ __forceinline__ void cp_commit() {
    asm volatile("cp.async.commit_group;" ::: "memory");
}
__device__ __forceinline__ void cp_wait1() {
    asm volatile("cp.async.wait_group 1;" ::: "memory");
}
__device__ __forceinline__ void ldm4(uint32_t* r, uint32_t addr) {
    asm volatile("ldmatrix.sync.aligned.m8n8.x4.shared.b16 {%0,%1,%2,%3}, [%4];"
                 : "=r"(r[0]), "=r"(r[1]), "=r"(r[2]), "=r"(r[3]) : "r"(addr));
}
__device__ __forceinline__ void mma_f16(float* d, const uint32_t* a, uint32_t b0, uint32_t b1) {
    asm volatile(
        "mma.sync.aligned.m16n8k16.row.col.f32.f16.f16.f32 "
        "{%0,%1,%2,%3}, {%4,%5,%6,%7}, {%8,%9}, {%0,%1,%2,%3};"
        : "+f"(d[0]), "+f"(d[1]), "+f"(d[2]), "+f"(d[3])
        : "r"(a[0]), "r"(a[1]), "r"(a[2]), "r"(a[3]), "r"(b0), "r"(b1));
}
__device__ __forceinline__ float gelu_exact(float x) {
    return 0.5f * x * (1.0f + erff(x * 0.70710678118654752f));
}
__device__ __forceinline__ uint32_t hpack(float f0, float f1) {
    __half2 h = __floats2half2_rn(f0, f1);
    uint32_t u;
    memcpy(&u, &h, 4);
    return u;
}

// ---------------- mega weight split (ALL weights -> fp16 single, [N,K]) ----------------
__global__ void wsplit_mega_kernel(const float* __restrict__ pW,
                                   const float* __restrict__ qkvW,
                                   const float* __restrict__ outW,
                                   const float* __restrict__ fc1W,
                                   const float* __restrict__ fc2W,
                                   __half* __restrict__ GFh) {
    const int seg = blockIdx.y;       // 0..48
    int K, N;
    const float* src;
    long dstoff;
    if (seg == 0) {
        K = 768; N = 768; src = pW; dstoff = W_PATCH_OFF;
    } else {
        int t = (seg - 1) & 3, l = (seg - 1) >> 2;
        long wb = W_LAYER_BASE + (long)l * W_LAYER_SZ;
        if (t == 0)      { K = 768;  N = 2304; src = qkvW + (long)l * 768 * 2304; dstoff = wb + W_QKV_OFF; }
        else if (t == 1) { K = 768;  N = 768;  src = outW + (long)l * 768 * 768;  dstoff = wb + W_OUT_OFF; }
        else if (t == 2) { K = 768;  N = 3072; src = fc1W + (long)l * 768 * 3072; dstoff = wb + W_FC1_OFF; }
        else             { K = 3072; N = 768;  src = fc2W + (long)l * 3072 * 768; dstoff = wb + W_FC2_OFF; }
    }
    const int tn = N >> 5, tk = K >> 5;
    const int tile = blockIdx.x;
    if (tile >= tn * tk) return;
    const int n0 = (tile % tn) * 32, k0 = (tile / tn) * 32;

    __shared__ float t_[32][33];
    const int tx = threadIdx.x, ty = threadIdx.y;    // 32 x 8
    #pragma unroll
    for (int i = 0; i < 32; i += 8)
        t_[ty + i][tx] = src[(long)(k0 + ty + i) * N + n0 + tx];
    __syncthreads();
    __half* Wh = GFh + dstoff;
    #pragma unroll
    for (int i = 0; i < 32; i += 8) {
        float v = t_[tx][ty + i];
        Wh[(long)(n0 + ty + i) * K + k0 + tx] = __float2half(v);
    }
}

// ---------------- fp16 1-pass GEMM: A fp16 single, W fp16 single ----------------
// 128x64 CTA tile, BK32, 256 thr, 8 warps 4m x 2n (32x32 tiles), 3-stage cp.async.
// EPI: 0 store f32 | 1 +bias f32 | 2 +bias,gelu -> fp16 | 3 +bias,gelu,+=C f32 | 4 +=C f32 | 5 store fp16
static constexpr int HG_STAGE = 12288;            // A 8K + B 4K
static constexpr int HG_SMEM  = 3 * HG_STAGE;     // 36864

template<int EPI>
__global__ void __launch_bounds__(256) hgemm_kernel(
    const __half* __restrict__ A,
    const __half* __restrict__ Wh,
    const float* __restrict__ bias, float* __restrict__ C,
    __half* __restrict__ O,
    int M, int N, int K)
{
    extern __shared__ char smc[];
    const uint32_t smb = smem_u32(smc);
    const int tid = threadIdx.x;
    const int lane = tid & 31, warp = tid >> 5;
    const int wm = warp >> 1, wn = warp & 1;
    const int n0 = blockIdx.x * 64, m0 = blockIdx.y * 128;
    const int KT = K >> 5;

    float acc[2][4][4];
    #pragma unroll
    for (int a = 0; a < 2; a++)
        #pragma unroll
        for (int b = 0; b < 4; b++)
            #pragma unroll
            for (int c = 0; c < 4; c++) acc[a][b][c] = 0.f;

    auto issue = [&](int kt, int s) {
        const int k0 = kt << 5;
        const uint32_t st = smb + s * HG_STAGE;
        #pragma unroll
        for (int i = 0; i < 2; i++) {
            int idx = tid + (i << 8);
            int row = idx >> 2, ch = idx & 3;
            uint32_t off = (uint32_t)(row * 64 + ((ch ^ ((row >> 1) & 3)) << 4));
            bool av = (m0 + row) < M;
            long aoff = (long)(m0 + row) * K + k0 + ch * 8;
            cp16(st + off, A + aoff, av);
        }
        {
            int row = tid >> 2, ch = tid & 3;
            uint32_t off = (uint32_t)(row * 64 + ((ch ^ ((row >> 1) & 3)) << 4));
            long boff = (long)(n0 + row) * K + k0 + ch * 8;
            cp16(st + 8192 + off, Wh + boff, true);
        }
    };
    auto ldaddr = [&](uint32_t tb, int r0, int ks) -> uint32_t {
        int row = r0 + (lane & 7) + ((lane & 8) ? 8 : 0);
        int ch  = (ks << 1) + ((lane >> 4) & 1);
        return tb + (uint32_t)(row * 64 + ((ch ^ ((row >> 1) & 3)) << 4));
    };

    issue(0, 0);
    cp_commit();
    if (KT > 1) issue(1, 1);
    cp_commit();

    for (int kt = 0; kt < KT; kt++) {
        cp_wait1();
        __syncthreads();
        int pf = kt + 2;
        if (pf < KT) issue(pf, pf % 3);
        cp_commit();

        const uint32_t st = smb + (kt % 3) * HG_STAGE;
        #pragma unroll
        for (int ks = 0; ks < 2; ks++) {
            uint32_t a4[2][4];
            #pragma unroll
            for (int mt = 0; mt < 2; mt++)
                ldm4(a4[mt], ldaddr(st, wm * 32 + mt * 16, ks));
            #pragma unroll
            for (int g = 0; g < 2; g++) {
                uint32_t bh[4];
                ldm4(bh, ldaddr(st + 8192, wn * 32 + g * 16, ks));
                #pragma unroll
                for (int mt = 0; mt < 2; mt++)
                    #pragma unroll
                    for (int sl = 0; sl < 2; sl++)
                        mma_f16(acc[mt][g * 2 + sl], a4[mt], bh[sl], bh[sl + 2]);
            }
        }
    }

    #pragma unroll
    for (int mt = 0; mt < 2; mt++)
        #pragma unroll
        for (int nt = 0; nt < 4; nt++) {
            int cb = n0 + wn * 32 + nt * 8 + (lane & 3) * 2;
            #pragma unroll
            for (int h = 0; h < 2; h++) {
                int r = m0 + wm * 32 + mt * 16 + (lane >> 2) + h * 8;
                if (r < M) {
                    float v0 = acc[mt][nt][h * 2 + 0];
                    float v1 = acc[mt][nt][h * 2 + 1];
                    if (EPI == 1) { v0 += bias[cb]; v1 += bias[cb + 1]; }
                    if (EPI == 2 || EPI == 3) {
                        v0 = gelu_exact(v0 + bias[cb]);
                        v1 = gelu_exact(v1 + bias[cb + 1]);
                    }
                    if (EPI == 2 || EPI == 5) {
                        *(uint32_t*)(O + (long)r * N + cb) = hpack(v0, v1);
                    } else {
                        float* cp = C + (long)r * N + cb;
                        if (EPI == 3 || EPI == 4) { v0 += cp[0]; v1 += cp[1]; }
                        cp[0] = v0; cp[1] = v1;
                    }
                }
            }
        }
}

// ---------------- tensor-core attention (fp16 single, 1-pass QK + 1-pass PV) ----------------
static constexpr int ATT_Q = 0;                      // 208 rows x 128B (swizzled)
static constexpr int ATT_K = 26624;                  // 224 rows x 128B
static constexpr int ATT_V = 55296;                  // Vt: 64 rows x 512B (token-major)
static constexpr int ATT_SMEM = 88064;

__global__ void __launch_bounds__(256) attn_mma_kernel(const __half* __restrict__ qkv,
                                                       __half* __restrict__ oo) {
    extern __shared__ char sma[];
    const uint32_t smb = smem_u32(sma);
    const int tid = threadIdx.x, lane = tid & 31, warp = tid >> 5;
    const int bb = blockIdx.x / NH, hh = blockIdx.x % NH;

    for (int i = tid; i < ATT_SMEM / 16; i += 256)
        *(uint4*)(sma + i * 16) = make_uint4(0, 0, 0, 0);
    __syncthreads();

    const __half* base = qkv + (long)bb * NTOK * 2304 + hh * 64;
    for (int idx = tid; idx < NTOK * 64; idx += 256) {
        int row = idx >> 6, d = idx & 63;
        const __half* rp = base + (long)row * 2304;
        uint32_t qko = (uint32_t)(row * 128 + (((d >> 3) ^ (row & 7)) << 4) + (d & 7) * 2);
        *(__half*)(sma + ATT_Q + qko) = rp[d];
        *(__half*)(sma + ATT_K + qko) = rp[768 + d];
        uint32_t vo = (uint32_t)(d * 512 + (((row >> 3) ^ (d & 7)) << 4) + (row & 7) * 2);
        *(__half*)(sma + ATT_V + vo) = rp[1536 + d];
    }
    __syncthreads();

    auto qkaddr = [&](uint32_t toff, int r0, int kt) -> uint32_t {
        int row = r0 + (lane & 7) + ((lane & 8) ? 8 : 0);
        int ch  = kt * 2 + (lane >> 4);
        return smb + toff + (uint32_t)(row * 128 + ((ch ^ (row & 7)) << 4));
    };
    auto vaddr = [&](int d0, int kt2) -> uint32_t {
        int row = d0 + (lane & 7) + ((lane & 8) ? 8 : 0);
        int ch  = kt2 * 2 + (lane >> 4);
        return smb + ATT_V + (uint32_t)(row * 512 + ((ch ^ (row & 7)) << 4));
    };

    for (int mt = warp; mt < 13; mt += 8) {
        const int r0 = mt * 16;
        float sacc[28][4];
        #pragma unroll
        for (int n = 0; n < 28; n++)
            #pragma unroll
            for (int c = 0; c < 4; c++) sacc[n][c] = 0.f;

        uint32_t aq[4][4];
        #pragma unroll
        for (int kt = 0; kt < 4; kt++)
            ldm4(aq[kt], qkaddr(ATT_Q, r0, kt));
        #pragma unroll
        for (int g = 0; g < 14; g++) {
            #pragma unroll
            for (int kt = 0; kt < 4; kt++) {
                uint32_t k4[4];
                ldm4(k4, qkaddr(ATT_K, g * 16, kt));
                #pragma unroll
                for (int sl = 0; sl < 2; sl++)
                    mma_f16(sacc[2 * g + sl], aq[kt], k4[sl], k4[sl + 2]);
            }
        }

        const int cb = (lane & 3) * 2;
        float m0 = -1e30f, m1 = -1e30f;
        #pragma unroll
        for (int nt = 0; nt < 28; nt++) {
            int c0 = nt * 8 + cb;
            sacc[nt][0] = (c0     < 197) ? sacc[nt][0] * 0.125f : -1e30f;
            sacc[nt][1] = (c0 + 1 < 197) ? sacc[nt][1] * 0.125f : -1e30f;
            sacc[nt][2] = (c0     < 197) ? sacc[nt][2] * 0.125f : -1e30f;
            sacc[nt][3] = (c0 + 1 < 197) ? sacc[nt][3] * 0.125f : -1e30f;
            m0 = fmaxf(m0, fmaxf(sacc[nt][0], sacc[nt][1]));
            m1 = fmaxf(m1, fmaxf(sacc[nt][2], sacc[nt][3]));
        }
        m0 = fmaxf(m0, __shfl_xor_sync(0xffffffffu, m0, 1));
        m0 = fmaxf(m0, __shfl_xor_sync(0xffffffffu, m0, 2));
        m1 = fmaxf(m1, __shfl_xor_sync(0xffffffffu, m1, 1));
        m1 = fmaxf(m1, __shfl_xor_sync(0xffffffffu, m1, 2));
        float s0 = 0.f, s1 = 0.f;
        #pragma unroll
        for (int nt = 0; nt < 28; nt++) {
            sacc[nt][0] = __expf(sacc[nt][0] - m0);
            sacc[nt][1] = __expf(sacc[nt][1] - m0);
            sacc[nt][2] = __expf(sacc[nt][2] - m1);
            sacc[nt][3] = __expf(sacc[nt][3] - m1);
            s0 += sacc[nt][0] + sacc[nt][1];
            s1 += sacc[nt][2] + sacc[nt][3];
        }
        s0 += __shfl_xor_sync(0xffffffffu, s0, 1);
        s0 += __shfl_xor_sync(0xffffffffu, s0, 2);
        s1 += __shfl_xor_sync(0xffffffffu, s1, 1);
        s1 += __shfl_xor_sync(0xffffffffu, s1, 2);
        float i0 = 1.f / s0, i1 = 1.f / s1;
        #pragma unroll
        for (int nt = 0; nt < 28; nt++) {
            sacc[nt][0] *= i0; sacc[nt][1] *= i0;
            sacc[nt][2] *= i1; sacc[nt][3] *= i1;
        }

        float oacc[8][4];
        #pragma unroll
        for (int n = 0; n < 8; n++)
            #pragma unroll
            for (int c = 0; c < 4; c++) oacc[n][c] = 0.f;
        #pragma unroll
        for (int kt2 = 0; kt2 < 14; kt2++) {
            uint32_t pa[4];
            pa[0] = hpack(sacc[2*kt2][0],   sacc[2*kt2][1]);
            pa[1] = hpack(sacc[2*kt2][2],   sacc[2*kt2][3]);
            pa[2] = hpack(sacc[2*kt2+1][0], sacc[2*kt2+1][1]);
            pa[3] = hpack(sacc[2*kt2+1][2], sacc[2*kt2+1][3]);
            #pragma unroll
            for (int g = 0; g < 4; g++) {
                uint32_t v4[4];
                ldm4(v4, vaddr(g * 16, kt2));
                #pragma unroll
                for (int sl = 0; sl < 2; sl++)
                    mma_f16(oacc[2 * g + sl], pa, v4[sl], v4[sl + 2]);
            }
        }

        const int row0 = r0 + (lane >> 2), row1 = row0 + 8;
        #pragma unroll
        for (int nt = 0; nt < 8; nt++) {
            int d0 = nt * 8 + cb;
            if (row0 < NTOK) {
                long o = ((long)(bb * NTOK + row0)) * H_ + hh * 64 + d0;
                *(uint32_t*)(oo + o) = hpack(oacc[nt][0], oacc[nt][1]);
            }
            if (row1 < NTOK) {
                long o = ((long)(bb * NTOK + row1)) * H_ + hh * 64 + d0;
                *(uint32_t*)(oo + o) = hpack(oacc[nt][2], oacc[nt][3]);
            }
        }
    }
}

// ---------------- LayerNorm (768) -> fp16 single ----------------
__global__ void ln_half_kernel(const float* __restrict__ in, __half* __restrict__ y,
                               const float* __restrict__ g, const float* __restrict__ b) {
    const int row = blockIdx.x;
    const int tid = threadIdx.x;
    const float* x = in + (long)row * H_;
    float v0 = x[tid], v1 = x[tid + 256], v2 = x[tid + 512];
    __shared__ float red[256];
    __shared__ float s_mean, s_rstd;
    red[tid] = v0 + v1 + v2;
    __syncthreads();
    for (int o = 128; o > 0; o >>= 1) { if (tid < o) red[tid] += red[tid + o]; __syncthreads(); }
    if (tid == 0) s_mean = red[0] * (1.f / H_);
    __syncthreads();
    float m = s_mean;
    float d0 = v0 - m, d1 = v1 - m, d2 = v2 - m;
    red[tid] = d0 * d0 + d1 * d1 + d2 * d2;
    __syncthreads();
    for (int o = 128; o > 0; o >>= 1) { if (tid < o) red[tid] += red[tid + o]; __syncthreads(); }
    if (tid == 0) s_rstd = rsqrtf(red[0] * (1.f / H_) + 1e-5f);
    __syncthreads();
    float rs = s_rstd;
    long base = (long)row * H_;
    y[base + tid]       = __float2half(d0 * rs * g[tid]       + b[tid]);
    y[base + tid + 256] = __float2half(d1 * rs * g[tid + 256] + b[tid + 256]);
    y[base + tid + 512] = __float2half(d2 * rs * g[tid + 512] + b[tid + 512]);
}

// ---------------- patchify + LN(pn1) -> fp16 single ----------------
__global__ void patchify_ln_kernel(const float* __restrict__ x,
                                   const float* __restrict__ g, const float* __restrict__ b,
                                   __half* __restrict__ y) {
    const int pidx = blockIdx.x;
    const int bimg = pidx / NP;
    const int pp   = pidx % NP;
    const int hg = pp / GRD, wg = pp % GRD;
    const int tid = threadIdx.x;
    float v[3];
    #pragma unroll
    for (int r = 0; r < 3; r++) {
        int f = tid + r * 256;
        int p1 = f / 48, rem = f % 48, p2 = rem / 3, c = rem % 3;
        v[r] = x[(((long)bimg * CCH + c) * IMG + (hg * P_ + p1)) * IMG + (wg * P_ + p2)];
    }
    __shared__ float red[256];
    __shared__ float s_mean, s_rstd;
    red[tid] = v[0] + v[1] + v[2];
    __syncthreads();
    for (int o = 128; o > 0; o >>= 1) { if (tid < o) red[tid] += red[tid + o]; __syncthreads(); }
    if (tid == 0) s_mean = red[0] * (1.f / H_);
    __syncthreads();
    float m = s_mean;
    float d0 = v[0] - m, d1 = v[1] - m, d2 = v[2] - m;
    red[tid] = d0 * d0 + d1 * d1 + d2 * d2;
    __syncthreads();
    for (int o = 128; o > 0; o >>= 1) { if (tid < o) red[tid] += red[tid + o]; __syncthreads(); }
    if (tid == 0) s_rstd = rsqrtf(red[0] * (1.f / H_) + 1e-5f);
    __syncthreads();
    float rs = s_rstd;
    long base = (long)pidx * H_;
    y[base + tid]       = __float2half(d0 * rs * g[tid]       + b[tid]);
    y[base + tid + 256] = __float2half(d1 * rs * g[tid + 256] + b[tid + 256]);
    y[base + tid + 512] = __float2half(d2 * rs * g[tid + 512] + b[tid + 512]);
}

// ---------------- LN(pn2) + cls + pos -> h (f32) ----------------
__global__ void assemble_kernel(const float* __restrict__ pemb,
                                const float* __restrict__ g, const float* __restrict__ b,
                                const float* __restrict__ cls, const float* __restrict__ pos,
                                float* __restrict__ h) {
    const int row = blockIdx.x;
    const int bb = row / NTOK, t = row % NTOK;
    const int tid = threadIdx.x;
    float* o_ = h + (long)row * H_;
    if (t == 0) {
        o_[tid]       = cls[tid]       + pos[tid];
        o_[tid + 256] = cls[tid + 256] + pos[tid + 256];
        o_[tid + 512] = cls[tid + 512] + pos[tid + 512];
        return;
    }
    const float* x = pemb + (long)(bb * NP + t - 1) * H_;
    float v0 = x[tid], v1 = x[tid + 256], v2 = x[tid + 512];
    __shared__ float red[256];
    __shared__ float s_mean, s_rstd;
    red[tid] = v0 + v1 + v2;
    __syncthreads();
    for (int o = 128; o > 0; o >>= 1) { if (tid < o) red[tid] += red[tid + o]; __syncthreads(); }
    if (tid == 0) s_mean = red[0] * (1.f / H_);
    __syncthreads();
    float m = s_mean;
    float d0 = v0 - m, d1 = v1 - m, d2 = v2 - m;
    red[tid] = d0 * d0 + d1 * d1 + d2 * d2;
    __syncthreads();
    for (int o = 128; o > 0; o >>= 1) { if (tid < o) red[tid] += red[tid + o]; __syncthreads(); }
    if (tid == 0) s_rstd = rsqrtf(red[0] * (1.f / H_) + 1e-5f);
    __syncthreads();
    float rs = s_rstd;
    const float* pp = pos + (long)t * H_;
    o_[tid]       = d0 * rs * g[tid]       + b[tid]       + pp[tid];
    o_[tid + 256] = d1 * rs * g[tid + 256] + b[tid + 256] + pp[tid + 256];
    o_[tid + 512] = d2 * rs * g[tid + 512] + b[tid + 512] + pp[tid + 512];
}

// ---------------- mean pool ----------------
__global__ void meanpool_kernel(const float* __restrict__ h, float* __restrict__ out) {
    const int bb = blockIdx.x;
    const int j = threadIdx.x;
    float s = 0.f;
    for (int i = 0; i < NTOK; i++) s += h[((long)bb * NTOK + i) * H_ + j];
    out[bb * H_ + j] = s * (1.f / NTOK);
}

// ---------------- host orchestration ----------------
static inline dim3 ggrid(int M, int N) { return dim3(N / 64, (M + 127) / 128); }

extern "C" void kernel_launch(void* const* d_in, const int* in_sizes, int n_in,
                              void* d_out, int out_size) {
    const float* x      = (const float*)d_in[0];
    const float* pn1_g  = (const float*)d_in[1];
    const float* pn1_b  = (const float*)d_in[2];
    const float* pW     = (const float*)d_in[3];
    const float* pb     = (const float*)d_in[4];
    const float* pn2_g  = (const float*)d_in[5];
    const float* pn2_b  = (const float*)d_in[6];
    const float* cls    = (const float*)d_in[7];
    const float* pos    = (const float*)d_in[8];
    const float* ln1_g  = (const float*)d_in[9];
    const float* ln1_b  = (const float*)d_in[10];
    const float* qkv_W  = (const float*)d_in[11];
    const float* out_W  = (const float*)d_in[12];
    const float* ln2_g  = (const float*)d_in[13];
    const float* ln2_b  = (const float*)d_in[14];
    const float* fc1_W  = (const float*)d_in[15];
    const float* fc1_b  = (const float*)d_in[16];
    const float* fc2_W  = (const float*)d_in[17];
    const float* fc2_b  = (const float*)d_in[18];
    float* out = (float*)d_out;

    float *p_h, *p_tmp;
    __half *p_qkv, *p_hq, *p_hy, *p_ha, *p_hm, *p_fh;
    cudaGetSymbolAddress((void**)&p_h,   g_h);
    cudaGetSymbolAddress((void**)&p_tmp, g_tmp);
    cudaGetSymbolAddress((void**)&p_qkv, g_qkv);
    cudaGetSymbolAddress((void**)&p_hq,  g_hq);
    cudaGetSymbolAddress((void**)&p_hy,  g_hy);
    cudaGetSymbolAddress((void**)&p_ha,  g_ha);
    cudaGetSymbolAddress((void**)&p_hm,  g_hm);
    cudaGetSymbolAddress((void**)&p_fh,  g_fh);

    cudaFuncSetAttribute(attn_mma_kernel, cudaFuncAttributeMaxDynamicSharedMemorySize, ATT_SMEM);
    cudaFuncSetAttribute(hgemm_kernel<1>, cudaFuncAttributeMaxDynamicSharedMemorySize, HG_SMEM);
    cudaFuncSetAttribute(hgemm_kernel<2>, cudaFuncAttributeMaxDynamicSharedMemorySize, HG_SMEM);
    cudaFuncSetAttribute(hgemm_kernel<3>, cudaFuncAttributeMaxDynamicSharedMemorySize, HG_SMEM);
    cudaFuncSetAttribute(hgemm_kernel<4>, cudaFuncAttributeMaxDynamicSharedMemorySize, HG_SMEM);
    cudaFuncSetAttribute(hgemm_kernel<5>, cudaFuncAttributeMaxDynamicSharedMemorySize, HG_SMEM);

    dim3 tb(32, 8);
    // idx 0: patchify + LN(pn1) -> fp16
    patchify_ln_kernel<<<PROWS, 256>>>(x, pn1_g, pn1_b, p_hq);
    // idx 1: mega weight split (all weights -> fp16 single)
    wsplit_mega_kernel<<<dim3(2304, 49), tb>>>(pW, qkv_W, out_W, fc1_W, fc2_W, p_fh);
    // idx 2: patch embed GEMM + bias -> g_tmp (f32)
    hgemm_kernel<1><<<ggrid(PROWS, H_), 256, HG_SMEM>>>(p_hq, p_fh + W_PATCH_OFF,
                                                        pb, p_tmp, nullptr, PROWS, H_, H_);
    // idx 3: LN(pn2) + cls + pos -> h
    assemble_kernel<<<ROWS, 256>>>(p_tmp, pn2_g, pn2_b, cls, pos, p_h);

    // transformer layers
    for (int l = 0; l < L_; l++) {
        long wb = W_LAYER_BASE + (long)l * W_LAYER_SZ;
        const float* l1g = ln1_g + l * H_;
        const float* l1b = ln1_b + l * H_;
        const float* l2g = ln2_g + l * H_;
        const float* l2b = ln2_b + l * H_;
        const float* f1b = fc1_b + (long)l * MLP_;
        const float* f2b = fc2_b + (long)l * H_;

        ln_half_kernel<<<ROWS, 256>>>(p_h, p_hq, l1g, l1b);
        hgemm_kernel<5><<<ggrid(ROWS, 3 * H_), 256, HG_SMEM>>>(
            p_hq, p_fh + wb + W_QKV_OFF,
            nullptr, nullptr, p_qkv, ROWS, 3 * H_, H_);
        attn_mma_kernel<<<B_ * NH, 256, ATT_SMEM>>>(p_qkv, p_ha);
        hgemm_kernel<4><<<ggrid(ROWS, H_), 256, HG_SMEM>>>(
            p_ha, p_fh + wb + W_OUT_OFF,
            nullptr, p_h, nullptr, ROWS, H_, H_);
        ln_half_kernel<<<ROWS, 256>>>(p_h, p_hy, l2g, l2b);
        hgemm_kernel<2><<<ggrid(ROWS, MLP_), 256, HG_SMEM>>>(
            p_hy, p_fh + wb + W_FC1_OFF,
            f1b, nullptr, p_hm, ROWS, MLP_, H_);
        hgemm_kernel<3><<<ggrid(ROWS, H_), 256, HG_SMEM>>>(
            p_hm, p_fh + wb + W_FC2_OFF,
            f2b, p_h, nullptr, ROWS, H_, MLP_);
    }

    // mean pool
    meanpool_kernel<<<B_, H_>>>(p_h, out);
}

// round 17
// speedup vs baseline: 2.5181x; 1.0539x over previous
#include <cuda_runtime.h>
#include <cuda_bf16.h>
#include <cuda_fp16.h>
#include <math.h>
#include <cstdint>

// ---------------- problem constants ----------------
static constexpr int B_   = 32;
static constexpr int CCH  = 3;
static constexpr int IMG  = 224;
static constexpr int P_   = 16;
static constexpr int GRD  = IMG / P_;        // 14
static constexpr int NP   = GRD * GRD;       // 196
static constexpr int NTOK = NP + 1;          // 197
static constexpr int H_   = 768;
static constexpr int NH   = 12;
static constexpr int HD   = 64;
static constexpr int MLP_ = 3072;
static constexpr int L_   = 12;
static constexpr int ROWS = B_ * NTOK;       // 6304
static constexpr int PROWS = B_ * NP;        // 6272

// fp16 weight scratch (ALL weights), transposed [N,K], single fp16
static constexpr long W_PATCH_OFF = 0;                        // 768x768
static constexpr long W_LAYER_BASE = 768L * 768;
static constexpr long W_QKV_OFF = 0;                          // 2304x768
static constexpr long W_OUT_OFF = 768L * 2304;
static constexpr long W_FC1_OFF = W_OUT_OFF + 768L * 768;
static constexpr long W_FC2_OFF = W_FC1_OFF + 768L * 3072;
static constexpr long W_LAYER_SZ = W_FC2_OFF + 3072L * 768;
static constexpr long W_TOTAL = W_LAYER_BASE + 12L * W_LAYER_SZ;

// ---------------- device scratch ----------------
__device__ float g_h   [ROWS * H_];
__device__ float g_tmp [PROWS * H_];
__device__ __align__(256) __half g_qkv [ROWS * 3 * H_];  // QKV (fp16 single)
__device__ __align__(256) __half g_hq [ROWS * H_];       // patchify / LN1 out
__device__ __align__(256) __half g_hy [ROWS * H_];       // LN2 out
__device__ __align__(256) __half g_ha [ROWS * H_];       // attention out
__device__ __align__(256) __half g_hm [ROWS * MLP_];     // FC1+gelu out
__device__ __align__(256) __half g_fh [W_TOTAL];

// ---------------- helpers ----------------
__device__ __forceinline__ uint32_t smem_u32(const void* p) {
    uint32_t a;
    asm("{ .reg .u64 t; cvta.to.shared.u64 t, %1; cvt.u32.u64 %0, t; }" : "=r"(a) : "l"(p));
    return a;
}
__device__ __forceinline__ void cp16(uint32_t dst, const void* src, bool valid) {
    int sz = valid ? 16 : 0;
    asm volatile("cp.async.cg.shared.global [%0], [%1], 16, %2;"
                 :: "r"(dst), "l"(src), "r"(sz) : "memory");
}
__device__ __forceinline__ void cp_commit() {
    asm volatile("cp.async.commit_group;" ::: "memory");
}
__device__ __forceinline__ void cp_wait1() {
    asm volatile("cp.async.wait_group 1;" ::: "memory");
}
__device__ __forceinline__ void ldm4(uint32_t* r, uint32_t addr) {
    asm volatile("ldmatrix.sync.aligned.m8n8.x4.shared.b16 {%0,%1,%2,%3}, [%4];"
                 : "=r"(r[0]), "=r"(r[1]), "=r"(r[2]), "=r"(r[3]) : "r"(addr));
}
__device__ __forceinline__ void mma_f16(float* d, const uint32_t* a, uint32_t b0, uint32_t b1) {
    asm volatile(
        "mma.sync.aligned.m16n8k16.row.col.f32.f16.f16.f32 "
        "{%0,%1,%2,%3}, {%4,%5,%6,%7}, {%8,%9}, {%0,%1,%2,%3};"
        : "+f"(d[0]), "+f"(d[1]), "+f"(d[2]), "+f"(d[3])
        : "r"(a[0]), "r"(a[1]), "r"(a[2]), "r"(a[3]), "r"(b0), "r"(b1));
}
__device__ __forceinline__ float gelu_exact(float x) {
    return 0.5f * x * (1.0f + erff(x * 0.70710678118654752f));
}
__device__ __forceinline__ uint32_t hpack(float f0, float f1) {
    __half2 h = __floats2half2_rn(f0, f1);
    uint32_t u;
    memcpy(&u, &h, 4);
    return u;
}

// ---------------- mega weight split (ALL weights -> fp16 single, [N,K]) ----------------
__global__ void wsplit_mega_kernel(const float* __restrict__ pW,
                                   const float* __restrict__ qkvW,
                                   const float* __restrict__ outW,
                                   const float* __restrict__ fc1W,
                                   const float* __restrict__ fc2W,
                                   __half* __restrict__ GFh) {
    const int seg = blockIdx.y;       // 0..48
    int K, N;
    const float* src;
    long dstoff;
    if (seg == 0) {
        K = 768; N = 768; src = pW; dstoff = W_PATCH_OFF;
    } else {
        int t = (seg - 1) & 3, l = (seg - 1) >> 2;
        long wb = W_LAYER_BASE + (long)l * W_LAYER_SZ;
        if (t == 0)      { K = 768;  N = 2304; src = qkvW + (long)l * 768 * 2304; dstoff = wb + W_QKV_OFF; }
        else if (t == 1) { K = 768;  N = 768;  src = outW + (long)l * 768 * 768;  dstoff = wb + W_OUT_OFF; }
        else if (t == 2) { K = 768;  N = 3072; src = fc1W + (long)l * 768 * 3072; dstoff = wb + W_FC1_OFF; }
        else             { K = 3072; N = 768;  src = fc2W + (long)l * 3072 * 768; dstoff = wb + W_FC2_OFF; }
    }
    const int tn = N >> 5, tk = K >> 5;
    const int tile = blockIdx.x;
    if (tile >= tn * tk) return;
    const int n0 = (tile % tn) * 32, k0 = (tile / tn) * 32;

    __shared__ float t_[32][33];
    const int tx = threadIdx.x, ty = threadIdx.y;    // 32 x 8
    #pragma unroll
    for (int i = 0; i < 32; i += 8)
        t_[ty + i][tx] = src[(long)(k0 + ty + i) * N + n0 + tx];
    __syncthreads();
    __half* Wh = GFh + dstoff;
    #pragma unroll
    for (int i = 0; i < 32; i += 8) {
        float v = t_[tx][ty + i];
        Wh[(long)(n0 + ty + i) * K + k0 + tx] = __float2half(v);
    }
}

// ---------------- fp16 1-pass GEMM: A fp16 single, W fp16 single ----------------
// 128x64 CTA tile, BK32, 256 thr, 8 warps 4m x 2n (32x32 tiles), 3-stage cp.async.
// EPI: 0 store f32 | 1 +bias f32 | 2 +bias,gelu -> fp16 | 3 +bias,gelu,+=C f32 | 4 +=C f32 | 5 store fp16
static constexpr int HG_STAGE = 12288;            // A 8K + B 4K
static constexpr int HG_SMEM  = 3 * HG_STAGE;     // 36864

template<int EPI>
__global__ void __launch_bounds__(256) hgemm_kernel(
    const __half* __restrict__ A,
    const __half* __restrict__ Wh,
    const float* __restrict__ bias, float* __restrict__ C,
    __half* __restrict__ O,
    int M, int N, int K)
{
    extern __shared__ char smc[];
    const uint32_t smb = smem_u32(smc);
    const int tid = threadIdx.x;
    const int lane = tid & 31, warp = tid >> 5;
    const int wm = warp >> 1, wn = warp & 1;
    const int n0 = blockIdx.x * 64, m0 = blockIdx.y * 128;
    const int KT = K >> 5;

    float acc[2][4][4];
    #pragma unroll
    for (int a = 0; a < 2; a++)
        #pragma unroll
        for (int b = 0; b < 4; b++)
            #pragma unroll
            for (int c = 0; c < 4; c++) acc[a][b][c] = 0.f;

    auto issue = [&](int kt, int s) {
        const int k0 = kt << 5;
        const uint32_t st = smb + s * HG_STAGE;
        #pragma unroll
        for (int i = 0; i < 2; i++) {
            int idx = tid + (i << 8);
            int row = idx >> 2, ch = idx & 3;
            uint32_t off = (uint32_t)(row * 64 + ((ch ^ ((row >> 1) & 3)) << 4));
            bool av = (m0 + row) < M;
            long aoff = (long)(m0 + row) * K + k0 + ch * 8;
            cp16(st + off, A + aoff, av);
        }
        {
            int row = tid >> 2, ch = tid & 3;
            uint32_t off = (uint32_t)(row * 64 + ((ch ^ ((row >> 1) & 3)) << 4));
            long boff = (long)(n0 + row) * K + k0 + ch * 8;
            cp16(st + 8192 + off, Wh + boff, true);
        }
    };
    auto ldaddr = [&](uint32_t tb, int r0, int ks) -> uint32_t {
        int row = r0 + (lane & 7) + ((lane & 8) ? 8 : 0);
        int ch  = (ks << 1) + ((lane >> 4) & 1);
        return tb + (uint32_t)(row * 64 + ((ch ^ ((row >> 1) & 3)) << 4));
    };

    issue(0, 0);
    cp_commit();
    if (KT > 1) issue(1, 1);
    cp_commit();

    for (int kt = 0; kt < KT; kt++) {
        cp_wait1();
        __syncthreads();
        int pf = kt + 2;
        if (pf < KT) issue(pf, pf % 3);
        cp_commit();

        const uint32_t st = smb + (kt % 3) * HG_STAGE;
        #pragma unroll
        for (int ks = 0; ks < 2; ks++) {
            uint32_t a4[2][4];
            #pragma unroll
            for (int mt = 0; mt < 2; mt++)
                ldm4(a4[mt], ldaddr(st, wm * 32 + mt * 16, ks));
            #pragma unroll
            for (int g = 0; g < 2; g++) {
                uint32_t bh[4];
                ldm4(bh, ldaddr(st + 8192, wn * 32 + g * 16, ks));
                #pragma unroll
                for (int mt = 0; mt < 2; mt++)
                    #pragma unroll
                    for (int sl = 0; sl < 2; sl++)
                        mma_f16(acc[mt][g * 2 + sl], a4[mt], bh[sl], bh[sl + 2]);
            }
        }
    }

    #pragma unroll
    for (int mt = 0; mt < 2; mt++)
        #pragma unroll
        for (int nt = 0; nt < 4; nt++) {
            int cb = n0 + wn * 32 + nt * 8 + (lane & 3) * 2;
            #pragma unroll
            for (int h = 0; h < 2; h++) {
                int r = m0 + wm * 32 + mt * 16 + (lane >> 2) + h * 8;
                if (r < M) {
                    float v0 = acc[mt][nt][h * 2 + 0];
                    float v1 = acc[mt][nt][h * 2 + 1];
                    if (EPI == 1) { v0 += bias[cb]; v1 += bias[cb + 1]; }
                    if (EPI == 2 || EPI == 3) {
                        v0 = gelu_exact(v0 + bias[cb]);
                        v1 = gelu_exact(v1 + bias[cb + 1]);
                    }
                    if (EPI == 2 || EPI == 5) {
                        *(uint32_t*)(O + (long)r * N + cb) = hpack(v0, v1);
                    } else {
                        float* cp = C + (long)r * N + cb;
                        if (EPI == 3 || EPI == 4) { v0 += cp[0]; v1 += cp[1]; }
                        cp[0] = v0; cp[1] = v1;
                    }
                }
            }
        }
}

// ---------------- tensor-core attention (fp16 single, 1-pass QK + 1-pass PV) ----------------
// Only the Vt token-pad must be zeroed: K-pad scores are masked (value discarded by select),
// Q-pad rows' outputs are discarded by the row<NTOK store guard.
static constexpr int ATT_Q = 0;                      // 208 rows x 128B (swizzled)
static constexpr int ATT_K = 26624;                  // 224 rows x 128B
static constexpr int ATT_V = 55296;                  // Vt: 64 rows x 512B (token-major)
static constexpr int ATT_SMEM = 88064;

__global__ void __launch_bounds__(256) attn_mma_kernel(const __half* __restrict__ qkv,
                                                       __half* __restrict__ oo) {
    extern __shared__ char sma[];
    const uint32_t smb = smem_u32(sma);
    const int tid = threadIdx.x, lane = tid & 31, warp = tid >> 5;
    const int bb = blockIdx.x / NH, hh = blockIdx.x % NH;

    // zero ONLY Vt pad tokens [197,256) (P=0 x garbage-Inf would be NaN otherwise)
    for (int idx = tid; idx < 64 * 59; idx += 256) {
        int d = idx / 59, tok = 197 + idx % 59;
        uint32_t vo = (uint32_t)(d * 512 + (((tok >> 3) ^ (d & 7)) << 4) + (tok & 7) * 2);
        *(__half*)(sma + ATT_V + vo) = __float2half(0.f);
    }

    // stage Q,K (row-major d) and Vt (token-major), fp16 single
    const __half* base = qkv + (long)bb * NTOK * 2304 + hh * 64;
    for (int idx = tid; idx < NTOK * 64; idx += 256) {
        int row = idx >> 6, d = idx & 63;
        const __half* rp = base + (long)row * 2304;
        uint32_t qko = (uint32_t)(row * 128 + (((d >> 3) ^ (row & 7)) << 4) + (d & 7) * 2);
        *(__half*)(sma + ATT_Q + qko) = rp[d];
        *(__half*)(sma + ATT_K + qko) = rp[768 + d];
        uint32_t vo = (uint32_t)(d * 512 + (((row >> 3) ^ (d & 7)) << 4) + (row & 7) * 2);
        *(__half*)(sma + ATT_V + vo) = rp[1536 + d];
    }
    __syncthreads();

    auto qkaddr = [&](uint32_t toff, int r0, int kt) -> uint32_t {
        int row = r0 + (lane & 7) + ((lane & 8) ? 8 : 0);
        int ch  = kt * 2 + (lane >> 4);
        return smb + toff + (uint32_t)(row * 128 + ((ch ^ (row & 7)) << 4));
    };
    auto vaddr = [&](int d0, int kt2) -> uint32_t {
        int row = d0 + (lane & 7) + ((lane & 8) ? 8 : 0);
        int ch  = kt2 * 2 + (lane >> 4);
        return smb + ATT_V + (uint32_t)(row * 512 + ((ch ^ (row & 7)) << 4));
    };

    for (int mt = warp; mt < 13; mt += 8) {
        const int r0 = mt * 16;
        float sacc[28][4];
        #pragma unroll
        for (int n = 0; n < 28; n++)
            #pragma unroll
            for (int c = 0; c < 4; c++) sacc[n][c] = 0.f;

        uint32_t aq[4][4];
        #pragma unroll
        for (int kt = 0; kt < 4; kt++)
            ldm4(aq[kt], qkaddr(ATT_Q, r0, kt));
        #pragma unroll
        for (int g = 0; g < 14; g++) {
            #pragma unroll
            for (int kt = 0; kt < 4; kt++) {
                uint32_t k4[4];
                ldm4(k4, qkaddr(ATT_K, g * 16, kt));
                #pragma unroll
                for (int sl = 0; sl < 2; sl++)
                    mma_f16(sacc[2 * g + sl], aq[kt], k4[sl], k4[sl + 2]);
            }
        }

        const int cb = (lane & 3) * 2;
        float m0 = -1e30f, m1 = -1e30f;
        #pragma unroll
        for (int nt = 0; nt < 28; nt++) {
            int c0 = nt * 8 + cb;
            sacc[nt][0] = (c0     < 197) ? sacc[nt][0] * 0.125f : -1e30f;
            sacc[nt][1] = (c0 + 1 < 197) ? sacc[nt][1] * 0.125f : -1e30f;
            sacc[nt][2] = (c0     < 197) ? sacc[nt][2] * 0.125f : -1e30f;
            sacc[nt][3] = (c0 + 1 < 197) ? sacc[nt][3] * 0.125f : -1e30f;
            m0 = fmaxf(m0, fmaxf(sacc[nt][0], sacc[nt][1]));
            m1 = fmaxf(m1, fmaxf(sacc[nt][2], sacc[nt][3]));
        }
        m0 = fmaxf(m0, __shfl_xor_sync(0xffffffffu, m0, 1));
        m0 = fmaxf(m0, __shfl_xor_sync(0xffffffffu, m0, 2));
        m1 = fmaxf(m1, __shfl_xor_sync(0xffffffffu, m1, 1));
        m1 = fmaxf(m1, __shfl_xor_sync(0xffffffffu, m1, 2));
        float s0 = 0.f, s1 = 0.f;
        #pragma unroll
        for (int nt = 0; nt < 28; nt++) {
            sacc[nt][0] = __expf(sacc[nt][0] - m0);
            sacc[nt][1] = __expf(sacc[nt][1] - m0);
            sacc[nt][2] = __expf(sacc[nt][2] - m1);
            sacc[nt][3] = __expf(sacc[nt][3] - m1);
            s0 += sacc[nt][0] + sacc[nt][1];
            s1 += sacc[nt][2] + sacc[nt][3];
        }
        s0 += __shfl_xor_sync(0xffffffffu, s0, 1);
        s0 += __shfl_xor_sync(0xffffffffu, s0, 2);
        s1 += __shfl_xor_sync(0xffffffffu, s1, 1);
        s1 += __shfl_xor_sync(0xffffffffu, s1, 2);
        float i0 = 1.f / s0, i1 = 1.f / s1;
        #pragma unroll
        for (int nt = 0; nt < 28; nt++) {
            sacc[nt][0] *= i0; sacc[nt][1] *= i0;
            sacc[nt][2] *= i1; sacc[nt][3] *= i1;
        }

        float oacc[8][4];
        #pragma unroll
        for (int n = 0; n < 8; n++)
            #pragma unroll
            for (int c = 0; c < 4; c++) oacc[n][c] = 0.f;
        #pragma unroll
        for (int kt2 = 0; kt2 < 14; kt2++) {
            uint32_t pa[4];
            pa[0] = hpack(sacc[2*kt2][0],   sacc[2*kt2][1]);
            pa[1] = hpack(sacc[2*kt2][2],   sacc[2*kt2][3]);
            pa[2] = hpack(sacc[2*kt2+1][0], sacc[2*kt2+1][1]);
            pa[3] = hpack(sacc[2*kt2+1][2], sacc[2*kt2+1][3]);
            #pragma unroll
            for (int g = 0; g < 4; g++) {
                uint32_t v4[4];
                ldm4(v4, vaddr(g * 16, kt2));
                #pragma unroll
                for (int sl = 0; sl < 2; sl++)
                    mma_f16(oacc[2 * g + sl], pa, v4[sl], v4[sl + 2]);
            }
        }

        const int row0 = r0 + (lane >> 2), row1 = row0 + 8;
        #pragma unroll
        for (int nt = 0; nt < 8; nt++) {
            int d0 = nt * 8 + cb;
            if (row0 < NTOK) {
                long o = ((long)(bb * NTOK + row0)) * H_ + hh * 64 + d0;
                *(uint32_t*)(oo + o) = hpack(oacc[nt][0], oacc[nt][1]);
            }
            if (row1 < NTOK) {
                long o = ((long)(bb * NTOK + row1)) * H_ + hh * 64 + d0;
                *(uint32_t*)(oo + o) = hpack(oacc[nt][2], oacc[nt][3]);
            }
        }
    }
}

// ---------------- warp-per-row LayerNorm (768) -> fp16 single ----------------
__global__ void __launch_bounds__(256) ln_half_kernel(const float* __restrict__ in,
                                                      __half* __restrict__ y,
                                                      const float* __restrict__ g,
                                                      const float* __restrict__ b) {
    const int row = blockIdx.x * 8 + (threadIdx.x >> 5);   // 8 rows per CTA
    const int lane = threadIdx.x & 31;
    const float* x = in + (long)row * H_;
    float v[24];
    float s = 0.f;
    #pragma unroll
    for (int i = 0; i < 6; i++) {
        float4 t = *(const float4*)(x + (i * 32 + lane) * 4);
        v[i*4+0] = t.x; v[i*4+1] = t.y; v[i*4+2] = t.z; v[i*4+3] = t.w;
        s += t.x + t.y + t.z + t.w;
    }
    #pragma unroll
    for (int o = 16; o > 0; o >>= 1) s += __shfl_xor_sync(0xffffffffu, s, o);
    float m = s * (1.f / H_);
    float q = 0.f;
    #pragma unroll
    for (int j = 0; j < 24; j++) { v[j] -= m; q += v[j] * v[j]; }
    #pragma unroll
    for (int o = 16; o > 0; o >>= 1) q += __shfl_xor_sync(0xffffffffu, q, o);
    float rs = rsqrtf(q * (1.f / H_) + 1e-5f);
    __half* yr = y + (long)row * H_;
    #pragma unroll
    for (int i = 0; i < 6; i++) {
        int c = (i * 32 + lane) * 4;
        float4 gg = *(const float4*)(g + c);
        float4 bb = *(const float4*)(b + c);
        uint2 u;
        u.x = hpack(v[i*4+0] * rs * gg.x + bb.x, v[i*4+1] * rs * gg.y + bb.y);
        u.y = hpack(v[i*4+2] * rs * gg.z + bb.z, v[i*4+3] * rs * gg.w + bb.w);
        *(uint2*)(yr + c) = u;
    }
}

// ---------------- patchify + LN(pn1) -> fp16 single ----------------
__global__ void patchify_ln_kernel(const float* __restrict__ x,
                                   const float* __restrict__ g, const float* __restrict__ b,
                                   __half* __restrict__ y) {
    const int pidx = blockIdx.x;
    const int bimg = pidx / NP;
    const int pp   = pidx % NP;
    const int hg = pp / GRD, wg = pp % GRD;
    const int tid = threadIdx.x;
    float v[3];
    #pragma unroll
    for (int r = 0; r < 3; r++) {
        int f = tid + r * 256;
        int p1 = f / 48, rem = f % 48, p2 = rem / 3, c = rem % 3;
        v[r] = x[(((long)bimg * CCH + c) * IMG + (hg * P_ + p1)) * IMG + (wg * P_ + p2)];
    }
    __shared__ float red[256];
    __shared__ float s_mean, s_rstd;
    red[tid] = v[0] + v[1] + v[2];
    __syncthreads();
    for (int o = 128; o > 0; o >>= 1) { if (tid < o) red[tid] += red[tid + o]; __syncthreads(); }
    if (tid == 0) s_mean = red[0] * (1.f / H_);
    __syncthreads();
    float m = s_mean;
    float d0 = v[0] - m, d1 = v[1] - m, d2 = v[2] - m;
    red[tid] = d0 * d0 + d1 * d1 + d2 * d2;
    __syncthreads();
    for (int o = 128; o > 0; o >>= 1) { if (tid < o) red[tid] += red[tid + o]; __syncthreads(); }
    if (tid == 0) s_rstd = rsqrtf(red[0] * (1.f / H_) + 1e-5f);
    __syncthreads();
    float rs = s_rstd;
    long base = (long)pidx * H_;
    y[base + tid]       = __float2half(d0 * rs * g[tid]       + b[tid]);
    y[base + tid + 256] = __float2half(d1 * rs * g[tid + 256] + b[tid + 256]);
    y[base + tid + 512] = __float2half(d2 * rs * g[tid + 512] + b[tid + 512]);
}

// ---------------- LN(pn2) + cls + pos -> h (f32) ----------------
__global__ void assemble_kernel(const float* __restrict__ pemb,
                                const float* __restrict__ g, const float* __restrict__ b,
                                const float* __restrict__ cls, const float* __restrict__ pos,
                                float* __restrict__ h) {
    const int row = blockIdx.x;
    const int bb = row / NTOK, t = row % NTOK;
    const int tid = threadIdx.x;
    float* o_ = h + (long)row * H_;
    if (t == 0) {
        o_[tid]       = cls[tid]       + pos[tid];
        o_[tid + 256] = cls[tid + 256] + pos[tid + 256];
        o_[tid + 512] = cls[tid + 512] + pos[tid + 512];
        return;
    }
    const float* x = pemb + (long)(bb * NP + t - 1) * H_;
    float v0 = x[tid], v1 = x[tid + 256], v2 = x[tid + 512];
    __shared__ float red[256];
    __shared__ float s_mean, s_rstd;
    red[tid] = v0 + v1 + v2;
    __syncthreads();
    for (int o = 128; o > 0; o >>= 1) { if (tid < o) red[tid] += red[tid + o]; __syncthreads(); }
    if (tid == 0) s_mean = red[0] * (1.f / H_);
    __syncthreads();
    float m = s_mean;
    float d0 = v0 - m, d1 = v1 - m, d2 = v2 - m;
    red[tid] = d0 * d0 + d1 * d1 + d2 * d2;
    __syncthreads();
    for (int o = 128; o > 0; o >>= 1) { if (tid < o) red[tid] += red[tid + o]; __syncthreads(); }
    if (tid == 0) s_rstd = rsqrtf(red[0] * (1.f / H_) + 1e-5f);
    __syncthreads();
    float rs = s_rstd;
    const float* pp = pos + (long)t * H_;
    o_[tid]       = d0 * rs * g[tid]       + b[tid]       + pp[tid];
    o_[tid + 256] = d1 * rs * g[tid + 256] + b[tid + 256] + pp[tid + 256];
    o_[tid + 512] = d2 * rs * g[tid + 512] + b[tid + 512] + pp[tid + 512];
}

// ---------------- mean pool ----------------
__global__ void meanpool_kernel(const float* __restrict__ h, float* __restrict__ out) {
    const int bb = blockIdx.x;
    const int j = threadIdx.x;
    float s = 0.f;
    for (int i = 0; i < NTOK; i++) s += h[((long)bb * NTOK + i) * H_ + j];
    out[bb * H_ + j] = s * (1.f / NTOK);
}

// ---------------- host orchestration ----------------
static inline dim3 ggrid(int M, int N) { return dim3(N / 64, (M + 127) / 128); }

extern "C" void kernel_launch(void* const* d_in, const int* in_sizes, int n_in,
                              void* d_out, int out_size) {
    const float* x      = (const float*)d_in[0];
    const float* pn1_g  = (const float*)d_in[1];
    const float* pn1_b  = (const float*)d_in[2];
    const float* pW     = (const float*)d_in[3];
    const float* pb     = (const float*)d_in[4];
    const float* pn2_g  = (const float*)d_in[5];
    const float* pn2_b  = (const float*)d_in[6];
    const float* cls    = (const float*)d_in[7];
    const float* pos    = (const float*)d_in[8];
    const float* ln1_g  = (const float*)d_in[9];
    const float* ln1_b  = (const float*)d_in[10];
    const float* qkv_W  = (const float*)d_in[11];
    const float* out_W  = (const float*)d_in[12];
    const float* ln2_g  = (const float*)d_in[13];
    const float* ln2_b  = (const float*)d_in[14];
    const float* fc1_W  = (const float*)d_in[15];
    const float* fc1_b  = (const float*)d_in[16];
    const float* fc2_W  = (const float*)d_in[17];
    const float* fc2_b  = (const float*)d_in[18];
    float* out = (float*)d_out;

    float *p_h, *p_tmp;
    __half *p_qkv, *p_hq, *p_hy, *p_ha, *p_hm, *p_fh;
    cudaGetSymbolAddress((void**)&p_h,   g_h);
    cudaGetSymbolAddress((void**)&p_tmp, g_tmp);
    cudaGetSymbolAddress((void**)&p_qkv, g_qkv);
    cudaGetSymbolAddress((void**)&p_hq,  g_hq);
    cudaGetSymbolAddress((void**)&p_hy,  g_hy);
    cudaGetSymbolAddress((void**)&p_ha,  g_ha);
    cudaGetSymbolAddress((void**)&p_hm,  g_hm);
    cudaGetSymbolAddress((void**)&p_fh,  g_fh);

    cudaFuncSetAttribute(attn_mma_kernel, cudaFuncAttributeMaxDynamicSharedMemorySize, ATT_SMEM);
    cudaFuncSetAttribute(hgemm_kernel<1>, cudaFuncAttributeMaxDynamicSharedMemorySize, HG_SMEM);
    cudaFuncSetAttribute(hgemm_kernel<2>, cudaFuncAttributeMaxDynamicSharedMemorySize, HG_SMEM);
    cudaFuncSetAttribute(hgemm_kernel<3>, cudaFuncAttributeMaxDynamicSharedMemorySize, HG_SMEM);
    cudaFuncSetAttribute(hgemm_kernel<4>, cudaFuncAttributeMaxDynamicSharedMemorySize, HG_SMEM);
    cudaFuncSetAttribute(hgemm_kernel<5>, cudaFuncAttributeMaxDynamicSharedMemorySize, HG_SMEM);

    dim3 tb(32, 8);
    // idx 0: patchify + LN(pn1) -> fp16
    patchify_ln_kernel<<<PROWS, 256>>>(x, pn1_g, pn1_b, p_hq);
    // idx 1: mega weight split (all weights -> fp16 single)
    wsplit_mega_kernel<<<dim3(2304, 49), tb>>>(pW, qkv_W, out_W, fc1_W, fc2_W, p_fh);
    // idx 2: patch embed GEMM + bias -> g_tmp (f32)
    hgemm_kernel<1><<<ggrid(PROWS, H_), 256, HG_SMEM>>>(p_hq, p_fh + W_PATCH_OFF,
                                                        pb, p_tmp, nullptr, PROWS, H_, H_);
    // idx 3: LN(pn2) + cls + pos -> h
    assemble_kernel<<<ROWS, 256>>>(p_tmp, pn2_g, pn2_b, cls, pos, p_h);

    // transformer layers
    for (int l = 0; l < L_; l++) {
        long wb = W_LAYER_BASE + (long)l * W_LAYER_SZ;
        const float* l1g = ln1_g + l * H_;
        const float* l1b = ln1_b + l * H_;
        const float* l2g = ln2_g + l * H_;
        const float* l2b = ln2_b + l * H_;
        const float* f1b = fc1_b + (long)l * MLP_;
        const float* f2b = fc2_b + (long)l * H_;

        ln_half_kernel<<<ROWS / 8, 256>>>(p_h, p_hq, l1g, l1b);
        hgemm_kernel<5><<<ggrid(ROWS, 3 * H_), 256, HG_SMEM>>>(
            p_hq, p_fh + wb + W_QKV_OFF,
            nullptr, nullptr, p_qkv, ROWS, 3 * H_, H_);
        attn_mma_kernel<<<B_ * NH, 256, ATT_SMEM>>>(p_qkv, p_ha);
        hgemm_kernel<4><<<ggrid(ROWS, H_), 256, HG_SMEM>>>(
            p_ha, p_fh + wb + W_OUT_OFF,
            nullptr, p_h, nullptr, ROWS, H_, H_);
        ln_half_kernel<<<ROWS / 8, 256>>>(p_h, p_hy, l2g, l2b);
        hgemm_kernel<2><<<ggrid(ROWS, MLP_), 256, HG_SMEM>>>(
            p_hy, p_fh + wb + W_FC1_OFF,
            f1b, nullptr, p_hm, ROWS, MLP_, H_);
        hgemm_kernel<3><<<ggrid(ROWS, H_), 256, HG_SMEM>>>(
            p_hm, p_fh + wb + W_FC2_OFF,
            f2b, p_h, nullptr, ROWS, H_, MLP_);
    }

    // mean pool
    meanpool_kernel<<<B_, H_>>>(p_h, out);
}